// round 11
// baseline (speedup 1.0000x reference)
#include <cuda_runtime.h>
#include <math.h>
#include <stdint.h>

// ---------------------------------------------------------------------------
// Problem constants
// ---------------------------------------------------------------------------
#define S_LEN   512
#define BATCH   64
#define D_IN    256
#define HID     512
#define G4      2048        // 4 gates * HID, packed unit-major: col = u*4 + gate
#define NH      4
#define DK      128
#define ROWS    (S_LEN*BATCH)        // 32768
#define DEC_ELEMS (S_LEN*BATCH*HID)  // 16777216
#define NB      64                   // persistent LSTM blocks
#define WPITCH  516                  // weight smem pitch (mod 32 == 4 -> conflict-free)
#define HHP     260                  // h half-tile smem pitch (mod 32 == 4)
#define APITCH  20                   // gemm A-smem pitch (floats)
#define BPITCH  72                   // gemm B-smem pitch, normal path
#define BTFL    1280                 // gemm B buffer floats (max of 16*72, 64*20)

// ---------------------------------------------------------------------------
// Device scratch (static allocations only — no cudaMalloc allowed)
// ---------------------------------------------------------------------------
__device__ float g_Wxp[D_IN*G4];          //   2 MB  packed input-gate weights
__device__ float g_Whp[HID*G4];           //   4 MB  packed recurrent-gate weights
__device__ float g_biasp[G4];
__device__ float g_gx[ROWS*G4];           // 256 MB  x-side gate preacts; reused as attn scores
__device__ float g_lstm[ROWS*HID];        //  64 MB  lstm_out [S,B,HID]; IS the h history
__device__ float g_c[BATCH*HID];
__device__ float g_PQ[ROWS*HID];          //  64 MB
__device__ float g_PK[ROWS*HID];
__device__ float g_PV[ROWS*HID];
__device__ unsigned g_cnt;                //  grid barrier counter

// ---------------------------------------------------------------------------
// Helpers
// ---------------------------------------------------------------------------
__device__ __forceinline__ float tf32_rnd(float x) {
    uint32_t u; asm("cvt.rna.tf32.f32 %0, %1;" : "=r"(u) : "f"(x));
    return __uint_as_float(u);
}
__device__ __forceinline__ uint32_t fu(float x) { return __float_as_uint(x); }

#define MMA8(cc, a, bb) \
    asm volatile("mma.sync.aligned.m16n8k8.row.col.f32.tf32.tf32.f32 " \
        "{%0,%1,%2,%3},{%4,%5,%6,%7},{%8,%9},{%0,%1,%2,%3};" \
        : "+f"(cc[0]), "+f"(cc[1]), "+f"(cc[2]), "+f"(cc[3]) \
        : "r"(a[0]), "r"(a[1]), "r"(a[2]), "r"(a[3]), "r"(bb[0]), "r"(bb[1]))

#define CPA16(dst, src) \
    asm volatile("cp.async.cg.shared.global [%0], [%1], 16;" :: "r"(dst), "l"(src))

// ---------------------------------------------------------------------------
// Weight repack: gates (f,i,g,o) interleaved per hid-unit, split x-rows/h-rows
// ---------------------------------------------------------------------------
__global__ void pack_weights(const float* __restrict__ Wf, const float* __restrict__ Wi,
                             const float* __restrict__ Wg, const float* __restrict__ Wo,
                             const float* __restrict__ bf, const float* __restrict__ bi,
                             const float* __restrict__ bg, const float* __restrict__ bo)
{
    int idx = blockIdx.x * blockDim.x + threadIdx.x;   // over 768*512
    if (idx < 768*HID) {
        int k = idx / HID, u = idx % HID;
        float vf = Wf[idx], vi = Wi[idx], vg = Wg[idx], vo = Wo[idx];
        float* dst = (k < D_IN) ? (g_Wxp + (long)k*G4) : (g_Whp + (long)(k - D_IN)*G4);
        dst[u*4+0] = vf; dst[u*4+1] = vi; dst[u*4+2] = vg; dst[u*4+3] = vo;
    }
    if (idx < HID) {
        g_biasp[idx*4+0] = bf[idx];
        g_biasp[idx*4+1] = bi[idx];
        g_biasp[idx*4+2] = bg[idx];
        g_biasp[idx*4+3] = bo[idx];
    }
    if (idx == 0) g_cnt = 0u;
}

// ---------------------------------------------------------------------------
// tf32 3-split GEMM v3: 128x64 block tile, 256 threads, 2 blocks/SM.
// Raw-residual lo split (tf32 MMA reads top 19 bits only).
// ---------------------------------------------------------------------------
__global__ __launch_bounds__(256, 2)
void gemm_tf32(const float* __restrict__ A, int lda, long as1, long as2,
               const float* __restrict__ B, int ldb, long bs1, long bs2,
               const float* __restrict__ bias,
               float* __restrict__ C, int ldc, long cs1, long cs2,
               int K, float alpha, int transB)
{
    __shared__ float As[2][128*APITCH];
    __shared__ float Bs[2][BTFL];

    int z = blockIdx.z;
    A += (long)(z >> 2) * as1 + (long)(z & 3) * as2;
    B += (long)(z >> 2) * bs1 + (long)(z & 3) * bs2;
    C += (long)(z >> 2) * cs1 + (long)(z & 3) * cs2;
    int m0 = blockIdx.y * 128, n0 = blockIdx.x * 64;

    int tid = threadIdx.x;
    int warp = tid >> 5, lane = tid & 31;
    int wm = (warp >> 1) * 32, wn = (warp & 1) * 32;
    int r = lane >> 2, q = lane & 3;

    const uint32_t a_smem = (uint32_t)__cvta_generic_to_shared(&As[0][0]);
    const uint32_t b_smem = (uint32_t)__cvta_generic_to_shared(&Bs[0][0]);
    const uint32_t abuf = 128*APITCH*4;
    const uint32_t bbuf = BTFL*4;

    int am0 = tid >> 2, ac = tid & 3;
    int bkr = tid >> 4, bc = tid & 15;
    int bn = tid >> 2, bc4 = tid & 3;

    int KT = K >> 4;

    auto issue = [&](int kt) {
        int k0 = kt << 4, buf = kt & 1;
        CPA16(a_smem + buf*abuf + (uint32_t)(am0*APITCH + ac*4)*4,
              A + (long)(m0 + am0)*lda + k0 + ac*4);
        CPA16(a_smem + buf*abuf + (uint32_t)((am0+64)*APITCH + ac*4)*4,
              A + (long)(m0 + am0 + 64)*lda + k0 + ac*4);
        if (!transB) {
            CPA16(b_smem + buf*bbuf + (uint32_t)(bkr*BPITCH + bc*4)*4,
                  B + (long)(k0 + bkr)*ldb + n0 + bc*4);
        } else {
            CPA16(b_smem + buf*bbuf + (uint32_t)(bn*APITCH + bc4*4)*4,
                  B + (long)(n0 + bn)*ldb + k0 + bc4*4);
        }
        asm volatile("cp.async.commit_group;");
    };

    float acc[2][4][4];
    #pragma unroll
    for (int mt = 0; mt < 2; mt++)
        #pragma unroll
        for (int nt = 0; nt < 4; nt++)
            #pragma unroll
            for (int e = 0; e < 4; e++) acc[mt][nt][e] = 0.f;

    issue(0);
    for (int kt = 0; kt < KT; kt++) {
        if (kt + 1 < KT) {
            issue(kt + 1);
            asm volatile("cp.async.wait_group 1;" ::: "memory");
        } else {
            asm volatile("cp.async.wait_group 0;" ::: "memory");
        }
        __syncthreads();

        const float* Ab = &As[kt & 1][0];
        const float* Bb = &Bs[kt & 1][0];
        #pragma unroll
        for (int p = 0; p < 2; p++) {
            int kb = p*8;
            uint32_t bh[4][2], bl[4][2];
            #pragma unroll
            for (int nt = 0; nt < 4; nt++) {
                int n = wn + nt*8 + r;
                float br0, br1;
                if (!transB) {
                    br0 = Bb[(kb+q  )*BPITCH + n];
                    br1 = Bb[(kb+q+4)*BPITCH + n];
                } else {
                    br0 = Bb[n*APITCH + kb+q  ];
                    br1 = Bb[n*APITCH + kb+q+4];
                }
                float bh0f = tf32_rnd(br0), bh1f = tf32_rnd(br1);
                bh[nt][0] = fu(bh0f);        bh[nt][1] = fu(bh1f);
                bl[nt][0] = fu(br0 - bh0f);  bl[nt][1] = fu(br1 - bh1f);
            }
            #pragma unroll
            for (int mt = 0; mt < 2; mt++) {
                int m = wm + mt*16 + r;
                float ar[4];
                ar[0] = Ab[ m     *APITCH + kb+q  ];
                ar[1] = Ab[(m+8)  *APITCH + kb+q  ];
                ar[2] = Ab[ m     *APITCH + kb+q+4];
                ar[3] = Ab[(m+8)  *APITCH + kb+q+4];
                uint32_t ah[4], al[4];
                #pragma unroll
                for (int e = 0; e < 4; e++) {
                    float hi = tf32_rnd(ar[e]);
                    ah[e] = fu(hi);
                    al[e] = fu(ar[e] - hi);
                }
                #pragma unroll
                for (int nt = 0; nt < 4; nt++) {
                    MMA8(acc[mt][nt], ah, bh[nt]);
                    MMA8(acc[mt][nt], ah, bl[nt]);
                    MMA8(acc[mt][nt], al, bh[nt]);
                }
            }
        }
        __syncthreads();
    }

    #pragma unroll
    for (int mt = 0; mt < 2; mt++)
        #pragma unroll
        for (int nt = 0; nt < 4; nt++) {
            int mrow = m0 + wm + mt*16 + r;
            int ncol = n0 + wn + nt*8 + q*2;
            float b0 = bias ? bias[ncol]   : 0.f;
            float b1 = bias ? bias[ncol+1] : 0.f;
            C[(long)mrow*ldc + ncol  ]     = alpha*acc[mt][nt][0] + b0;
            C[(long)mrow*ldc + ncol+1]     = alpha*acc[mt][nt][1] + b1;
            C[(long)(mrow+8)*ldc + ncol  ] = alpha*acc[mt][nt][2] + b0;
            C[(long)(mrow+8)*ldc + ncol+1] = alpha*acc[mt][nt][3] + b1;
        }
}

// ---------------------------------------------------------------------------
// Persistent LSTM recurrence v2 — tensor-core matvec, 64 blocks x 256 threads.
// Block bid owns packed cols [bid*32, bid*32+32) = hid-units [bid*8, bid*8+8).
// Per step: out[64x32] = h[64x512] @ Wslice[512x32], m16n8k8 tf32 3-split
// (lo term = raw fp32 residual; tf32 MMA reads top 19 bits).
// 8 warps: mt = warp>>1 (m16 tile), ntp = warp&1; warp computes n8 tiles
// ntv = ntp and ntp+2 (A fragments converted once, reused for both).
// Weights presplit hi/lo ONCE into n-major smem [j][k] pitch 516 (132 KB).
// h = g_lstm[t-1], staged per step in two k-halves [64][260] (66 KB) so the
// whole thing fits in 198 KB smem. t=0 skips the matvec (h=0).
// Epilogue per even-q lane: 2 units x 2 batch rows; partner shfl.xor(1).
// ---------------------------------------------------------------------------
__global__ __launch_bounds__(256)
void lstm_persistent(const float* __restrict__ gx)
{
    extern __shared__ float sm[];
    float* Bhs = sm;                     // [32][516] weight hi
    float* Bls = sm + 32*WPITCH;         // [32][516] weight lo
    float* hs  = sm + 64*WPITCH;         // [64][260] staged h half

    const int tid = threadIdx.x, bid = blockIdx.x;
    const int c0 = bid * 32;
    const int warp = tid >> 5, lane = tid & 31;
    const int mt = warp >> 1, ntp = warp & 1;
    const int r = lane >> 2, q = lane & 3;
    const int row0 = mt*16 + r;

    // ---- presplit weight slice into n-major hi/lo (once) ----
    for (int idx = tid; idx < 32*512; idx += 256) {
        int k = idx >> 5, j = idx & 31;
        float w = g_Whp[(long)k*G4 + c0 + j];
        float hi = tf32_rnd(w);
        Bhs[j*WPITCH + k] = hi;
        Bls[j*WPITCH + k] = tf32_rnd(w - hi);
    }

    // cell state: even-q lanes own 2 units x 2 rows
    float cA0 = 0.f, cB0 = 0.f, cA2 = 0.f, cB2 = 0.f;
    const int u0 = bid*8 + 2*ntp + (q >> 1);   // unit for tile ntv=ntp
    const int u2 = u0 + 4;                     // unit for tile ntv=ntp+2

    __syncthreads();

    const float* arow0 = hs + row0*HHP;
    const float* arow8 = arow0 + 8*HHP;
    const float* brh0  = Bhs + (ntp*8 + r)*WPITCH;       // tile ntv=ntp
    const float* brl0  = Bls + (ntp*8 + r)*WPITCH;
    const float* brh2  = brh0 + 16*WPITCH;               // tile ntv=ntp+2
    const float* brl2  = brl0 + 16*WPITCH;

    for (int t = 0; t < S_LEN; t++) {
        // prefetch this thread's gx preacts: 2 tiles x 2 rows x 2 cols
        const float* gbase = gx + ((long)t*BATCH)*G4 + c0 + ntp*8 + 2*q;
        const float2 g0A = *(const float2*)(gbase + (long)row0*G4);
        const float2 g0B = *(const float2*)(gbase + (long)(row0+8)*G4);
        const float2 g2A = *(const float2*)(gbase + 16 + (long)row0*G4);
        const float2 g2B = *(const float2*)(gbase + 16 + (long)(row0+8)*G4);

        float acc0[4] = {0.f, 0.f, 0.f, 0.f};
        float acc2[4] = {0.f, 0.f, 0.f, 0.f};

        if (t) {
            // ---- grid barrier: all blocks done with step t-1 ----
            if (tid == 0) {
                unsigned target = (unsigned)t * NB;
                while (*(volatile unsigned*)&g_cnt < target) { }
                __threadfence();
            }
            __syncthreads();

            const float* hp = g_lstm + (long)(t-1)*BATCH*HID;
            #pragma unroll
            for (int ph = 0; ph < 2; ph++) {
                int ks = ph * 256;
                // ---- stage k-half [64][256] ----
                #pragma unroll 4
                for (int i = 0; i < 16; i++) {
                    int idx = tid + i*256;           // float4 idx, 4096 total
                    int rr = idx >> 6, cc = idx & 63;
                    float4 v = __ldcg((const float4*)(hp + rr*HID + ks + cc*4));
                    *(float4*)(hs + rr*HHP + cc*4) = v;
                }
                __syncthreads();

                // ---- mma over this k-half ----
                #pragma unroll 4
                for (int k0 = 0; k0 < 256; k0 += 8) {
                    int kg = ks + k0;
                    float a0 = arow0[k0+q  ];
                    float a1 = arow8[k0+q  ];
                    float a2 = arow0[k0+q+4];
                    float a3 = arow8[k0+q+4];
                    float h0f = tf32_rnd(a0), h1f = tf32_rnd(a1);
                    float h2f = tf32_rnd(a2), h3f = tf32_rnd(a3);
                    uint32_t ah[4] = { fu(h0f), fu(h1f), fu(h2f), fu(h3f) };
                    uint32_t al[4] = { fu(a0 - h0f), fu(a1 - h1f),
                                       fu(a2 - h2f), fu(a3 - h3f) };
                    uint32_t bh_0[2] = { fu(brh0[kg+q]), fu(brh0[kg+q+4]) };
                    uint32_t bl_0[2] = { fu(brl0[kg+q]), fu(brl0[kg+q+4]) };
                    uint32_t bh_2[2] = { fu(brh2[kg+q]), fu(brh2[kg+q+4]) };
                    uint32_t bl_2[2] = { fu(brl2[kg+q]), fu(brl2[kg+q+4]) };
                    MMA8(acc0, ah, bh_0);
                    MMA8(acc0, ah, bl_0);
                    MMA8(acc0, al, bh_0);
                    MMA8(acc2, ah, bh_2);
                    MMA8(acc2, ah, bl_2);
                    MMA8(acc2, al, bh_2);
                }
                __syncthreads();   // before next phase overwrites hs / arrive
            }
        }

        // ---- epilogue: add gx, activate, exchange, cell update (both tiles)
        float p00 = acc0[0] + g0A.x,  p01 = acc0[1] + g0A.y;
        float p02 = acc0[2] + g0B.x,  p03 = acc0[3] + g0B.y;
        float p20 = acc2[0] + g2A.x,  p21 = acc2[1] + g2A.y;
        float p22 = acc2[2] + g2B.x,  p23 = acc2[3] + g2B.y;

        float s00, s01, s02, s03, s20, s21, s22, s23;
        if (q & 1) {            // odd lanes: cols are (g, o)
            s00 = tanhf(p00);               s01 = 1.f/(1.f+expf(-p01));
            s02 = tanhf(p02);               s03 = 1.f/(1.f+expf(-p03));
            s20 = tanhf(p20);               s21 = 1.f/(1.f+expf(-p21));
            s22 = tanhf(p22);               s23 = 1.f/(1.f+expf(-p23));
        } else {                // even lanes: cols are (f, i)
            s00 = 1.f/(1.f+expf(-p00));     s01 = 1.f/(1.f+expf(-p01));
            s02 = 1.f/(1.f+expf(-p02));     s03 = 1.f/(1.f+expf(-p03));
            s20 = 1.f/(1.f+expf(-p20));     s21 = 1.f/(1.f+expf(-p21));
            s22 = 1.f/(1.f+expf(-p22));     s23 = 1.f/(1.f+expf(-p23));
        }
        float x00 = __shfl_xor_sync(0xFFFFFFFFu, s00, 1);
        float x01 = __shfl_xor_sync(0xFFFFFFFFu, s01, 1);
        float x02 = __shfl_xor_sync(0xFFFFFFFFu, s02, 1);
        float x03 = __shfl_xor_sync(0xFFFFFFFFu, s03, 1);
        float x20 = __shfl_xor_sync(0xFFFFFFFFu, s20, 1);
        float x21 = __shfl_xor_sync(0xFFFFFFFFu, s21, 1);
        float x22 = __shfl_xor_sync(0xFFFFFFFFu, s22, 1);
        float x23 = __shfl_xor_sync(0xFFFFFFFFu, s23, 1);

        if (!(q & 1)) {
            float* lw = g_lstm + (long)t*BATCH*HID;
            // tile 0: s=f,i  x=g,o
            cA0 = s00 * cA0 + s01 * x00;
            float hA0 = x01 * tanhf(cA0);
            cB0 = s02 * cB0 + s03 * x02;
            float hB0 = x03 * tanhf(cB0);
            lw[row0*HID + u0]     = hA0;
            lw[(row0+8)*HID + u0] = hB0;
            // tile 2
            cA2 = s20 * cA2 + s21 * x20;
            float hA2 = x21 * tanhf(cA2);
            cB2 = s22 * cB2 + s23 * x22;
            float hB2 = x23 * tanhf(cB2);
            lw[row0*HID + u2]     = hA2;
            lw[(row0+8)*HID + u2] = hB2;
            if (t == S_LEN-1) {
                g_c[row0*HID + u0]     = cA0;
                g_c[(row0+8)*HID + u0] = cB0;
                g_c[row0*HID + u2]     = cA2;
                g_c[(row0+8)*HID + u2] = cB2;
            }
        }

        // ---- arrive: cta barrier, then tid0-only fence + atomic ----
        __syncthreads();
        if (tid == 0) {
            __threadfence();
            atomicAdd(&g_cnt, 1u);
        }
    }
}

// ---------------------------------------------------------------------------
// Row softmax over 512-wide rows. One block (128 threads) per row.
// ---------------------------------------------------------------------------
__global__ __launch_bounds__(128)
void softmax512(float* __restrict__ s)
{
    float* row = s + (size_t)blockIdx.x * 512;
    int tid = threadIdx.x;
    float v0 = row[tid], v1 = row[tid+128], v2 = row[tid+256], v3 = row[tid+384];
    float mx = fmaxf(fmaxf(v0, v1), fmaxf(v2, v3));
    __shared__ float sm[4];
    __shared__ float ss[4];
    #pragma unroll
    for (int off = 16; off > 0; off >>= 1)
        mx = fmaxf(mx, __shfl_xor_sync(0xFFFFFFFFu, mx, off));
    if ((tid & 31) == 0) sm[tid >> 5] = mx;
    __syncthreads();
    mx = fmaxf(fmaxf(sm[0], sm[1]), fmaxf(sm[2], sm[3]));
    v0 = expf(v0 - mx); v1 = expf(v1 - mx); v2 = expf(v2 - mx); v3 = expf(v3 - mx);
    float sum = v0 + v1 + v2 + v3;
    #pragma unroll
    for (int off = 16; off > 0; off >>= 1)
        sum += __shfl_xor_sync(0xFFFFFFFFu, sum, off);
    if ((tid & 31) == 0) ss[tid >> 5] = sum;
    __syncthreads();
    sum = ss[0] + ss[1] + ss[2] + ss[3];
    float inv = 1.f / sum;
    row[tid] = v0*inv; row[tid+128] = v1*inv; row[tid+256] = v2*inv; row[tid+384] = v3*inv;
}

__global__ void copy_hc(const float* __restrict__ h, const float* __restrict__ c,
                        float* __restrict__ out)
{
    int i = blockIdx.x * blockDim.x + threadIdx.x;
    if (i < BATCH*HID) {
        out[DEC_ELEMS + i] = h[i];
        out[DEC_ELEMS + BATCH*HID + i] = c[i];
    }
}

// ---------------------------------------------------------------------------
// Host orchestration (graph-capturable: launches only)
// ---------------------------------------------------------------------------
extern "C" void kernel_launch(void* const* d_in, const int* in_sizes, int n_in,
                              void* d_out, int out_size)
{
    const float* x  = (const float*)d_in[0];
    const float* Wf = (const float*)d_in[1];
    const float* bf = (const float*)d_in[2];
    const float* Wi = (const float*)d_in[3];
    const float* bi = (const float*)d_in[4];
    const float* Wg = (const float*)d_in[5];
    const float* bg = (const float*)d_in[6];
    const float* Wo = (const float*)d_in[7];
    const float* bo = (const float*)d_in[8];
    const float* Wq = (const float*)d_in[9];
    const float* bq = (const float*)d_in[10];
    const float* Wk = (const float*)d_in[11];
    const float* bk = (const float*)d_in[12];
    const float* Wv = (const float*)d_in[13];
    const float* bv = (const float*)d_in[14];
    float* out = (float*)d_out;

    float *Wxp, *biasp, *gx, *lstm, *c, *PQ, *PK, *PV;
    cudaGetSymbolAddress((void**)&Wxp,   g_Wxp);
    cudaGetSymbolAddress((void**)&biasp, g_biasp);
    cudaGetSymbolAddress((void**)&gx,    g_gx);
    cudaGetSymbolAddress((void**)&lstm,  g_lstm);
    cudaGetSymbolAddress((void**)&c,     g_c);
    cudaGetSymbolAddress((void**)&PQ,    g_PQ);
    cudaGetSymbolAddress((void**)&PK,    g_PK);
    cudaGetSymbolAddress((void**)&PV,    g_PV);

    // smem: weights 2*32*516 + h half 64*260 floats = 198,656 B
    const int SMEM_LSTM = (64*WPITCH + 64*HHP) * (int)sizeof(float);
    cudaFuncSetAttribute(lstm_persistent,
                         cudaFuncAttributeMaxDynamicSharedMemorySize, SMEM_LSTM);

    // 1. repack weights + reset barrier counter
    pack_weights<<<(768*HID + 255)/256, 256>>>(Wf, Wi, Wg, Wo, bf, bi, bg, bo);

    // 2. x-side gate preacts: gx = x @ Wxp + biasp   [32768,256]@[256,2048]
    gemm_tf32<<<dim3(G4/64, ROWS/128, 1), 256>>>(
        x, D_IN, 0, 0, Wxp, G4, 0, 0, biasp, gx, G4, 0, 0, D_IN, 1.0f, 0);

    // 3. recurrence: persistent tensor-core kernel, device grid barrier per step
    lstm_persistent<<<NB, 256, SMEM_LSTM>>>(gx);

    // 4. Q/K/V projections: [32768,512]@[512,512]+b
    gemm_tf32<<<dim3(HID/64, ROWS/128, 1), 256>>>(
        lstm, HID, 0, 0, Wq, HID, 0, 0, bq, PQ, HID, 0, 0, HID, 1.0f, 0);
    gemm_tf32<<<dim3(HID/64, ROWS/128, 1), 256>>>(
        lstm, HID, 0, 0, Wk, HID, 0, 0, bk, PK, HID, 0, 0, HID, 1.0f, 0);
    gemm_tf32<<<dim3(HID/64, ROWS/128, 1), 256>>>(
        lstm, HID, 0, 0, Wv, HID, 0, 0, bv, PV, HID, 0, 0, HID, 1.0f, 0);

    // 5. scores = (Q @ K^T)/sqrt(dk), z = b'*4 + h
    const long pbS = (long)S_LEN * HID;          // per-b' stride in PQ/PK/PV
    const long phS = DK;                         // per-h stride
    const long scB = 4L * S_LEN * S_LEN;         // scores per-b' stride
    const long scH = (long)S_LEN * S_LEN;        // scores per-h stride
    float scale = 1.0f / sqrtf((float)DK);
    gemm_tf32<<<dim3(S_LEN/64, S_LEN/128, BATCH*NH), 256>>>(
        PQ, HID, pbS, phS,
        PK, HID, pbS, phS,
        (const float*)0,
        gx /* reused as scores */, S_LEN, scB, scH, DK, scale, 1);

    // 6. softmax over last axis
    softmax512<<<BATCH*NH*S_LEN, 128>>>(gx);

    // 7. out = attn @ V, written directly in decoded layout:
    //    d_out[(s*64 + b')*512 + h*128 + d]
    gemm_tf32<<<dim3(DK/64, S_LEN/128, BATCH*NH), 256>>>(
        gx, S_LEN, scB, scH,
        PV, HID, pbS, phS,
        (const float*)0,
        out, BATCH*HID, (long)HID, (long)DK, S_LEN, 1.0f, 0);

    // 8. final hidden/cell state (h_final = last lstm_out slice)
    copy_hc<<<(BATCH*HID + 255)/256, 256>>>(
        lstm + (long)(S_LEN-1)*BATCH*HID, c, out);
}

// round 12
// speedup vs baseline: 1.1144x; 1.1144x over previous
#include <cuda_runtime.h>
#include <math.h>
#include <stdint.h>

// ---------------------------------------------------------------------------
// Problem constants
// ---------------------------------------------------------------------------
#define S_LEN   512
#define BATCH   64
#define D_IN    256
#define HID     512
#define G4      2048        // 4 gates * HID, packed unit-major: col = u*4 + gate
#define NH      4
#define DK      128
#define ROWS    (S_LEN*BATCH)        // 32768
#define DEC_ELEMS (S_LEN*BATCH*HID)  // 16777216
#define NB      128                  // persistent LSTM blocks (1/SM -> full chip)
#define HPAD    516                  // padded pitch (floats)
#define APITCH  20                   // gemm A-smem pitch (floats)
#define BPITCH  72                   // gemm B-smem pitch, normal path
#define BTFL    1280                 // gemm B buffer floats (max of 16*72, 64*20)

// ---------------------------------------------------------------------------
// Device scratch (static allocations only — no cudaMalloc allowed)
// ---------------------------------------------------------------------------
__device__ float g_Wxp[D_IN*G4];          //   2 MB  packed input-gate weights
__device__ float g_Whp[HID*G4];           //   4 MB  packed recurrent-gate weights
__device__ float g_biasp[G4];
__device__ float g_gx[ROWS*G4];           // 256 MB  x-side gate preacts; reused as attn scores
__device__ float g_lstm[ROWS*HID];        //  64 MB  lstm_out [S,B,HID]
__device__ float g_h[2][BATCH*HID];       //  h double buffer
__device__ float g_c[BATCH*HID];
__device__ float g_PQ[ROWS*HID];          //  64 MB
__device__ float g_PK[ROWS*HID];
__device__ float g_PV[ROWS*HID];
__device__ unsigned g_cnt;                //  grid barrier counter

// ---------------------------------------------------------------------------
// Helpers
// ---------------------------------------------------------------------------
__device__ __forceinline__ float tf32_rnd(float x) {
    uint32_t u; asm("cvt.rna.tf32.f32 %0, %1;" : "=r"(u) : "f"(x));
    return __uint_as_float(u);
}
__device__ __forceinline__ uint32_t fu(float x) { return __float_as_uint(x); }

#define MMA8(cc, a, bb) \
    asm volatile("mma.sync.aligned.m16n8k8.row.col.f32.tf32.tf32.f32 " \
        "{%0,%1,%2,%3},{%4,%5,%6,%7},{%8,%9},{%0,%1,%2,%3};" \
        : "+f"(cc[0]), "+f"(cc[1]), "+f"(cc[2]), "+f"(cc[3]) \
        : "r"(a[0]), "r"(a[1]), "r"(a[2]), "r"(a[3]), "r"(bb[0]), "r"(bb[1]))

#define CPA16(dst, src) \
    asm volatile("cp.async.cg.shared.global [%0], [%1], 16;" :: "r"(dst), "l"(src))

// ---------------------------------------------------------------------------
// Weight repack: gates (f,i,g,o) interleaved per hid-unit, split x-rows/h-rows
// ---------------------------------------------------------------------------
__global__ void pack_weights(const float* __restrict__ Wf, const float* __restrict__ Wi,
                             const float* __restrict__ Wg, const float* __restrict__ Wo,
                             const float* __restrict__ bf, const float* __restrict__ bi,
                             const float* __restrict__ bg, const float* __restrict__ bo)
{
    int idx = blockIdx.x * blockDim.x + threadIdx.x;   // over 768*512
    if (idx < 768*HID) {
        int k = idx / HID, u = idx % HID;
        float vf = Wf[idx], vi = Wi[idx], vg = Wg[idx], vo = Wo[idx];
        float* dst = (k < D_IN) ? (g_Wxp + (long)k*G4) : (g_Whp + (long)(k - D_IN)*G4);
        dst[u*4+0] = vf; dst[u*4+1] = vi; dst[u*4+2] = vg; dst[u*4+3] = vo;
    }
    if (idx < HID) {
        g_biasp[idx*4+0] = bf[idx];
        g_biasp[idx*4+1] = bi[idx];
        g_biasp[idx*4+2] = bg[idx];
        g_biasp[idx*4+3] = bo[idx];
    }
}

__global__ void zero_state()
{
    int i = blockIdx.x * blockDim.x + threadIdx.x;
    if (i < BATCH*HID) { g_h[0][i] = 0.f; g_c[i] = 0.f; }
    if (i == 0) g_cnt = 0u;
}

// ---------------------------------------------------------------------------
// tf32 3-split GEMM: 128x64 block tile, 256 threads, 2 blocks/SM.
// Raw-residual lo split (tf32 MMA reads top 19 bits only). Proven R11.
// ---------------------------------------------------------------------------
__global__ __launch_bounds__(256, 2)
void gemm_tf32(const float* __restrict__ A, int lda, long as1, long as2,
               const float* __restrict__ B, int ldb, long bs1, long bs2,
               const float* __restrict__ bias,
               float* __restrict__ C, int ldc, long cs1, long cs2,
               int K, float alpha, int transB)
{
    __shared__ float As[2][128*APITCH];
    __shared__ float Bs[2][BTFL];

    int z = blockIdx.z;
    A += (long)(z >> 2) * as1 + (long)(z & 3) * as2;
    B += (long)(z >> 2) * bs1 + (long)(z & 3) * bs2;
    C += (long)(z >> 2) * cs1 + (long)(z & 3) * cs2;
    int m0 = blockIdx.y * 128, n0 = blockIdx.x * 64;

    int tid = threadIdx.x;
    int warp = tid >> 5, lane = tid & 31;
    int wm = (warp >> 1) * 32, wn = (warp & 1) * 32;
    int r = lane >> 2, q = lane & 3;

    const uint32_t a_smem = (uint32_t)__cvta_generic_to_shared(&As[0][0]);
    const uint32_t b_smem = (uint32_t)__cvta_generic_to_shared(&Bs[0][0]);
    const uint32_t abuf = 128*APITCH*4;
    const uint32_t bbuf = BTFL*4;

    int am0 = tid >> 2, ac = tid & 3;
    int bkr = tid >> 4, bc = tid & 15;
    int bn = tid >> 2, bc4 = tid & 3;

    int KT = K >> 4;

    auto issue = [&](int kt) {
        int k0 = kt << 4, buf = kt & 1;
        CPA16(a_smem + buf*abuf + (uint32_t)(am0*APITCH + ac*4)*4,
              A + (long)(m0 + am0)*lda + k0 + ac*4);
        CPA16(a_smem + buf*abuf + (uint32_t)((am0+64)*APITCH + ac*4)*4,
              A + (long)(m0 + am0 + 64)*lda + k0 + ac*4);
        if (!transB) {
            CPA16(b_smem + buf*bbuf + (uint32_t)(bkr*BPITCH + bc*4)*4,
                  B + (long)(k0 + bkr)*ldb + n0 + bc*4);
        } else {
            CPA16(b_smem + buf*bbuf + (uint32_t)(bn*APITCH + bc4*4)*4,
                  B + (long)(n0 + bn)*ldb + k0 + bc4*4);
        }
        asm volatile("cp.async.commit_group;");
    };

    float acc[2][4][4];
    #pragma unroll
    for (int mt = 0; mt < 2; mt++)
        #pragma unroll
        for (int nt = 0; nt < 4; nt++)
            #pragma unroll
            for (int e = 0; e < 4; e++) acc[mt][nt][e] = 0.f;

    issue(0);
    for (int kt = 0; kt < KT; kt++) {
        if (kt + 1 < KT) {
            issue(kt + 1);
            asm volatile("cp.async.wait_group 1;" ::: "memory");
        } else {
            asm volatile("cp.async.wait_group 0;" ::: "memory");
        }
        __syncthreads();

        const float* Ab = &As[kt & 1][0];
        const float* Bb = &Bs[kt & 1][0];
        #pragma unroll
        for (int p = 0; p < 2; p++) {
            int kb = p*8;
            uint32_t bh[4][2], bl[4][2];
            #pragma unroll
            for (int nt = 0; nt < 4; nt++) {
                int n = wn + nt*8 + r;
                float br0, br1;
                if (!transB) {
                    br0 = Bb[(kb+q  )*BPITCH + n];
                    br1 = Bb[(kb+q+4)*BPITCH + n];
                } else {
                    br0 = Bb[n*APITCH + kb+q  ];
                    br1 = Bb[n*APITCH + kb+q+4];
                }
                float bh0f = tf32_rnd(br0), bh1f = tf32_rnd(br1);
                bh[nt][0] = fu(bh0f);        bh[nt][1] = fu(bh1f);
                bl[nt][0] = fu(br0 - bh0f);  bl[nt][1] = fu(br1 - bh1f);
            }
            #pragma unroll
            for (int mt = 0; mt < 2; mt++) {
                int m = wm + mt*16 + r;
                float ar[4];
                ar[0] = Ab[ m     *APITCH + kb+q  ];
                ar[1] = Ab[(m+8)  *APITCH + kb+q  ];
                ar[2] = Ab[ m     *APITCH + kb+q+4];
                ar[3] = Ab[(m+8)  *APITCH + kb+q+4];
                uint32_t ah[4], al[4];
                #pragma unroll
                for (int e = 0; e < 4; e++) {
                    float hi = tf32_rnd(ar[e]);
                    ah[e] = fu(hi);
                    al[e] = fu(ar[e] - hi);
                }
                #pragma unroll
                for (int nt = 0; nt < 4; nt++) {
                    MMA8(acc[mt][nt], ah, bh[nt]);
                    MMA8(acc[mt][nt], ah, bl[nt]);
                    MMA8(acc[mt][nt], al, bh[nt]);
                }
            }
        }
        __syncthreads();
    }

    #pragma unroll
    for (int mt = 0; mt < 2; mt++)
        #pragma unroll
        for (int nt = 0; nt < 4; nt++) {
            int mrow = m0 + wm + mt*16 + r;
            int ncol = n0 + wn + nt*8 + q*2;
            float b0 = bias ? bias[ncol]   : 0.f;
            float b1 = bias ? bias[ncol+1] : 0.f;
            C[(long)mrow*ldc + ncol  ]     = alpha*acc[mt][nt][0] + b0;
            C[(long)mrow*ldc + ncol+1]     = alpha*acc[mt][nt][1] + b1;
            C[(long)(mrow+8)*ldc + ncol  ] = alpha*acc[mt][nt][2] + b0;
            C[(long)(mrow+8)*ldc + ncol+1] = alpha*acc[mt][nt][3] + b1;
        }
}

// ---------------------------------------------------------------------------
// Persistent LSTM recurrence — tensor-core matvec, R10 structure (NB=128,
// one 64x16 tile per block, full-chip parallelism) + raw-residual lo split
// (removes 4 cvt.rna per k8 iteration and 1 per presplit element).
// ---------------------------------------------------------------------------
__global__ __launch_bounds__(256)
void lstm_persistent(const float* __restrict__ gx)
{
    extern __shared__ float sm[];
    float* Bhs = sm;                    // [16][516] presplit weight hi
    float* Bls = sm + 16*HPAD;          // [16][516] presplit weight lo (raw residual)
    float* hs  = sm + 32*HPAD;          // [64][516] staged h

    const int tid = threadIdx.x, bid = blockIdx.x;
    const int c0 = bid * 16;
    const int warp = tid >> 5, lane = tid & 31;
    const int mt = warp >> 1, nt = warp & 1;
    const int r = lane >> 2, q = lane & 3;
    const int row0 = mt*16 + r;

    for (int idx = tid; idx < 16*512; idx += 256) {
        int k = idx >> 4, j = idx & 15;
        float w = g_Whp[(long)k*G4 + c0 + j];
        float hi = tf32_rnd(w);
        Bhs[j*HPAD + k] = hi;
        Bls[j*HPAD + k] = w - hi;       // raw residual (tf32 MMA reads top 19 bits)
    }

    float c_a = 0.f, c_b = 0.f;
    float* h0 = g_h[0];
    float* h1 = g_h[1];
    const int u = bid*4 + nt*2 + (q >> 1);

    __syncthreads();

    const float* arow0 = hs + row0*HPAD;
    const float* arow8 = arow0 + 8*HPAD;
    const float* brh   = Bhs + (nt*8 + r)*HPAD;
    const float* brl   = Bls + (nt*8 + r)*HPAD;

    for (int t = 0; t < S_LEN; t++) {
        const float* gbase = gx + ((long)t*BATCH)*G4 + c0 + nt*8 + 2*q;
        const float2 gA = *(const float2*)(gbase + (long)row0*G4);
        const float2 gB = *(const float2*)(gbase + (long)(row0+8)*G4);

        if (t) {
            if (tid == 0) {
                unsigned target = (unsigned)t * NB;
                while (*(volatile unsigned*)&g_cnt < target) { }
                __threadfence();
            }
            __syncthreads();
        }

        const float* hr = (t & 1) ? h1 : h0;
        #pragma unroll 8
        for (int i = 0; i < 32; i++) {
            int idx = tid + i*256;
            int rr = idx >> 7, cc = idx & 127;
            float4 v = __ldcg((const float4*)hr + idx);
            *(float4*)(hs + rr*HPAD + cc*4) = v;
        }
        __syncthreads();

        float acc[4] = {0.f, 0.f, 0.f, 0.f};
        #pragma unroll 4
        for (int k0 = 0; k0 < HID; k0 += 8) {
            float a0 = arow0[k0+q  ];
            float a1 = arow8[k0+q  ];
            float a2 = arow0[k0+q+4];
            float a3 = arow8[k0+q+4];
            float h0f = tf32_rnd(a0), h1f = tf32_rnd(a1);
            float h2f = tf32_rnd(a2), h3f = tf32_rnd(a3);
            uint32_t ah[4] = { fu(h0f), fu(h1f), fu(h2f), fu(h3f) };
            uint32_t al[4] = { fu(a0 - h0f), fu(a1 - h1f),
                               fu(a2 - h2f), fu(a3 - h3f) };
            uint32_t bh[2] = { fu(brh[k0+q]), fu(brh[k0+q+4]) };
            uint32_t bl[2] = { fu(brl[k0+q]), fu(brl[k0+q+4]) };
            MMA8(acc, ah, bh);
            MMA8(acc, ah, bl);
            MMA8(acc, al, bh);
        }

        float p0 = acc[0] + gA.x;
        float p1 = acc[1] + gA.y;
        float p2 = acc[2] + gB.x;
        float p3 = acc[3] + gB.y;

        float s0, s1, s2, s3;
        if (q & 1) {
            s0 = tanhf(p0);
            s1 = 1.f / (1.f + expf(-p1));
            s2 = tanhf(p2);
            s3 = 1.f / (1.f + expf(-p3));
        } else {
            s0 = 1.f / (1.f + expf(-p0));
            s1 = 1.f / (1.f + expf(-p1));
            s2 = 1.f / (1.f + expf(-p2));
            s3 = 1.f / (1.f + expf(-p3));
        }
        float x0 = __shfl_xor_sync(0xFFFFFFFFu, s0, 1);
        float x1 = __shfl_xor_sync(0xFFFFFFFFu, s1, 1);
        float x2 = __shfl_xor_sync(0xFFFFFFFFu, s2, 1);
        float x3 = __shfl_xor_sync(0xFFFFFFFFu, s3, 1);

        if (!(q & 1)) {
            c_a = s0 * c_a + s1 * x0;
            float hA = x1 * tanhf(c_a);
            c_b = s2 * c_b + s3 * x2;
            float hB = x3 * tanhf(c_b);

            float* hw = (t & 1) ? h0 : h1;
            hw[row0*HID + u] = hA;
            hw[(row0+8)*HID + u] = hB;
            g_lstm[((long)t*BATCH + row0)*HID + u] = hA;
            g_lstm[((long)t*BATCH + row0+8)*HID + u] = hB;
            if (t == S_LEN-1) {
                g_c[row0*HID + u] = c_a;
                g_c[(row0+8)*HID + u] = c_b;
            }
        }

        __syncthreads();
        if (tid == 0) {
            __threadfence();
            atomicAdd(&g_cnt, 1u);
        }
    }
}

// ---------------------------------------------------------------------------
// Row softmax over 512-wide rows. One block (128 threads) per row.
// ---------------------------------------------------------------------------
__global__ __launch_bounds__(128)
void softmax512(float* __restrict__ s)
{
    float* row = s + (size_t)blockIdx.x * 512;
    int tid = threadIdx.x;
    float v0 = row[tid], v1 = row[tid+128], v2 = row[tid+256], v3 = row[tid+384];
    float mx = fmaxf(fmaxf(v0, v1), fmaxf(v2, v3));
    __shared__ float sm[4];
    __shared__ float ss[4];
    #pragma unroll
    for (int off = 16; off > 0; off >>= 1)
        mx = fmaxf(mx, __shfl_xor_sync(0xFFFFFFFFu, mx, off));
    if ((tid & 31) == 0) sm[tid >> 5] = mx;
    __syncthreads();
    mx = fmaxf(fmaxf(sm[0], sm[1]), fmaxf(sm[2], sm[3]));
    v0 = expf(v0 - mx); v1 = expf(v1 - mx); v2 = expf(v2 - mx); v3 = expf(v3 - mx);
    float sum = v0 + v1 + v2 + v3;
    #pragma unroll
    for (int off = 16; off > 0; off >>= 1)
        sum += __shfl_xor_sync(0xFFFFFFFFu, sum, off);
    if ((tid & 31) == 0) ss[tid >> 5] = sum;
    __syncthreads();
    sum = ss[0] + ss[1] + ss[2] + ss[3];
    float inv = 1.f / sum;
    row[tid] = v0*inv; row[tid+128] = v1*inv; row[tid+256] = v2*inv; row[tid+384] = v3*inv;
}

__global__ void copy_hc(const float* __restrict__ h, const float* __restrict__ c,
                        float* __restrict__ out)
{
    int i = blockIdx.x * blockDim.x + threadIdx.x;
    if (i < BATCH*HID) {
        out[DEC_ELEMS + i] = h[i];
        out[DEC_ELEMS + BATCH*HID + i] = c[i];
    }
}

// ---------------------------------------------------------------------------
// Host orchestration (graph-capturable: launches only)
// ---------------------------------------------------------------------------
extern "C" void kernel_launch(void* const* d_in, const int* in_sizes, int n_in,
                              void* d_out, int out_size)
{
    const float* x  = (const float*)d_in[0];
    const float* Wf = (const float*)d_in[1];
    const float* bf = (const float*)d_in[2];
    const float* Wi = (const float*)d_in[3];
    const float* bi = (const float*)d_in[4];
    const float* Wg = (const float*)d_in[5];
    const float* bg = (const float*)d_in[6];
    const float* Wo = (const float*)d_in[7];
    const float* bo = (const float*)d_in[8];
    const float* Wq = (const float*)d_in[9];
    const float* bq = (const float*)d_in[10];
    const float* Wk = (const float*)d_in[11];
    const float* bk = (const float*)d_in[12];
    const float* Wv = (const float*)d_in[13];
    const float* bv = (const float*)d_in[14];
    float* out = (float*)d_out;

    float *Wxp, *biasp, *gx, *lstm, *hbase, *c, *PQ, *PK, *PV;
    cudaGetSymbolAddress((void**)&Wxp,   g_Wxp);
    cudaGetSymbolAddress((void**)&biasp, g_biasp);
    cudaGetSymbolAddress((void**)&gx,    g_gx);
    cudaGetSymbolAddress((void**)&lstm,  g_lstm);
    cudaGetSymbolAddress((void**)&hbase, g_h);
    cudaGetSymbolAddress((void**)&c,     g_c);
    cudaGetSymbolAddress((void**)&PQ,    g_PQ);
    cudaGetSymbolAddress((void**)&PK,    g_PK);
    cudaGetSymbolAddress((void**)&PV,    g_PV);
    float* h0 = hbase;

    const int SMEM_LSTM = (96*HPAD) * (int)sizeof(float);   // 198,144 B
    cudaFuncSetAttribute(lstm_persistent,
                         cudaFuncAttributeMaxDynamicSharedMemorySize, SMEM_LSTM);

    // 1. repack weights + zero h0 / barrier counter
    pack_weights<<<(768*HID + 255)/256, 256>>>(Wf, Wi, Wg, Wo, bf, bi, bg, bo);
    zero_state<<<(BATCH*HID + 255)/256, 256>>>();

    // 2. x-side gate preacts: gx = x @ Wxp + biasp   [32768,256]@[256,2048]
    gemm_tf32<<<dim3(G4/64, ROWS/128, 1), 256>>>(
        x, D_IN, 0, 0, Wxp, G4, 0, 0, biasp, gx, G4, 0, 0, D_IN, 1.0f, 0);

    // 3. recurrence: persistent tensor-core kernel, device grid barrier per step
    lstm_persistent<<<NB, 256, SMEM_LSTM>>>(gx);

    // 4. Q/K/V projections: [32768,512]@[512,512]+b
    gemm_tf32<<<dim3(HID/64, ROWS/128, 1), 256>>>(
        lstm, HID, 0, 0, Wq, HID, 0, 0, bq, PQ, HID, 0, 0, HID, 1.0f, 0);
    gemm_tf32<<<dim3(HID/64, ROWS/128, 1), 256>>>(
        lstm, HID, 0, 0, Wk, HID, 0, 0, bk, PK, HID, 0, 0, HID, 1.0f, 0);
    gemm_tf32<<<dim3(HID/64, ROWS/128, 1), 256>>>(
        lstm, HID, 0, 0, Wv, HID, 0, 0, bv, PV, HID, 0, 0, HID, 1.0f, 0);

    // 5. scores = (Q @ K^T)/sqrt(dk), z = b'*4 + h
    const long pbS = (long)S_LEN * HID;          // per-b' stride in PQ/PK/PV
    const long phS = DK;                         // per-h stride
    const long scB = 4L * S_LEN * S_LEN;         // scores per-b' stride
    const long scH = (long)S_LEN * S_LEN;        // scores per-h stride
    float scale = 1.0f / sqrtf((float)DK);
    gemm_tf32<<<dim3(S_LEN/64, S_LEN/128, BATCH*NH), 256>>>(
        PQ, HID, pbS, phS,
        PK, HID, pbS, phS,
        (const float*)0,
        gx /* reused as scores */, S_LEN, scB, scH, DK, scale, 1);

    // 6. softmax over last axis
    softmax512<<<BATCH*NH*S_LEN, 128>>>(gx);

    // 7. out = attn @ V, written directly in decoded layout:
    //    d_out[(s*64 + b')*512 + h*128 + d]
    gemm_tf32<<<dim3(DK/64, S_LEN/128, BATCH*NH), 256>>>(
        gx, S_LEN, scB, scH,
        PV, HID, pbS, phS,
        (const float*)0,
        out, BATCH*HID, (long)HID, (long)DK, S_LEN, 1.0f, 0);

    // 8. final hidden/cell state (after step 511 the live h buffer is h0)
    copy_hc<<<(BATCH*HID + 255)/256, 256>>>(h0, c, out);
}

// round 13
// speedup vs baseline: 1.2203x; 1.0950x over previous
#include <cuda_runtime.h>
#include <math.h>
#include <stdint.h>

// ---------------------------------------------------------------------------
// Problem constants
// ---------------------------------------------------------------------------
#define S_LEN   512
#define BATCH   64
#define D_IN    256
#define HID     512
#define G4      2048        // 4 gates * HID, packed unit-major: col = u*4 + gate
#define NH      4
#define DK      128
#define ROWS    (S_LEN*BATCH)        // 32768
#define DEC_ELEMS (S_LEN*BATCH*HID)  // 16777216
#define NB      128                  // persistent LSTM blocks (1/SM -> full chip)
#define HPAD    516                  // padded pitch (floats)
#define APITCH  20                   // gemm A-smem pitch (floats)
#define BPITCH  72                   // gemm B-smem pitch, normal path
#define BTFL    1280                 // gemm B buffer floats (max of 16*72, 64*20)

// ---------------------------------------------------------------------------
// Device scratch (static allocations only — no cudaMalloc allowed)
// ---------------------------------------------------------------------------
__device__ float g_Wxp[D_IN*G4];          //   2 MB  packed input-gate weights
__device__ float g_Whp[HID*G4];           //   4 MB  packed recurrent-gate weights
__device__ float g_biasp[G4];
__device__ float g_gx[ROWS*G4];           // 256 MB  x-side gate preacts; reused as attn scores
__device__ float g_lstm[ROWS*HID];        //  64 MB  lstm_out [S,B,HID]
__device__ float g_h[2][BATCH*HID];       //  h double buffer
__device__ float g_c[BATCH*HID];
__device__ float g_PQ[ROWS*HID];          //  64 MB
__device__ float g_PK[ROWS*HID];
__device__ float g_PV[ROWS*HID];
__device__ unsigned g_cnt;                //  grid barrier counter
// pre-split weight copies (hi = tf32-rounded, lo = raw residual)
__device__ float g_Wxph[D_IN*G4], g_Wxpl[D_IN*G4];   // 2 MB each
__device__ float g_Wqh[HID*HID],  g_Wql[HID*HID];
__device__ float g_Wkh[HID*HID],  g_Wkl[HID*HID];
__device__ float g_Wvh[HID*HID],  g_Wvl[HID*HID];

// ---------------------------------------------------------------------------
// Helpers
// ---------------------------------------------------------------------------
__device__ __forceinline__ float tf32_rnd(float x) {
    uint32_t u; asm("cvt.rna.tf32.f32 %0, %1;" : "=r"(u) : "f"(x));
    return __uint_as_float(u);
}
__device__ __forceinline__ uint32_t fu(float x) { return __float_as_uint(x); }

#define MMA8(cc, a, bb) \
    asm volatile("mma.sync.aligned.m16n8k8.row.col.f32.tf32.tf32.f32 " \
        "{%0,%1,%2,%3},{%4,%5,%6,%7},{%8,%9},{%0,%1,%2,%3};" \
        : "+f"(cc[0]), "+f"(cc[1]), "+f"(cc[2]), "+f"(cc[3]) \
        : "r"(a[0]), "r"(a[1]), "r"(a[2]), "r"(a[3]), "r"(bb[0]), "r"(bb[1]))

#define CPA16(dst, src) \
    asm volatile("cp.async.cg.shared.global [%0], [%1], 16;" :: "r"(dst), "l"(src))

// ---------------------------------------------------------------------------
// Weight repack + splits
// ---------------------------------------------------------------------------
__global__ void pack_weights(const float* __restrict__ Wf, const float* __restrict__ Wi,
                             const float* __restrict__ Wg, const float* __restrict__ Wo,
                             const float* __restrict__ bf, const float* __restrict__ bi,
                             const float* __restrict__ bg, const float* __restrict__ bo)
{
    int idx = blockIdx.x * blockDim.x + threadIdx.x;   // over 768*512
    if (idx < 768*HID) {
        int k = idx / HID, u = idx % HID;
        float vf = Wf[idx], vi = Wi[idx], vg = Wg[idx], vo = Wo[idx];
        float* dst = (k < D_IN) ? (g_Wxp + (long)k*G4) : (g_Whp + (long)(k - D_IN)*G4);
        dst[u*4+0] = vf; dst[u*4+1] = vi; dst[u*4+2] = vg; dst[u*4+3] = vo;
    }
    if (idx < HID) {
        g_biasp[idx*4+0] = bf[idx];
        g_biasp[idx*4+1] = bi[idx];
        g_biasp[idx*4+2] = bg[idx];
        g_biasp[idx*4+3] = bo[idx];
    }
}

__global__ void zero_state()
{
    int i = blockIdx.x * blockDim.x + threadIdx.x;
    if (i < BATCH*HID) { g_h[0][i] = 0.f; g_c[i] = 0.f; }
    if (i == 0) g_cnt = 0u;
}

__global__ void split_wxp()
{
    int i = blockIdx.x * blockDim.x + threadIdx.x;
    if (i < D_IN*G4) {
        float w = g_Wxp[i];
        float hi = tf32_rnd(w);
        g_Wxph[i] = hi;
        g_Wxpl[i] = w - hi;
    }
}

__global__ void split_w(const float* __restrict__ W, float* __restrict__ Wh,
                        float* __restrict__ Wl, int n)
{
    int i = blockIdx.x * blockDim.x + threadIdx.x;
    if (i < n) {
        float w = W[i];
        float hi = tf32_rnd(w);
        Wh[i] = hi;
        Wl[i] = w - hi;
    }
}

// ---------------------------------------------------------------------------
// tf32 3-split GEMM: 128x64 block tile, 256 threads, 2 blocks/SM.
// Raw-residual lo split. Used for scores (transB) and attn@V. Proven R11/R12.
// ---------------------------------------------------------------------------
__global__ __launch_bounds__(256, 2)
void gemm_tf32(const float* __restrict__ A, int lda, long as1, long as2,
               const float* __restrict__ B, int ldb, long bs1, long bs2,
               const float* __restrict__ bias,
               float* __restrict__ C, int ldc, long cs1, long cs2,
               int K, float alpha, int transB)
{
    __shared__ float As[2][128*APITCH];
    __shared__ float Bs[2][BTFL];

    int z = blockIdx.z;
    A += (long)(z >> 2) * as1 + (long)(z & 3) * as2;
    B += (long)(z >> 2) * bs1 + (long)(z & 3) * bs2;
    C += (long)(z >> 2) * cs1 + (long)(z & 3) * cs2;
    int m0 = blockIdx.y * 128, n0 = blockIdx.x * 64;

    int tid = threadIdx.x;
    int warp = tid >> 5, lane = tid & 31;
    int wm = (warp >> 1) * 32, wn = (warp & 1) * 32;
    int r = lane >> 2, q = lane & 3;

    const uint32_t a_smem = (uint32_t)__cvta_generic_to_shared(&As[0][0]);
    const uint32_t b_smem = (uint32_t)__cvta_generic_to_shared(&Bs[0][0]);
    const uint32_t abuf = 128*APITCH*4;
    const uint32_t bbuf = BTFL*4;

    int am0 = tid >> 2, ac = tid & 3;
    int bkr = tid >> 4, bc = tid & 15;
    int bn = tid >> 2, bc4 = tid & 3;

    int KT = K >> 4;

    auto issue = [&](int kt) {
        int k0 = kt << 4, buf = kt & 1;
        CPA16(a_smem + buf*abuf + (uint32_t)(am0*APITCH + ac*4)*4,
              A + (long)(m0 + am0)*lda + k0 + ac*4);
        CPA16(a_smem + buf*abuf + (uint32_t)((am0+64)*APITCH + ac*4)*4,
              A + (long)(m0 + am0 + 64)*lda + k0 + ac*4);
        if (!transB) {
            CPA16(b_smem + buf*bbuf + (uint32_t)(bkr*BPITCH + bc*4)*4,
                  B + (long)(k0 + bkr)*ldb + n0 + bc*4);
        } else {
            CPA16(b_smem + buf*bbuf + (uint32_t)(bn*APITCH + bc4*4)*4,
                  B + (long)(n0 + bn)*ldb + k0 + bc4*4);
        }
        asm volatile("cp.async.commit_group;");
    };

    float acc[2][4][4];
    #pragma unroll
    for (int mt = 0; mt < 2; mt++)
        #pragma unroll
        for (int nt = 0; nt < 4; nt++)
            #pragma unroll
            for (int e = 0; e < 4; e++) acc[mt][nt][e] = 0.f;

    issue(0);
    for (int kt = 0; kt < KT; kt++) {
        if (kt + 1 < KT) {
            issue(kt + 1);
            asm volatile("cp.async.wait_group 1;" ::: "memory");
        } else {
            asm volatile("cp.async.wait_group 0;" ::: "memory");
        }
        __syncthreads();

        const float* Ab = &As[kt & 1][0];
        const float* Bb = &Bs[kt & 1][0];
        #pragma unroll
        for (int p = 0; p < 2; p++) {
            int kb = p*8;
            uint32_t bh[4][2], bl[4][2];
            #pragma unroll
            for (int nt = 0; nt < 4; nt++) {
                int n = wn + nt*8 + r;
                float br0, br1;
                if (!transB) {
                    br0 = Bb[(kb+q  )*BPITCH + n];
                    br1 = Bb[(kb+q+4)*BPITCH + n];
                } else {
                    br0 = Bb[n*APITCH + kb+q  ];
                    br1 = Bb[n*APITCH + kb+q+4];
                }
                float bh0f = tf32_rnd(br0), bh1f = tf32_rnd(br1);
                bh[nt][0] = fu(bh0f);        bh[nt][1] = fu(bh1f);
                bl[nt][0] = fu(br0 - bh0f);  bl[nt][1] = fu(br1 - bh1f);
            }
            #pragma unroll
            for (int mt = 0; mt < 2; mt++) {
                int m = wm + mt*16 + r;
                float ar[4];
                ar[0] = Ab[ m     *APITCH + kb+q  ];
                ar[1] = Ab[(m+8)  *APITCH + kb+q  ];
                ar[2] = Ab[ m     *APITCH + kb+q+4];
                ar[3] = Ab[(m+8)  *APITCH + kb+q+4];
                uint32_t ah[4], al[4];
                #pragma unroll
                for (int e = 0; e < 4; e++) {
                    float hi = tf32_rnd(ar[e]);
                    ah[e] = fu(hi);
                    al[e] = fu(ar[e] - hi);
                }
                #pragma unroll
                for (int nt = 0; nt < 4; nt++) {
                    MMA8(acc[mt][nt], ah, bh[nt]);
                    MMA8(acc[mt][nt], ah, bl[nt]);
                    MMA8(acc[mt][nt], al, bh[nt]);
                }
            }
        }
        __syncthreads();
    }

    #pragma unroll
    for (int mt = 0; mt < 2; mt++)
        #pragma unroll
        for (int nt = 0; nt < 4; nt++) {
            int mrow = m0 + wm + mt*16 + r;
            int ncol = n0 + wn + nt*8 + q*2;
            float b0 = bias ? bias[ncol]   : 0.f;
            float b1 = bias ? bias[ncol+1] : 0.f;
            C[(long)mrow*ldc + ncol  ]     = alpha*acc[mt][nt][0] + b0;
            C[(long)mrow*ldc + ncol+1]     = alpha*acc[mt][nt][1] + b1;
            C[(long)(mrow+8)*ldc + ncol  ] = alpha*acc[mt][nt][2] + b0;
            C[(long)(mrow+8)*ldc + ncol+1] = alpha*acc[mt][nt][3] + b1;
        }
}

// ---------------------------------------------------------------------------
// tf32 3-split GEMM, PRE-SPLIT B variant (normal orientation only).
// B given as hi/lo global arrays [K][N]; no B-side conversions in the k-loop.
// Used for gx (Wxp) and Q/K/V projections. Numerically identical to gemm_tf32.
// ---------------------------------------------------------------------------
__global__ __launch_bounds__(256, 2)
void gemm_tf32_pb(const float* __restrict__ A, int lda,
                  const float* __restrict__ Bh, const float* __restrict__ Bl, int ldb,
                  const float* __restrict__ bias,
                  float* __restrict__ C, int ldc,
                  int K, float alpha)
{
    __shared__ float As [2][128*APITCH];
    __shared__ float Bhs[2][16*BPITCH];
    __shared__ float Bls[2][16*BPITCH];

    int m0 = blockIdx.y * 128, n0 = blockIdx.x * 64;

    int tid = threadIdx.x;
    int warp = tid >> 5, lane = tid & 31;
    int wm = (warp >> 1) * 32, wn = (warp & 1) * 32;
    int r = lane >> 2, q = lane & 3;

    const uint32_t a_smem  = (uint32_t)__cvta_generic_to_shared(&As[0][0]);
    const uint32_t bh_smem = (uint32_t)__cvta_generic_to_shared(&Bhs[0][0]);
    const uint32_t bl_smem = (uint32_t)__cvta_generic_to_shared(&Bls[0][0]);
    const uint32_t abuf = 128*APITCH*4;
    const uint32_t bbuf = 16*BPITCH*4;

    int am0 = tid >> 2, ac = tid & 3;
    int bkr = tid >> 4, bc = tid & 15;

    int KT = K >> 4;

    auto issue = [&](int kt) {
        int k0 = kt << 4, buf = kt & 1;
        CPA16(a_smem + buf*abuf + (uint32_t)(am0*APITCH + ac*4)*4,
              A + (long)(m0 + am0)*lda + k0 + ac*4);
        CPA16(a_smem + buf*abuf + (uint32_t)((am0+64)*APITCH + ac*4)*4,
              A + (long)(m0 + am0 + 64)*lda + k0 + ac*4);
        CPA16(bh_smem + buf*bbuf + (uint32_t)(bkr*BPITCH + bc*4)*4,
              Bh + (long)(k0 + bkr)*ldb + n0 + bc*4);
        CPA16(bl_smem + buf*bbuf + (uint32_t)(bkr*BPITCH + bc*4)*4,
              Bl + (long)(k0 + bkr)*ldb + n0 + bc*4);
        asm volatile("cp.async.commit_group;");
    };

    float acc[2][4][4];
    #pragma unroll
    for (int mt = 0; mt < 2; mt++)
        #pragma unroll
        for (int nt = 0; nt < 4; nt++)
            #pragma unroll
            for (int e = 0; e < 4; e++) acc[mt][nt][e] = 0.f;

    issue(0);
    for (int kt = 0; kt < KT; kt++) {
        if (kt + 1 < KT) {
            issue(kt + 1);
            asm volatile("cp.async.wait_group 1;" ::: "memory");
        } else {
            asm volatile("cp.async.wait_group 0;" ::: "memory");
        }
        __syncthreads();

        const float* Abb = &As [kt & 1][0];
        const float* Bhb = &Bhs[kt & 1][0];
        const float* Blb = &Bls[kt & 1][0];
        #pragma unroll
        for (int p = 0; p < 2; p++) {
            int kb = p*8;
            uint32_t bh[4][2], bl[4][2];
            #pragma unroll
            for (int nt = 0; nt < 4; nt++) {
                int n = wn + nt*8 + r;
                bh[nt][0] = fu(Bhb[(kb+q  )*BPITCH + n]);
                bh[nt][1] = fu(Bhb[(kb+q+4)*BPITCH + n]);
                bl[nt][0] = fu(Blb[(kb+q  )*BPITCH + n]);
                bl[nt][1] = fu(Blb[(kb+q+4)*BPITCH + n]);
            }
            #pragma unroll
            for (int mt = 0; mt < 2; mt++) {
                int m = wm + mt*16 + r;
                float ar[4];
                ar[0] = Abb[ m     *APITCH + kb+q  ];
                ar[1] = Abb[(m+8)  *APITCH + kb+q  ];
                ar[2] = Abb[ m     *APITCH + kb+q+4];
                ar[3] = Abb[(m+8)  *APITCH + kb+q+4];
                uint32_t ah[4], al[4];
                #pragma unroll
                for (int e = 0; e < 4; e++) {
                    float hi = tf32_rnd(ar[e]);
                    ah[e] = fu(hi);
                    al[e] = fu(ar[e] - hi);
                }
                #pragma unroll
                for (int nt = 0; nt < 4; nt++) {
                    MMA8(acc[mt][nt], ah, bh[nt]);
                    MMA8(acc[mt][nt], ah, bl[nt]);
                    MMA8(acc[mt][nt], al, bh[nt]);
                }
            }
        }
        __syncthreads();
    }

    #pragma unroll
    for (int mt = 0; mt < 2; mt++)
        #pragma unroll
        for (int nt = 0; nt < 4; nt++) {
            int mrow = m0 + wm + mt*16 + r;
            int ncol = n0 + wn + nt*8 + q*2;
            float b0 = bias ? bias[ncol]   : 0.f;
            float b1 = bias ? bias[ncol+1] : 0.f;
            C[(long)mrow*ldc + ncol  ]     = alpha*acc[mt][nt][0] + b0;
            C[(long)mrow*ldc + ncol+1]     = alpha*acc[mt][nt][1] + b1;
            C[(long)(mrow+8)*ldc + ncol  ] = alpha*acc[mt][nt][2] + b0;
            C[(long)(mrow+8)*ldc + ncol+1] = alpha*acc[mt][nt][3] + b1;
        }
}

// ---------------------------------------------------------------------------
// Persistent LSTM recurrence — tensor-core matvec (NB=128, R12 math) with
// PIPELINED h staging: cp.async in two k-half commit groups; mma on half 0
// overlaps the in-flight load of half 1.
// ---------------------------------------------------------------------------
__global__ __launch_bounds__(256)
void lstm_persistent(const float* __restrict__ gx)
{
    extern __shared__ float sm[];
    float* Bhs = sm;                    // [16][516] presplit weight hi
    float* Bls = sm + 16*HPAD;          // [16][516] presplit weight lo (raw residual)
    float* hs  = sm + 32*HPAD;          // [64][516] staged h

    const int tid = threadIdx.x, bid = blockIdx.x;
    const int c0 = bid * 16;
    const int warp = tid >> 5, lane = tid & 31;
    const int mt = warp >> 5 ? 0 : (warp >> 1), nt = warp & 1;   // mt = warp>>1
    const int r = lane >> 2, q = lane & 3;
    const int row0 = (warp >> 1)*16 + r;
    (void)mt;

    for (int idx = tid; idx < 16*512; idx += 256) {
        int k = idx >> 4, j = idx & 15;
        float w = g_Whp[(long)k*G4 + c0 + j];
        float hi = tf32_rnd(w);
        Bhs[j*HPAD + k] = hi;
        Bls[j*HPAD + k] = w - hi;
    }

    float c_a = 0.f, c_b = 0.f;
    float* h0 = g_h[0];
    float* h1 = g_h[1];
    const int u = bid*4 + nt*2 + (q >> 1);

    const uint32_t hs_u32 = (uint32_t)__cvta_generic_to_shared(hs);

    __syncthreads();

    const float* arow0 = hs + row0*HPAD;
    const float* arow8 = arow0 + 8*HPAD;
    const float* brh   = Bhs + (nt*8 + r)*HPAD;
    const float* brl   = Bls + (nt*8 + r)*HPAD;

    for (int t = 0; t < S_LEN; t++) {
        const float* gbase = gx + ((long)t*BATCH)*G4 + c0 + nt*8 + 2*q;
        const float2 gA = *(const float2*)(gbase + (long)row0*G4);
        const float2 gB = *(const float2*)(gbase + (long)(row0+8)*G4);

        if (t) {
            if (tid == 0) {
                unsigned target = (unsigned)t * NB;
                while (*(volatile unsigned*)&g_cnt < target) { }
                __threadfence();
            }
            __syncthreads();
        }

        // ---- stage h: two cp.async commit groups (k-halves) ----
        const float* hr = (t & 1) ? h1 : h0;
        #pragma unroll 4
        for (int i = 0; i < 16; i++) {
            int idx = tid + i*256;               // 0..4095
            int rr = idx >> 6, cc = idx & 63;    // row, k-chunk (half 0)
            CPA16(hs_u32 + (uint32_t)(rr*HPAD + cc*4)*4,
                  hr + rr*HID + cc*4);
        }
        asm volatile("cp.async.commit_group;");
        #pragma unroll 4
        for (int i = 0; i < 16; i++) {
            int idx = tid + i*256;
            int rr = idx >> 6, cc = idx & 63;    // half 1: k offset +256
            CPA16(hs_u32 + (uint32_t)(rr*HPAD + 256 + cc*4)*4,
                  hr + rr*HID + 256 + cc*4);
        }
        asm volatile("cp.async.commit_group;");

        float acc[4] = {0.f, 0.f, 0.f, 0.f};

        asm volatile("cp.async.wait_group 1;" ::: "memory");
        __syncthreads();
        // ---- mma over k-half 0 while half 1 is still loading ----
        #pragma unroll 4
        for (int k0 = 0; k0 < 256; k0 += 8) {
            float a0 = arow0[k0+q  ];
            float a1 = arow8[k0+q  ];
            float a2 = arow0[k0+q+4];
            float a3 = arow8[k0+q+4];
            float h0f = tf32_rnd(a0), h1f = tf32_rnd(a1);
            float h2f = tf32_rnd(a2), h3f = tf32_rnd(a3);
            uint32_t ah[4] = { fu(h0f), fu(h1f), fu(h2f), fu(h3f) };
            uint32_t al[4] = { fu(a0 - h0f), fu(a1 - h1f),
                               fu(a2 - h2f), fu(a3 - h3f) };
            uint32_t bh[2] = { fu(brh[k0+q]), fu(brh[k0+q+4]) };
            uint32_t bl[2] = { fu(brl[k0+q]), fu(brl[k0+q+4]) };
            MMA8(acc, ah, bh);
            MMA8(acc, ah, bl);
            MMA8(acc, al, bh);
        }
        asm volatile("cp.async.wait_group 0;" ::: "memory");
        __syncthreads();
        // ---- mma over k-half 1 ----
        #pragma unroll 4
        for (int k0 = 256; k0 < 512; k0 += 8) {
            float a0 = arow0[k0+q  ];
            float a1 = arow8[k0+q  ];
            float a2 = arow0[k0+q+4];
            float a3 = arow8[k0+q+4];
            float h0f = tf32_rnd(a0), h1f = tf32_rnd(a1);
            float h2f = tf32_rnd(a2), h3f = tf32_rnd(a3);
            uint32_t ah[4] = { fu(h0f), fu(h1f), fu(h2f), fu(h3f) };
            uint32_t al[4] = { fu(a0 - h0f), fu(a1 - h1f),
                               fu(a2 - h2f), fu(a3 - h3f) };
            uint32_t bh[2] = { fu(brh[k0+q]), fu(brh[k0+q+4]) };
            uint32_t bl[2] = { fu(brl[k0+q]), fu(brl[k0+q+4]) };
            MMA8(acc, ah, bh);
            MMA8(acc, ah, bl);
            MMA8(acc, al, bh);
        }

        float p0 = acc[0] + gA.x;
        float p1 = acc[1] + gA.y;
        float p2 = acc[2] + gB.x;
        float p3 = acc[3] + gB.y;

        float s0, s1, s2, s3;
        if (q & 1) {
            s0 = tanhf(p0);
            s1 = 1.f / (1.f + expf(-p1));
            s2 = tanhf(p2);
            s3 = 1.f / (1.f + expf(-p3));
        } else {
            s0 = 1.f / (1.f + expf(-p0));
            s1 = 1.f / (1.f + expf(-p1));
            s2 = 1.f / (1.f + expf(-p2));
            s3 = 1.f / (1.f + expf(-p3));
        }
        float x0 = __shfl_xor_sync(0xFFFFFFFFu, s0, 1);
        float x1 = __shfl_xor_sync(0xFFFFFFFFu, s1, 1);
        float x2 = __shfl_xor_sync(0xFFFFFFFFu, s2, 1);
        float x3 = __shfl_xor_sync(0xFFFFFFFFu, s3, 1);

        if (!(q & 1)) {
            c_a = s0 * c_a + s1 * x0;
            float hA = x1 * tanhf(c_a);
            c_b = s2 * c_b + s3 * x2;
            float hB = x3 * tanhf(c_b);

            float* hw = (t & 1) ? h0 : h1;
            hw[row0*HID + u] = hA;
            hw[(row0+8)*HID + u] = hB;
            g_lstm[((long)t*BATCH + row0)*HID + u] = hA;
            g_lstm[((long)t*BATCH + row0+8)*HID + u] = hB;
            if (t == S_LEN-1) {
                g_c[row0*HID + u] = c_a;
                g_c[(row0+8)*HID + u] = c_b;
            }
        }

        __syncthreads();
        if (tid == 0) {
            __threadfence();
            atomicAdd(&g_cnt, 1u);
        }
    }
}

// ---------------------------------------------------------------------------
// Row softmax over 512-wide rows. One block (128 threads) per row.
// ---------------------------------------------------------------------------
__global__ __launch_bounds__(128)
void softmax512(float* __restrict__ s)
{
    float* row = s + (size_t)blockIdx.x * 512;
    int tid = threadIdx.x;
    float v0 = row[tid], v1 = row[tid+128], v2 = row[tid+256], v3 = row[tid+384];
    float mx = fmaxf(fmaxf(v0, v1), fmaxf(v2, v3));
    __shared__ float sm[4];
    __shared__ float ss[4];
    #pragma unroll
    for (int off = 16; off > 0; off >>= 1)
        mx = fmaxf(mx, __shfl_xor_sync(0xFFFFFFFFu, mx, off));
    if ((tid & 31) == 0) sm[tid >> 5] = mx;
    __syncthreads();
    mx = fmaxf(fmaxf(sm[0], sm[1]), fmaxf(sm[2], sm[3]));
    v0 = expf(v0 - mx); v1 = expf(v1 - mx); v2 = expf(v2 - mx); v3 = expf(v3 - mx);
    float sum = v0 + v1 + v2 + v3;
    #pragma unroll
    for (int off = 16; off > 0; off >>= 1)
        sum += __shfl_xor_sync(0xFFFFFFFFu, sum, off);
    if ((tid & 31) == 0) ss[tid >> 5] = sum;
    __syncthreads();
    sum = ss[0] + ss[1] + ss[2] + ss[3];
    float inv = 1.f / sum;
    row[tid] = v0*inv; row[tid+128] = v1*inv; row[tid+256] = v2*inv; row[tid+384] = v3*inv;
}

__global__ void copy_hc(const float* __restrict__ h, const float* __restrict__ c,
                        float* __restrict__ out)
{
    int i = blockIdx.x * blockDim.x + threadIdx.x;
    if (i < BATCH*HID) {
        out[DEC_ELEMS + i] = h[i];
        out[DEC_ELEMS + BATCH*HID + i] = c[i];
    }
}

// ---------------------------------------------------------------------------
// Host orchestration (graph-capturable: launches only)
// ---------------------------------------------------------------------------
extern "C" void kernel_launch(void* const* d_in, const int* in_sizes, int n_in,
                              void* d_out, int out_size)
{
    const float* x  = (const float*)d_in[0];
    const float* Wf = (const float*)d_in[1];
    const float* bf = (const float*)d_in[2];
    const float* Wi = (const float*)d_in[3];
    const float* bi = (const float*)d_in[4];
    const float* Wg = (const float*)d_in[5];
    const float* bg = (const float*)d_in[6];
    const float* Wo = (const float*)d_in[7];
    const float* bo = (const float*)d_in[8];
    const float* Wq = (const float*)d_in[9];
    const float* bq = (const float*)d_in[10];
    const float* Wk = (const float*)d_in[11];
    const float* bk = (const float*)d_in[12];
    const float* Wv = (const float*)d_in[13];
    const float* bv = (const float*)d_in[14];
    float* out = (float*)d_out;

    float *biasp, *gx, *lstm, *hbase, *c, *PQ, *PK, *PV;
    float *Wxph, *Wxpl, *Wqh, *Wql, *Wkh, *Wkl, *Wvh, *Wvl;
    cudaGetSymbolAddress((void**)&biasp, g_biasp);
    cudaGetSymbolAddress((void**)&gx,    g_gx);
    cudaGetSymbolAddress((void**)&lstm,  g_lstm);
    cudaGetSymbolAddress((void**)&hbase, g_h);
    cudaGetSymbolAddress((void**)&c,     g_c);
    cudaGetSymbolAddress((void**)&PQ,    g_PQ);
    cudaGetSymbolAddress((void**)&PK,    g_PK);
    cudaGetSymbolAddress((void**)&PV,    g_PV);
    cudaGetSymbolAddress((void**)&Wxph,  g_Wxph);
    cudaGetSymbolAddress((void**)&Wxpl,  g_Wxpl);
    cudaGetSymbolAddress((void**)&Wqh,   g_Wqh);
    cudaGetSymbolAddress((void**)&Wql,   g_Wql);
    cudaGetSymbolAddress((void**)&Wkh,   g_Wkh);
    cudaGetSymbolAddress((void**)&Wkl,   g_Wkl);
    cudaGetSymbolAddress((void**)&Wvh,   g_Wvh);
    cudaGetSymbolAddress((void**)&Wvl,   g_Wvl);
    float* h0 = hbase;

    const int SMEM_LSTM = (96*HPAD) * (int)sizeof(float);   // 198,144 B
    cudaFuncSetAttribute(lstm_persistent,
                         cudaFuncAttributeMaxDynamicSharedMemorySize, SMEM_LSTM);

    // 1. repack + zero + pre-split weights
    pack_weights<<<(768*HID + 255)/256, 256>>>(Wf, Wi, Wg, Wo, bf, bi, bg, bo);
    zero_state<<<(BATCH*HID + 255)/256, 256>>>();
    split_wxp<<<(D_IN*G4 + 255)/256, 256>>>();
    split_w<<<(HID*HID + 255)/256, 256>>>(Wq, Wqh, Wql, HID*HID);
    split_w<<<(HID*HID + 255)/256, 256>>>(Wk, Wkh, Wkl, HID*HID);
    split_w<<<(HID*HID + 255)/256, 256>>>(Wv, Wvh, Wvl, HID*HID);

    // 2. x-side gate preacts: gx = x @ Wxp + biasp   [32768,256]@[256,2048]
    gemm_tf32_pb<<<dim3(G4/64, ROWS/128), 256>>>(
        x, D_IN, Wxph, Wxpl, G4, biasp, gx, G4, D_IN, 1.0f);

    // 3. recurrence: persistent tensor-core kernel, device grid barrier per step
    lstm_persistent<<<NB, 256, SMEM_LSTM>>>(gx);

    // 4. Q/K/V projections: [32768,512]@[512,512]+b
    gemm_tf32_pb<<<dim3(HID/64, ROWS/128), 256>>>(
        lstm, HID, Wqh, Wql, HID, bq, PQ, HID, HID, 1.0f);
    gemm_tf32_pb<<<dim3(HID/64, ROWS/128), 256>>>(
        lstm, HID, Wkh, Wkl, HID, bk, PK, HID, HID, 1.0f);
    gemm_tf32_pb<<<dim3(HID/64, ROWS/128), 256>>>(
        lstm, HID, Wvh, Wvl, HID, bv, PV, HID, HID, 1.0f);

    // 5. scores = (Q @ K^T)/sqrt(dk), z = b'*4 + h
    const long pbS = (long)S_LEN * HID;
    const long phS = DK;
    const long scB = 4L * S_LEN * S_LEN;
    const long scH = (long)S_LEN * S_LEN;
    float scale = 1.0f / sqrtf((float)DK);
    gemm_tf32<<<dim3(S_LEN/64, S_LEN/128, BATCH*NH), 256>>>(
        PQ, HID, pbS, phS,
        PK, HID, pbS, phS,
        (const float*)0,
        gx /* reused as scores */, S_LEN, scB, scH, DK, scale, 1);

    // 6. softmax over last axis
    softmax512<<<BATCH*NH*S_LEN, 128>>>(gx);

    // 7. out = attn @ V, decoded layout d_out[(s*64 + b')*512 + h*128 + d]
    gemm_tf32<<<dim3(DK/64, S_LEN/128, BATCH*NH), 256>>>(
        gx, S_LEN, scB, scH,
        PV, HID, pbS, phS,
        (const float*)0,
        out, BATCH*HID, (long)HID, (long)DK, S_LEN, 1.0f, 0);

    // 8. final hidden/cell state (after step 511 the live h buffer is h0)
    copy_hc<<<(BATCH*HID + 255)/256, 256>>>(h0, c, out);
}

// round 14
// speedup vs baseline: 1.2483x; 1.0229x over previous
#include <cuda_runtime.h>
#include <math.h>
#include <stdint.h>

// ---------------------------------------------------------------------------
// Problem constants
// ---------------------------------------------------------------------------
#define S_LEN   512
#define BATCH   64
#define D_IN    256
#define HID     512
#define G4      2048        // 4 gates * HID, packed unit-major: col = u*4 + gate
#define NH      4
#define DK      128
#define ROWS    (S_LEN*BATCH)        // 32768
#define DEC_ELEMS (S_LEN*BATCH*HID)  // 16777216
#define NB      128                  // persistent LSTM blocks (1/SM -> full chip)
#define HPAD    516                  // padded pitch (floats)
#define APITCH  20                   // gemm A-smem pitch (floats)
#define BPITCH  72                   // gemm B-smem pitch, normal path
#define BTFL    1280                 // gemm B buffer floats (max of 16*72, 64*20)

// ---------------------------------------------------------------------------
// Device scratch (static allocations only — no cudaMalloc allowed)
// ---------------------------------------------------------------------------
__device__ float g_Wxp[D_IN*G4];          //   2 MB  packed input-gate weights
__device__ float g_Whp[HID*G4];           //   4 MB  packed recurrent-gate weights
__device__ float g_biasp[G4];
__device__ float g_gx[ROWS*G4];           // 256 MB  x-side gate preacts; reused as attn scores
__device__ float g_lstm[ROWS*HID];        //  64 MB  lstm_out [S,B,HID]
__device__ float g_h[2][BATCH*HID];       //  h double buffer
__device__ float g_c[BATCH*HID];
__device__ float g_PQ[ROWS*HID];          //  64 MB
__device__ float g_PK[ROWS*HID];
__device__ float g_PV[ROWS*HID];
__device__ unsigned g_cnt;                //  grid barrier counter
// pre-split weight copies (hi = tf32-rounded, lo = raw residual)
__device__ float g_Wxph[D_IN*G4], g_Wxpl[D_IN*G4];   // 2 MB each
__device__ float g_Wqh[HID*HID],  g_Wql[HID*HID];
__device__ float g_Wkh[HID*HID],  g_Wkl[HID*HID];
__device__ float g_Wvh[HID*HID],  g_Wvl[HID*HID];

// ---------------------------------------------------------------------------
// Helpers
// ---------------------------------------------------------------------------
__device__ __forceinline__ float tf32_rnd(float x) {
    uint32_t u; asm("cvt.rna.tf32.f32 %0, %1;" : "=r"(u) : "f"(x));
    return __uint_as_float(u);
}
__device__ __forceinline__ uint32_t fu(float x) { return __float_as_uint(x); }

#define MMA8(cc, a, bb) \
    asm volatile("mma.sync.aligned.m16n8k8.row.col.f32.tf32.tf32.f32 " \
        "{%0,%1,%2,%3},{%4,%5,%6,%7},{%8,%9},{%0,%1,%2,%3};" \
        : "+f"(cc[0]), "+f"(cc[1]), "+f"(cc[2]), "+f"(cc[3]) \
        : "r"(a[0]), "r"(a[1]), "r"(a[2]), "r"(a[3]), "r"(bb[0]), "r"(bb[1]))

#define CPA16(dst, src) \
    asm volatile("cp.async.cg.shared.global [%0], [%1], 16;" :: "r"(dst), "l"(src))

// ---------------------------------------------------------------------------
// Weight repack + splits
// ---------------------------------------------------------------------------
__global__ void pack_weights(const float* __restrict__ Wf, const float* __restrict__ Wi,
                             const float* __restrict__ Wg, const float* __restrict__ Wo,
                             const float* __restrict__ bf, const float* __restrict__ bi,
                             const float* __restrict__ bg, const float* __restrict__ bo)
{
    int idx = blockIdx.x * blockDim.x + threadIdx.x;   // over 768*512
    if (idx < 768*HID) {
        int k = idx / HID, u = idx % HID;
        float vf = Wf[idx], vi = Wi[idx], vg = Wg[idx], vo = Wo[idx];
        float* dst = (k < D_IN) ? (g_Wxp + (long)k*G4) : (g_Whp + (long)(k - D_IN)*G4);
        dst[u*4+0] = vf; dst[u*4+1] = vi; dst[u*4+2] = vg; dst[u*4+3] = vo;
    }
    if (idx < HID) {
        g_biasp[idx*4+0] = bf[idx];
        g_biasp[idx*4+1] = bi[idx];
        g_biasp[idx*4+2] = bg[idx];
        g_biasp[idx*4+3] = bo[idx];
    }
}

__global__ void zero_state()
{
    int i = blockIdx.x * blockDim.x + threadIdx.x;
    if (i < BATCH*HID) { g_h[0][i] = 0.f; g_c[i] = 0.f; }
    if (i == 0) g_cnt = 0u;
}

__global__ void split_wxp()
{
    int i = blockIdx.x * blockDim.x + threadIdx.x;
    if (i < D_IN*G4) {
        float w = g_Wxp[i];
        float hi = tf32_rnd(w);
        g_Wxph[i] = hi;
        g_Wxpl[i] = w - hi;
    }
}

__global__ void split_w(const float* __restrict__ W, float* __restrict__ Wh,
                        float* __restrict__ Wl, int n)
{
    int i = blockIdx.x * blockDim.x + threadIdx.x;
    if (i < n) {
        float w = W[i];
        float hi = tf32_rnd(w);
        Wh[i] = hi;
        Wl[i] = w - hi;
    }
}

// ---------------------------------------------------------------------------
// tf32 3-split GEMM: 128x64 block tile, 256 threads, 2 blocks/SM.
// Raw-residual lo split. Used for scores (transB) and attn@V. Proven R11-R13.
// ---------------------------------------------------------------------------
__global__ __launch_bounds__(256, 2)
void gemm_tf32(const float* __restrict__ A, int lda, long as1, long as2,
               const float* __restrict__ B, int ldb, long bs1, long bs2,
               const float* __restrict__ bias,
               float* __restrict__ C, int ldc, long cs1, long cs2,
               int K, float alpha, int transB)
{
    __shared__ float As[2][128*APITCH];
    __shared__ float Bs[2][BTFL];

    int z = blockIdx.z;
    A += (long)(z >> 2) * as1 + (long)(z & 3) * as2;
    B += (long)(z >> 2) * bs1 + (long)(z & 3) * bs2;
    C += (long)(z >> 2) * cs1 + (long)(z & 3) * cs2;
    int m0 = blockIdx.y * 128, n0 = blockIdx.x * 64;

    int tid = threadIdx.x;
    int warp = tid >> 5, lane = tid & 31;
    int wm = (warp >> 1) * 32, wn = (warp & 1) * 32;
    int r = lane >> 2, q = lane & 3;

    const uint32_t a_smem = (uint32_t)__cvta_generic_to_shared(&As[0][0]);
    const uint32_t b_smem = (uint32_t)__cvta_generic_to_shared(&Bs[0][0]);
    const uint32_t abuf = 128*APITCH*4;
    const uint32_t bbuf = BTFL*4;

    int am0 = tid >> 2, ac = tid & 3;
    int bkr = tid >> 4, bc = tid & 15;
    int bn = tid >> 2, bc4 = tid & 3;

    int KT = K >> 4;

    auto issue = [&](int kt) {
        int k0 = kt << 4, buf = kt & 1;
        CPA16(a_smem + buf*abuf + (uint32_t)(am0*APITCH + ac*4)*4,
              A + (long)(m0 + am0)*lda + k0 + ac*4);
        CPA16(a_smem + buf*abuf + (uint32_t)((am0+64)*APITCH + ac*4)*4,
              A + (long)(m0 + am0 + 64)*lda + k0 + ac*4);
        if (!transB) {
            CPA16(b_smem + buf*bbuf + (uint32_t)(bkr*BPITCH + bc*4)*4,
                  B + (long)(k0 + bkr)*ldb + n0 + bc*4);
        } else {
            CPA16(b_smem + buf*bbuf + (uint32_t)(bn*APITCH + bc4*4)*4,
                  B + (long)(n0 + bn)*ldb + k0 + bc4*4);
        }
        asm volatile("cp.async.commit_group;");
    };

    float acc[2][4][4];
    #pragma unroll
    for (int mt = 0; mt < 2; mt++)
        #pragma unroll
        for (int nt = 0; nt < 4; nt++)
            #pragma unroll
            for (int e = 0; e < 4; e++) acc[mt][nt][e] = 0.f;

    issue(0);
    for (int kt = 0; kt < KT; kt++) {
        if (kt + 1 < KT) {
            issue(kt + 1);
            asm volatile("cp.async.wait_group 1;" ::: "memory");
        } else {
            asm volatile("cp.async.wait_group 0;" ::: "memory");
        }
        __syncthreads();

        const float* Ab = &As[kt & 1][0];
        const float* Bb = &Bs[kt & 1][0];
        #pragma unroll
        for (int p = 0; p < 2; p++) {
            int kb = p*8;
            uint32_t bh[4][2], bl[4][2];
            #pragma unroll
            for (int nt = 0; nt < 4; nt++) {
                int n = wn + nt*8 + r;
                float br0, br1;
                if (!transB) {
                    br0 = Bb[(kb+q  )*BPITCH + n];
                    br1 = Bb[(kb+q+4)*BPITCH + n];
                } else {
                    br0 = Bb[n*APITCH + kb+q  ];
                    br1 = Bb[n*APITCH + kb+q+4];
                }
                float bh0f = tf32_rnd(br0), bh1f = tf32_rnd(br1);
                bh[nt][0] = fu(bh0f);        bh[nt][1] = fu(bh1f);
                bl[nt][0] = fu(br0 - bh0f);  bl[nt][1] = fu(br1 - bh1f);
            }
            #pragma unroll
            for (int mt = 0; mt < 2; mt++) {
                int m = wm + mt*16 + r;
                float ar[4];
                ar[0] = Ab[ m     *APITCH + kb+q  ];
                ar[1] = Ab[(m+8)  *APITCH + kb+q  ];
                ar[2] = Ab[ m     *APITCH + kb+q+4];
                ar[3] = Ab[(m+8)  *APITCH + kb+q+4];
                uint32_t ah[4], al[4];
                #pragma unroll
                for (int e = 0; e < 4; e++) {
                    float hi = tf32_rnd(ar[e]);
                    ah[e] = fu(hi);
                    al[e] = fu(ar[e] - hi);
                }
                #pragma unroll
                for (int nt = 0; nt < 4; nt++) {
                    MMA8(acc[mt][nt], ah, bh[nt]);
                    MMA8(acc[mt][nt], ah, bl[nt]);
                    MMA8(acc[mt][nt], al, bh[nt]);
                }
            }
        }
        __syncthreads();
    }

    #pragma unroll
    for (int mt = 0; mt < 2; mt++)
        #pragma unroll
        for (int nt = 0; nt < 4; nt++) {
            int mrow = m0 + wm + mt*16 + r;
            int ncol = n0 + wn + nt*8 + q*2;
            float b0 = bias ? bias[ncol]   : 0.f;
            float b1 = bias ? bias[ncol+1] : 0.f;
            C[(long)mrow*ldc + ncol  ]     = alpha*acc[mt][nt][0] + b0;
            C[(long)mrow*ldc + ncol+1]     = alpha*acc[mt][nt][1] + b1;
            C[(long)(mrow+8)*ldc + ncol  ] = alpha*acc[mt][nt][2] + b0;
            C[(long)(mrow+8)*ldc + ncol+1] = alpha*acc[mt][nt][3] + b1;
        }
}

// ---------------------------------------------------------------------------
// tf32 3-split GEMM, PRE-SPLIT B variant (normal orientation only). Proven R13.
// ---------------------------------------------------------------------------
__global__ __launch_bounds__(256, 2)
void gemm_tf32_pb(const float* __restrict__ A, int lda,
                  const float* __restrict__ Bh, const float* __restrict__ Bl, int ldb,
                  const float* __restrict__ bias,
                  float* __restrict__ C, int ldc,
                  int K, float alpha)
{
    __shared__ float As [2][128*APITCH];
    __shared__ float Bhs[2][16*BPITCH];
    __shared__ float Bls[2][16*BPITCH];

    int m0 = blockIdx.y * 128, n0 = blockIdx.x * 64;

    int tid = threadIdx.x;
    int warp = tid >> 5, lane = tid & 31;
    int wm = (warp >> 1) * 32, wn = (warp & 1) * 32;
    int r = lane >> 2, q = lane & 3;

    const uint32_t a_smem  = (uint32_t)__cvta_generic_to_shared(&As[0][0]);
    const uint32_t bh_smem = (uint32_t)__cvta_generic_to_shared(&Bhs[0][0]);
    const uint32_t bl_smem = (uint32_t)__cvta_generic_to_shared(&Bls[0][0]);
    const uint32_t abuf = 128*APITCH*4;
    const uint32_t bbuf = 16*BPITCH*4;

    int am0 = tid >> 2, ac = tid & 3;
    int bkr = tid >> 4, bc = tid & 15;

    int KT = K >> 4;

    auto issue = [&](int kt) {
        int k0 = kt << 4, buf = kt & 1;
        CPA16(a_smem + buf*abuf + (uint32_t)(am0*APITCH + ac*4)*4,
              A + (long)(m0 + am0)*lda + k0 + ac*4);
        CPA16(a_smem + buf*abuf + (uint32_t)((am0+64)*APITCH + ac*4)*4,
              A + (long)(m0 + am0 + 64)*lda + k0 + ac*4);
        CPA16(bh_smem + buf*bbuf + (uint32_t)(bkr*BPITCH + bc*4)*4,
              Bh + (long)(k0 + bkr)*ldb + n0 + bc*4);
        CPA16(bl_smem + buf*bbuf + (uint32_t)(bkr*BPITCH + bc*4)*4,
              Bl + (long)(k0 + bkr)*ldb + n0 + bc*4);
        asm volatile("cp.async.commit_group;");
    };

    float acc[2][4][4];
    #pragma unroll
    for (int mt = 0; mt < 2; mt++)
        #pragma unroll
        for (int nt = 0; nt < 4; nt++)
            #pragma unroll
            for (int e = 0; e < 4; e++) acc[mt][nt][e] = 0.f;

    issue(0);
    for (int kt = 0; kt < KT; kt++) {
        if (kt + 1 < KT) {
            issue(kt + 1);
            asm volatile("cp.async.wait_group 1;" ::: "memory");
        } else {
            asm volatile("cp.async.wait_group 0;" ::: "memory");
        }
        __syncthreads();

        const float* Abb = &As [kt & 1][0];
        const float* Bhb = &Bhs[kt & 1][0];
        const float* Blb = &Bls[kt & 1][0];
        #pragma unroll
        for (int p = 0; p < 2; p++) {
            int kb = p*8;
            uint32_t bh[4][2], bl[4][2];
            #pragma unroll
            for (int nt = 0; nt < 4; nt++) {
                int n = wn + nt*8 + r;
                bh[nt][0] = fu(Bhb[(kb+q  )*BPITCH + n]);
                bh[nt][1] = fu(Bhb[(kb+q+4)*BPITCH + n]);
                bl[nt][0] = fu(Blb[(kb+q  )*BPITCH + n]);
                bl[nt][1] = fu(Blb[(kb+q+4)*BPITCH + n]);
            }
            #pragma unroll
            for (int mt = 0; mt < 2; mt++) {
                int m = wm + mt*16 + r;
                float ar[4];
                ar[0] = Abb[ m     *APITCH + kb+q  ];
                ar[1] = Abb[(m+8)  *APITCH + kb+q  ];
                ar[2] = Abb[ m     *APITCH + kb+q+4];
                ar[3] = Abb[(m+8)  *APITCH + kb+q+4];
                uint32_t ah[4], al[4];
                #pragma unroll
                for (int e = 0; e < 4; e++) {
                    float hi = tf32_rnd(ar[e]);
                    ah[e] = fu(hi);
                    al[e] = fu(ar[e] - hi);
                }
                #pragma unroll
                for (int nt = 0; nt < 4; nt++) {
                    MMA8(acc[mt][nt], ah, bh[nt]);
                    MMA8(acc[mt][nt], ah, bl[nt]);
                    MMA8(acc[mt][nt], al, bh[nt]);
                }
            }
        }
        __syncthreads();
    }

    #pragma unroll
    for (int mt = 0; mt < 2; mt++)
        #pragma unroll
        for (int nt = 0; nt < 4; nt++) {
            int mrow = m0 + wm + mt*16 + r;
            int ncol = n0 + wn + nt*8 + q*2;
            float b0 = bias ? bias[ncol]   : 0.f;
            float b1 = bias ? bias[ncol+1] : 0.f;
            C[(long)mrow*ldc + ncol  ]     = alpha*acc[mt][nt][0] + b0;
            C[(long)mrow*ldc + ncol+1]     = alpha*acc[mt][nt][1] + b1;
            C[(long)(mrow+8)*ldc + ncol  ] = alpha*acc[mt][nt][2] + b0;
            C[(long)(mrow+8)*ldc + ncol+1] = alpha*acc[mt][nt][3] + b1;
        }
}

// ---------------------------------------------------------------------------
// Persistent LSTM recurrence — tensor-core matvec, K-SPLIT across 16 warps.
// 128 blocks x 512 threads. Warps 0-7 (group 0) own k[0,256); warps 8-15
// (group 1) own k[256,512). Each group stages its own k-half (own cp.async
// commit group + group-private named barrier), runs its 32-iter mma loop in
// parallel, then partial accumulators combine via a 4KB smem reduction.
// Group 0 does the (unchanged) epilogue. Math identical to R13 up to one
// final fp add per gate.
// ---------------------------------------------------------------------------
__global__ __launch_bounds__(512)
void lstm_persistent(const float* __restrict__ gx)
{
    extern __shared__ float sm[];
    float* Bhs = sm;                    // [16][516] presplit weight hi
    float* Bls = sm + 16*HPAD;          // [16][516] presplit weight lo (raw residual)
    float* hs  = sm + 32*HPAD;          // [64][516] staged h
    float* red = sm + 96*HPAD;          // [8][32][4] group-1 partial accs

    const int tid = threadIdx.x, bid = blockIdx.x;
    const int c0 = bid * 16;
    const int warp = tid >> 5, lane = tid & 31;
    const int kg = warp >> 3;           // k-group: 0 or 1
    const int wl = warp & 7;            // warp id within group
    const int nt = wl & 1;
    const int r = lane >> 2, q = lane & 3;
    const int row0 = (wl >> 1)*16 + r;

    // ---- presplit weight slice into n-major hi/lo (once, all 512 threads) ----
    for (int idx = tid; idx < 16*512; idx += 512) {
        int k = idx >> 4, j = idx & 15;
        float w = g_Whp[(long)k*G4 + c0 + j];
        float hi = tf32_rnd(w);
        Bhs[j*HPAD + k] = hi;
        Bls[j*HPAD + k] = w - hi;
    }

    float c_a = 0.f, c_b = 0.f;
    float* h0 = g_h[0];
    float* h1 = g_h[1];
    const int u = bid*4 + nt*2 + (q >> 1);

    const uint32_t hs_u32 = (uint32_t)__cvta_generic_to_shared(hs);
    __syncthreads();

    const float* arow0 = hs + row0*HPAD;
    const float* arow8 = arow0 + 8*HPAD;
    const float* brh   = Bhs + (nt*8 + r)*HPAD;
    const float* brl   = Bls + (nt*8 + r)*HPAD;

    const int kbase = kg * 256;         // this group's k-offset
    const int tl = tid & 255;           // thread id within group

    for (int t = 0; t < S_LEN; t++) {
        // group 0 prefetches its gx preacts (it owns the epilogue)
        float2 gA = make_float2(0.f, 0.f), gB = make_float2(0.f, 0.f);
        if (kg == 0) {
            const float* gbase = gx + ((long)t*BATCH)*G4 + c0 + nt*8 + 2*q;
            gA = *(const float2*)(gbase + (long)row0*G4);
            gB = *(const float2*)(gbase + (long)(row0+8)*G4);
        }

        // ---- grid barrier: all blocks done with step t-1 ----
        if (t) {
            if (tid == 0) {
                unsigned target = (unsigned)t * NB;
                while (*(volatile unsigned*)&g_cnt < target) { }
                __threadfence();
            }
            __syncthreads();
        }

        // ---- each group stages ITS OWN k-half (4096 float4 / group) ----
        const float* hr = (t & 1) ? h1 : h0;
        #pragma unroll 4
        for (int i = 0; i < 16; i++) {
            int idx = tl + i*256;                // 0..4095
            int rr = idx >> 6, cc = idx & 63;
            CPA16(hs_u32 + (uint32_t)(rr*HPAD + kbase + cc*4)*4,
                  hr + rr*HID + kbase + cc*4);
        }
        asm volatile("cp.async.commit_group;");
        asm volatile("cp.async.wait_group 0;" ::: "memory");
        // group-private barrier: all of this group's copies are visible
        if (kg == 0) asm volatile("bar.sync 1, 256;" ::: "memory");
        else         asm volatile("bar.sync 2, 256;" ::: "memory");

        // ---- mma over this group's k-half ----
        float acc[4] = {0.f, 0.f, 0.f, 0.f};
        #pragma unroll 4
        for (int k0 = kbase; k0 < kbase + 256; k0 += 8) {
            float a0 = arow0[k0+q  ];
            float a1 = arow8[k0+q  ];
            float a2 = arow0[k0+q+4];
            float a3 = arow8[k0+q+4];
            float h0f = tf32_rnd(a0), h1f = tf32_rnd(a1);
            float h2f = tf32_rnd(a2), h3f = tf32_rnd(a3);
            uint32_t ah[4] = { fu(h0f), fu(h1f), fu(h2f), fu(h3f) };
            uint32_t al[4] = { fu(a0 - h0f), fu(a1 - h1f),
                               fu(a2 - h2f), fu(a3 - h3f) };
            uint32_t bh[2] = { fu(brh[k0+q]), fu(brh[k0+q+4]) };
            uint32_t bl[2] = { fu(brl[k0+q]), fu(brl[k0+q+4]) };
            MMA8(acc, ah, bh);
            MMA8(acc, ah, bl);
            MMA8(acc, al, bh);
        }

        // ---- cross-group reduction ----
        if (kg == 1)
            ((float4*)red)[wl*32 + lane] = make_float4(acc[0], acc[1], acc[2], acc[3]);
        __syncthreads();

        if (kg == 0) {
            float4 pa = ((float4*)red)[wl*32 + lane];
            float p0 = acc[0] + pa.x + gA.x;
            float p1 = acc[1] + pa.y + gA.y;
            float p2 = acc[2] + pa.z + gB.x;
            float p3 = acc[3] + pa.w + gB.y;

            float s0, s1, s2, s3;
            if (q & 1) {                // odd lanes: cols are (g, o)
                s0 = tanhf(p0);
                s1 = 1.f / (1.f + expf(-p1));
                s2 = tanhf(p2);
                s3 = 1.f / (1.f + expf(-p3));
            } else {                    // even lanes: cols are (f, i)
                s0 = 1.f / (1.f + expf(-p0));
                s1 = 1.f / (1.f + expf(-p1));
                s2 = 1.f / (1.f + expf(-p2));
                s3 = 1.f / (1.f + expf(-p3));
            }
            float x0 = __shfl_xor_sync(0xFFFFFFFFu, s0, 1);
            float x1 = __shfl_xor_sync(0xFFFFFFFFu, s1, 1);
            float x2 = __shfl_xor_sync(0xFFFFFFFFu, s2, 1);
            float x3 = __shfl_xor_sync(0xFFFFFFFFu, s3, 1);

            if (!(q & 1)) {
                c_a = s0 * c_a + s1 * x0;
                float hA = x1 * tanhf(c_a);
                c_b = s2 * c_b + s3 * x2;
                float hB = x3 * tanhf(c_b);

                float* hw = (t & 1) ? h0 : h1;
                hw[row0*HID + u] = hA;
                hw[(row0+8)*HID + u] = hB;
                g_lstm[((long)t*BATCH + row0)*HID + u] = hA;
                g_lstm[((long)t*BATCH + row0+8)*HID + u] = hB;
                if (t == S_LEN-1) {
                    g_c[row0*HID + u] = c_a;
                    g_c[(row0+8)*HID + u] = c_b;
                }
            }
        }

        // ---- arrive: cta barrier, then tid0-only fence + atomic ----
        __syncthreads();
        if (tid == 0) {
            __threadfence();
            atomicAdd(&g_cnt, 1u);
        }
    }
}

// ---------------------------------------------------------------------------
// Row softmax over 512-wide rows. One block (128 threads) per row.
// ---------------------------------------------------------------------------
__global__ __launch_bounds__(128)
void softmax512(float* __restrict__ s)
{
    float* row = s + (size_t)blockIdx.x * 512;
    int tid = threadIdx.x;
    float v0 = row[tid], v1 = row[tid+128], v2 = row[tid+256], v3 = row[tid+384];
    float mx = fmaxf(fmaxf(v0, v1), fmaxf(v2, v3));
    __shared__ float sm[4];
    __shared__ float ss[4];
    #pragma unroll
    for (int off = 16; off > 0; off >>= 1)
        mx = fmaxf(mx, __shfl_xor_sync(0xFFFFFFFFu, mx, off));
    if ((tid & 31) == 0) sm[tid >> 5] = mx;
    __syncthreads();
    mx = fmaxf(fmaxf(sm[0], sm[1]), fmaxf(sm[2], sm[3]));
    v0 = expf(v0 - mx); v1 = expf(v1 - mx); v2 = expf(v2 - mx); v3 = expf(v3 - mx);
    float sum = v0 + v1 + v2 + v3;
    #pragma unroll
    for (int off = 16; off > 0; off >>= 1)
        sum += __shfl_xor_sync(0xFFFFFFFFu, sum, off);
    if ((tid & 31) == 0) ss[tid >> 5] = sum;
    __syncthreads();
    sum = ss[0] + ss[1] + ss[2] + ss[3];
    float inv = 1.f / sum;
    row[tid] = v0*inv; row[tid+128] = v1*inv; row[tid+256] = v2*inv; row[tid+384] = v3*inv;
}

__global__ void copy_hc(const float* __restrict__ h, const float* __restrict__ c,
                        float* __restrict__ out)
{
    int i = blockIdx.x * blockDim.x + threadIdx.x;
    if (i < BATCH*HID) {
        out[DEC_ELEMS + i] = h[i];
        out[DEC_ELEMS + BATCH*HID + i] = c[i];
    }
}

// ---------------------------------------------------------------------------
// Host orchestration (graph-capturable: launches only)
// ---------------------------------------------------------------------------
extern "C" void kernel_launch(void* const* d_in, const int* in_sizes, int n_in,
                              void* d_out, int out_size)
{
    const float* x  = (const float*)d_in[0];
    const float* Wf = (const float*)d_in[1];
    const float* bf = (const float*)d_in[2];
    const float* Wi = (const float*)d_in[3];
    const float* bi = (const float*)d_in[4];
    const float* Wg = (const float*)d_in[5];
    const float* bg = (const float*)d_in[6];
    const float* Wo = (const float*)d_in[7];
    const float* bo = (const float*)d_in[8];
    const float* Wq = (const float*)d_in[9];
    const float* bq = (const float*)d_in[10];
    const float* Wk = (const float*)d_in[11];
    const float* bk = (const float*)d_in[12];
    const float* Wv = (const float*)d_in[13];
    const float* bv = (const float*)d_in[14];
    float* out = (float*)d_out;

    float *biasp, *gx, *lstm, *hbase, *c, *PQ, *PK, *PV;
    float *Wxph, *Wxpl, *Wqh, *Wql, *Wkh, *Wkl, *Wvh, *Wvl;
    cudaGetSymbolAddress((void**)&biasp, g_biasp);
    cudaGetSymbolAddress((void**)&gx,    g_gx);
    cudaGetSymbolAddress((void**)&lstm,  g_lstm);
    cudaGetSymbolAddress((void**)&hbase, g_h);
    cudaGetSymbolAddress((void**)&c,     g_c);
    cudaGetSymbolAddress((void**)&PQ,    g_PQ);
    cudaGetSymbolAddress((void**)&PK,    g_PK);
    cudaGetSymbolAddress((void**)&PV,    g_PV);
    cudaGetSymbolAddress((void**)&Wxph,  g_Wxph);
    cudaGetSymbolAddress((void**)&Wxpl,  g_Wxpl);
    cudaGetSymbolAddress((void**)&Wqh,   g_Wqh);
    cudaGetSymbolAddress((void**)&Wql,   g_Wql);
    cudaGetSymbolAddress((void**)&Wkh,   g_Wkh);
    cudaGetSymbolAddress((void**)&Wkl,   g_Wkl);
    cudaGetSymbolAddress((void**)&Wvh,   g_Wvh);
    cudaGetSymbolAddress((void**)&Wvl,   g_Wvl);
    float* h0 = hbase;

    // smem: 96*HPAD floats (weights + h) + 1024 floats reduction = 202,240 B
    const int SMEM_LSTM = (96*HPAD + 8*32*4) * (int)sizeof(float);
    cudaFuncSetAttribute(lstm_persistent,
                         cudaFuncAttributeMaxDynamicSharedMemorySize, SMEM_LSTM);

    // 1. repack + zero + pre-split weights
    pack_weights<<<(768*HID + 255)/256, 256>>>(Wf, Wi, Wg, Wo, bf, bi, bg, bo);
    zero_state<<<(BATCH*HID + 255)/256, 256>>>();
    split_wxp<<<(D_IN*G4 + 255)/256, 256>>>();
    split_w<<<(HID*HID + 255)/256, 256>>>(Wq, Wqh, Wql, HID*HID);
    split_w<<<(HID*HID + 255)/256, 256>>>(Wk, Wkh, Wkl, HID*HID);
    split_w<<<(HID*HID + 255)/256, 256>>>(Wv, Wvh, Wvl, HID*HID);

    // 2. x-side gate preacts: gx = x @ Wxp + biasp   [32768,256]@[256,2048]
    gemm_tf32_pb<<<dim3(G4/64, ROWS/128), 256>>>(
        x, D_IN, Wxph, Wxpl, G4, biasp, gx, G4, D_IN, 1.0f);

    // 3. recurrence: persistent tensor-core kernel, k-split, grid barrier/step
    lstm_persistent<<<NB, 512, SMEM_LSTM>>>(gx);

    // 4. Q/K/V projections: [32768,512]@[512,512]+b
    gemm_tf32_pb<<<dim3(HID/64, ROWS/128), 256>>>(
        lstm, HID, Wqh, Wql, HID, bq, PQ, HID, HID, 1.0f);
    gemm_tf32_pb<<<dim3(HID/64, ROWS/128), 256>>>(
        lstm, HID, Wkh, Wkl, HID, bk, PK, HID, HID, 1.0f);
    gemm_tf32_pb<<<dim3(HID/64, ROWS/128), 256>>>(
        lstm, HID, Wvh, Wvl, HID, bv, PV, HID, HID, 1.0f);

    // 5. scores = (Q @ K^T)/sqrt(dk), z = b'*4 + h
    const long pbS = (long)S_LEN * HID;
    const long phS = DK;
    const long scB = 4L * S_LEN * S_LEN;
    const long scH = (long)S_LEN * S_LEN;
    float scale = 1.0f / sqrtf((float)DK);
    gemm_tf32<<<dim3(S_LEN/64, S_LEN/128, BATCH*NH), 256>>>(
        PQ, HID, pbS, phS,
        PK, HID, pbS, phS,
        (const float*)0,
        gx /* reused as scores */, S_LEN, scB, scH, DK, scale, 1);

    // 6. softmax over last axis
    softmax512<<<BATCH*NH*S_LEN, 128>>>(gx);

    // 7. out = attn @ V, decoded layout d_out[(s*64 + b')*512 + h*128 + d]
    gemm_tf32<<<dim3(DK/64, S_LEN/128, BATCH*NH), 256>>>(
        gx, S_LEN, scB, scH,
        PV, HID, pbS, phS,
        (const float*)0,
        out, BATCH*HID, (long)HID, (long)DK, S_LEN, 1.0f, 0);

    // 8. final hidden/cell state (after step 511 the live h buffer is h0)
    copy_hc<<<(BATCH*HID + 255)/256, 256>>>(h0, c, out);
}

// round 15
// speedup vs baseline: 1.3437x; 1.0765x over previous
#include <cuda_runtime.h>
#include <math.h>
#include <stdint.h>

// ---------------------------------------------------------------------------
// Problem constants
// ---------------------------------------------------------------------------
#define S_LEN   512
#define BATCH   64
#define D_IN    256
#define HID     512
#define G4      2048        // 4 gates * HID, packed unit-major: col = u*4 + gate
#define NH      4
#define DK      128
#define ROWS    (S_LEN*BATCH)        // 32768
#define DEC_ELEMS (S_LEN*BATCH*HID)  // 16777216
#define NB      128                  // persistent LSTM blocks (1/SM -> full chip)
#define HPAD    516                  // padded pitch (floats)
#define APITCH  20                   // gemm A-smem pitch (floats)
#define BPITCH  72                   // gemm B-smem pitch, normal path
#define BTFL    1280                 // gemm B buffer floats (max of 16*72, 64*20)

// ---------------------------------------------------------------------------
// Device scratch (static allocations only — no cudaMalloc allowed)
// ---------------------------------------------------------------------------
__device__ float g_Wxp[D_IN*G4];          //   2 MB  packed input-gate weights
__device__ float g_Whp[HID*G4];           //   4 MB  packed recurrent-gate weights
__device__ float g_biasp[G4];
__device__ float g_gx[ROWS*G4];           // 256 MB  x-side gate preacts; reused as attn scores
__device__ float g_lstm[ROWS*HID];        //  64 MB  lstm_out [S,B,HID]
__device__ float g_h[2][BATCH*HID];       //  h double buffer
__device__ float g_c[BATCH*HID];
__device__ float g_PQ[ROWS*HID];          //  64 MB
__device__ float g_PK[ROWS*HID];
__device__ float g_PV[ROWS*HID];
__device__ unsigned g_cnt;                //  grid barrier counter
// pre-split copies: Wxp as fp32 hi/lo (tf32 path); Wq/k/v as packed bf16x2 hi/lo
__device__ float g_Wxph[D_IN*G4], g_Wxpl[D_IN*G4];
__device__ uint32_t g_Wqh[(HID/2)*HID], g_Wql[(HID/2)*HID];
__device__ uint32_t g_Wkh[(HID/2)*HID], g_Wkl[(HID/2)*HID];
__device__ uint32_t g_Wvh[(HID/2)*HID], g_Wvl[(HID/2)*HID];

// ---------------------------------------------------------------------------
// Helpers
// ---------------------------------------------------------------------------
__device__ __forceinline__ float tf32_rnd(float x) {
    uint32_t u; asm("cvt.rna.tf32.f32 %0, %1;" : "=r"(u) : "f"(x));
    return __uint_as_float(u);
}
__device__ __forceinline__ uint32_t fu(float x) { return __float_as_uint(x); }

// bf16 pair split: h = {trunc16(f0) lo, trunc16(f1) hi} (exact bf16 values),
// l = rn-bf16x2 of the exact fp32 residuals. low half = even-k element.
__device__ __forceinline__ void bsplit2(float f0, float f1, uint32_t& h, uint32_t& l)
{
    uint32_t u0 = __float_as_uint(f0), u1 = __float_as_uint(f1);
    asm("prmt.b32 %0, %1, %2, 0x7632;" : "=r"(h) : "r"(u0), "r"(u1));
    float h0 = __uint_as_float(u0 & 0xFFFF0000u);
    float h1 = __uint_as_float(u1 & 0xFFFF0000u);
    asm("cvt.rn.bf16x2.f32 %0, %1, %2;" : "=r"(l) : "f"(f1 - h1), "f"(f0 - h0));
}

#define MMA8(cc, a, bb) \
    asm volatile("mma.sync.aligned.m16n8k8.row.col.f32.tf32.tf32.f32 " \
        "{%0,%1,%2,%3},{%4,%5,%6,%7},{%8,%9},{%0,%1,%2,%3};" \
        : "+f"(cc[0]), "+f"(cc[1]), "+f"(cc[2]), "+f"(cc[3]) \
        : "r"(a[0]), "r"(a[1]), "r"(a[2]), "r"(a[3]), "r"(bb[0]), "r"(bb[1]))

#define MMA16(cc, a, bb) \
    asm volatile("mma.sync.aligned.m16n8k16.row.col.f32.bf16.bf16.f32 " \
        "{%0,%1,%2,%3},{%4,%5,%6,%7},{%8,%9},{%0,%1,%2,%3};" \
        : "+f"(cc[0]), "+f"(cc[1]), "+f"(cc[2]), "+f"(cc[3]) \
        : "r"(a[0]), "r"(a[1]), "r"(a[2]), "r"(a[3]), "r"(bb[0]), "r"(bb[1]))

#define CPA16(dst, src) \
    asm volatile("cp.async.cg.shared.global [%0], [%1], 16;" :: "r"(dst), "l"(src))

// ---------------------------------------------------------------------------
// Weight repack + splits
// ---------------------------------------------------------------------------
__global__ void pack_weights(const float* __restrict__ Wf, const float* __restrict__ Wi,
                             const float* __restrict__ Wg, const float* __restrict__ Wo,
                             const float* __restrict__ bf, const float* __restrict__ bi,
                             const float* __restrict__ bg, const float* __restrict__ bo)
{
    int idx = blockIdx.x * blockDim.x + threadIdx.x;   // over 768*512
    if (idx < 768*HID) {
        int k = idx / HID, u = idx % HID;
        float vf = Wf[idx], vi = Wi[idx], vg = Wg[idx], vo = Wo[idx];
        float* dst = (k < D_IN) ? (g_Wxp + (long)k*G4) : (g_Whp + (long)(k - D_IN)*G4);
        dst[u*4+0] = vf; dst[u*4+1] = vi; dst[u*4+2] = vg; dst[u*4+3] = vo;
    }
    if (idx < HID) {
        g_biasp[idx*4+0] = bf[idx];
        g_biasp[idx*4+1] = bi[idx];
        g_biasp[idx*4+2] = bg[idx];
        g_biasp[idx*4+3] = bo[idx];
    }
}

__global__ void zero_state()
{
    int i = blockIdx.x * blockDim.x + threadIdx.x;
    if (i < BATCH*HID) { g_h[0][i] = 0.f; g_c[i] = 0.f; }
    if (i == 0) g_cnt = 0u;
}

__global__ void split_wxp()
{
    int i = blockIdx.x * blockDim.x + threadIdx.x;
    if (i < D_IN*G4) {
        float w = g_Wxp[i];
        float hi = tf32_rnd(w);
        g_Wxph[i] = hi;
        g_Wxpl[i] = w - hi;
    }
}

// pack W[K][N] fp32 into bf16x2 hi/lo arrays [K/2][N] (k-pairs per entry)
__global__ void split_w_bfp(const float* __restrict__ W, uint32_t* __restrict__ Wh,
                            uint32_t* __restrict__ Wl, int N, int total)
{
    int idx = blockIdx.x * blockDim.x + threadIdx.x;
    if (idx < total) {
        int kp = idx / N, n = idx - kp*N;
        float f0 = W[(long)(2*kp)*N + n];
        float f1 = W[(long)(2*kp+1)*N + n];
        uint32_t h, l;
        bsplit2(f0, f1, h, l);
        Wh[idx] = h;
        Wl[idx] = l;
    }
}

// ---------------------------------------------------------------------------
// tf32 3-split GEMM, PRE-SPLIT B (fp32 hi/lo). Used ONLY for gx (feeds the
// recurrence; keep highest precision). Proven R13/R14.
// ---------------------------------------------------------------------------
__global__ __launch_bounds__(256, 2)
void gemm_tf32_pb(const float* __restrict__ A, int lda,
                  const float* __restrict__ Bh, const float* __restrict__ Bl, int ldb,
                  const float* __restrict__ bias,
                  float* __restrict__ C, int ldc,
                  int K, float alpha)
{
    __shared__ float As [2][128*APITCH];
    __shared__ float Bhs[2][16*BPITCH];
    __shared__ float Bls[2][16*BPITCH];

    int m0 = blockIdx.y * 128, n0 = blockIdx.x * 64;

    int tid = threadIdx.x;
    int warp = tid >> 5, lane = tid & 31;
    int wm = (warp >> 1) * 32, wn = (warp & 1) * 32;
    int r = lane >> 2, q = lane & 3;

    const uint32_t a_smem  = (uint32_t)__cvta_generic_to_shared(&As[0][0]);
    const uint32_t bh_smem = (uint32_t)__cvta_generic_to_shared(&Bhs[0][0]);
    const uint32_t bl_smem = (uint32_t)__cvta_generic_to_shared(&Bls[0][0]);
    const uint32_t abuf = 128*APITCH*4;
    const uint32_t bbuf = 16*BPITCH*4;

    int am0 = tid >> 2, ac = tid & 3;
    int bkr = tid >> 4, bc = tid & 15;

    int KT = K >> 4;

    auto issue = [&](int kt) {
        int k0 = kt << 4, buf = kt & 1;
        CPA16(a_smem + buf*abuf + (uint32_t)(am0*APITCH + ac*4)*4,
              A + (long)(m0 + am0)*lda + k0 + ac*4);
        CPA16(a_smem + buf*abuf + (uint32_t)((am0+64)*APITCH + ac*4)*4,
              A + (long)(m0 + am0 + 64)*lda + k0 + ac*4);
        CPA16(bh_smem + buf*bbuf + (uint32_t)(bkr*BPITCH + bc*4)*4,
              Bh + (long)(k0 + bkr)*ldb + n0 + bc*4);
        CPA16(bl_smem + buf*bbuf + (uint32_t)(bkr*BPITCH + bc*4)*4,
              Bl + (long)(k0 + bkr)*ldb + n0 + bc*4);
        asm volatile("cp.async.commit_group;");
    };

    float acc[2][4][4];
    #pragma unroll
    for (int mt = 0; mt < 2; mt++)
        #pragma unroll
        for (int nt = 0; nt < 4; nt++)
            #pragma unroll
            for (int e = 0; e < 4; e++) acc[mt][nt][e] = 0.f;

    issue(0);
    for (int kt = 0; kt < KT; kt++) {
        if (kt + 1 < KT) {
            issue(kt + 1);
            asm volatile("cp.async.wait_group 1;" ::: "memory");
        } else {
            asm volatile("cp.async.wait_group 0;" ::: "memory");
        }
        __syncthreads();

        const float* Abb = &As [kt & 1][0];
        const float* Bhb = &Bhs[kt & 1][0];
        const float* Blb = &Bls[kt & 1][0];
        #pragma unroll
        for (int p = 0; p < 2; p++) {
            int kb = p*8;
            uint32_t bh[4][2], bl[4][2];
            #pragma unroll
            for (int nt = 0; nt < 4; nt++) {
                int n = wn + nt*8 + r;
                bh[nt][0] = fu(Bhb[(kb+q  )*BPITCH + n]);
                bh[nt][1] = fu(Bhb[(kb+q+4)*BPITCH + n]);
                bl[nt][0] = fu(Blb[(kb+q  )*BPITCH + n]);
                bl[nt][1] = fu(Blb[(kb+q+4)*BPITCH + n]);
            }
            #pragma unroll
            for (int mt = 0; mt < 2; mt++) {
                int m = wm + mt*16 + r;
                float ar[4];
                ar[0] = Abb[ m     *APITCH + kb+q  ];
                ar[1] = Abb[(m+8)  *APITCH + kb+q  ];
                ar[2] = Abb[ m     *APITCH + kb+q+4];
                ar[3] = Abb[(m+8)  *APITCH + kb+q+4];
                uint32_t ah[4], al[4];
                #pragma unroll
                for (int e = 0; e < 4; e++) {
                    float hi = tf32_rnd(ar[e]);
                    ah[e] = fu(hi);
                    al[e] = fu(ar[e] - hi);
                }
                #pragma unroll
                for (int nt = 0; nt < 4; nt++) {
                    MMA8(acc[mt][nt], ah, bh[nt]);
                    MMA8(acc[mt][nt], ah, bl[nt]);
                    MMA8(acc[mt][nt], al, bh[nt]);
                }
            }
        }
        __syncthreads();
    }

    #pragma unroll
    for (int mt = 0; mt < 2; mt++)
        #pragma unroll
        for (int nt = 0; nt < 4; nt++) {
            int mrow = m0 + wm + mt*16 + r;
            int ncol = n0 + wn + nt*8 + q*2;
            float b0 = bias ? bias[ncol]   : 0.f;
            float b1 = bias ? bias[ncol+1] : 0.f;
            C[(long)mrow*ldc + ncol  ]     = alpha*acc[mt][nt][0] + b0;
            C[(long)mrow*ldc + ncol+1]     = alpha*acc[mt][nt][1] + b1;
            C[(long)(mrow+8)*ldc + ncol  ] = alpha*acc[mt][nt][2] + b0;
            C[(long)(mrow+8)*ldc + ncol+1] = alpha*acc[mt][nt][3] + b1;
        }
}

// ---------------------------------------------------------------------------
// bf16 3-split GEMM (m16n8k16): 128x64 tile, 256 threads, 2 blocks/SM.
// Runtime-split both operands. Used for scores (transB=1) and attn@V.
// Fragment map: a0=(r,2q:2q+1) a1=(r+8,·) a2=(r,2q+8:2q+9) a3=(r+8,·);
// b0=(2q:2q+1,n) b1=(2q+8:2q+9,n); low half = even k. C as m16n8k8.
// ---------------------------------------------------------------------------
__global__ __launch_bounds__(256, 2)
void gemm_bf16(const float* __restrict__ A, int lda, long as1, long as2,
               const float* __restrict__ B, int ldb, long bs1, long bs2,
               const float* __restrict__ bias,
               float* __restrict__ C, int ldc, long cs1, long cs2,
               int K, float alpha, int transB)
{
    __shared__ float As[2][128*APITCH];
    __shared__ float Bs[2][BTFL];

    int z = blockIdx.z;
    A += (long)(z >> 2) * as1 + (long)(z & 3) * as2;
    B += (long)(z >> 2) * bs1 + (long)(z & 3) * bs2;
    C += (long)(z >> 2) * cs1 + (long)(z & 3) * cs2;
    int m0 = blockIdx.y * 128, n0 = blockIdx.x * 64;

    int tid = threadIdx.x;
    int warp = tid >> 5, lane = tid & 31;
    int wm = (warp >> 1) * 32, wn = (warp & 1) * 32;
    int r = lane >> 2, q = lane & 3;

    const uint32_t a_smem = (uint32_t)__cvta_generic_to_shared(&As[0][0]);
    const uint32_t b_smem = (uint32_t)__cvta_generic_to_shared(&Bs[0][0]);
    const uint32_t abuf = 128*APITCH*4;
    const uint32_t bbuf = BTFL*4;

    int am0 = tid >> 2, ac = tid & 3;
    int bkr = tid >> 4, bc = tid & 15;
    int bn = tid >> 2, bc4 = tid & 3;

    int KT = K >> 4;

    auto issue = [&](int kt) {
        int k0 = kt << 4, buf = kt & 1;
        CPA16(a_smem + buf*abuf + (uint32_t)(am0*APITCH + ac*4)*4,
              A + (long)(m0 + am0)*lda + k0 + ac*4);
        CPA16(a_smem + buf*abuf + (uint32_t)((am0+64)*APITCH + ac*4)*4,
              A + (long)(m0 + am0 + 64)*lda + k0 + ac*4);
        if (!transB) {
            CPA16(b_smem + buf*bbuf + (uint32_t)(bkr*BPITCH + bc*4)*4,
                  B + (long)(k0 + bkr)*ldb + n0 + bc*4);
        } else {
            CPA16(b_smem + buf*bbuf + (uint32_t)(bn*APITCH + bc4*4)*4,
                  B + (long)(n0 + bn)*ldb + k0 + bc4*4);
        }
        asm volatile("cp.async.commit_group;");
    };

    float acc[2][4][4];
    #pragma unroll
    for (int mt = 0; mt < 2; mt++)
        #pragma unroll
        for (int nt = 0; nt < 4; nt++)
            #pragma unroll
            for (int e = 0; e < 4; e++) acc[mt][nt][e] = 0.f;

    issue(0);
    for (int kt = 0; kt < KT; kt++) {
        if (kt + 1 < KT) {
            issue(kt + 1);
            asm volatile("cp.async.wait_group 1;" ::: "memory");
        } else {
            asm volatile("cp.async.wait_group 0;" ::: "memory");
        }
        __syncthreads();

        const float* Ab = &As[kt & 1][0];
        const float* Bb = &Bs[kt & 1][0];

        // ---- B frags (one k16 set) ----
        uint32_t bh[4][2], bl[4][2];
        #pragma unroll
        for (int nt = 0; nt < 4; nt++) {
            int n = wn + nt*8 + r;
            if (!transB) {
                bsplit2(Bb[(2*q  )*BPITCH + n], Bb[(2*q+1)*BPITCH + n],
                        bh[nt][0], bl[nt][0]);
                bsplit2(Bb[(2*q+8)*BPITCH + n], Bb[(2*q+9)*BPITCH + n],
                        bh[nt][1], bl[nt][1]);
            } else {
                float2 p0 = *(const float2*)(Bb + n*APITCH + 2*q);
                float2 p1 = *(const float2*)(Bb + n*APITCH + 2*q + 8);
                bsplit2(p0.x, p0.y, bh[nt][0], bl[nt][0]);
                bsplit2(p1.x, p1.y, bh[nt][1], bl[nt][1]);
            }
        }

        // ---- A frags + MMAs ----
        #pragma unroll
        for (int mt = 0; mt < 2; mt++) {
            int m = wm + mt*16 + r;
            float2 q0 = *(const float2*)(Ab +  m    *APITCH + 2*q);
            float2 q1 = *(const float2*)(Ab + (m+8) *APITCH + 2*q);
            float2 q2 = *(const float2*)(Ab +  m    *APITCH + 2*q + 8);
            float2 q3 = *(const float2*)(Ab + (m+8) *APITCH + 2*q + 8);
            uint32_t ah[4], al[4];
            bsplit2(q0.x, q0.y, ah[0], al[0]);
            bsplit2(q1.x, q1.y, ah[1], al[1]);
            bsplit2(q2.x, q2.y, ah[2], al[2]);
            bsplit2(q3.x, q3.y, ah[3], al[3]);
            #pragma unroll
            for (int nt = 0; nt < 4; nt++) {
                MMA16(acc[mt][nt], ah, bh[nt]);
                MMA16(acc[mt][nt], ah, bl[nt]);
                MMA16(acc[mt][nt], al, bh[nt]);
            }
        }
        __syncthreads();
    }

    #pragma unroll
    for (int mt = 0; mt < 2; mt++)
        #pragma unroll
        for (int nt = 0; nt < 4; nt++) {
            int mrow = m0 + wm + mt*16 + r;
            int ncol = n0 + wn + nt*8 + q*2;
            float b0 = bias ? bias[ncol]   : 0.f;
            float b1 = bias ? bias[ncol+1] : 0.f;
            C[(long)mrow*ldc + ncol  ]     = alpha*acc[mt][nt][0] + b0;
            C[(long)mrow*ldc + ncol+1]     = alpha*acc[mt][nt][1] + b1;
            C[(long)(mrow+8)*ldc + ncol  ] = alpha*acc[mt][nt][2] + b0;
            C[(long)(mrow+8)*ldc + ncol+1] = alpha*acc[mt][nt][3] + b1;
        }
}

// ---------------------------------------------------------------------------
// bf16 3-split GEMM, PRE-PACKED B: B supplied as bf16x2 hi/lo [K/2][N] uint32.
// No B-side conversions in the k-loop; B staging bytes halved.
// Used for Q/K/V projections.
// ---------------------------------------------------------------------------
__global__ __launch_bounds__(256, 2)
void gemm_bf16_pb(const float* __restrict__ A, int lda,
                  const uint32_t* __restrict__ Bhp, const uint32_t* __restrict__ Blp,
                  int ldbp,
                  const float* __restrict__ bias,
                  float* __restrict__ C, int ldc,
                  int K, float alpha)
{
    __shared__ float    As [2][128*APITCH];
    __shared__ uint32_t Bhs[2][8*BPITCH];
    __shared__ uint32_t Bls[2][8*BPITCH];

    int m0 = blockIdx.y * 128, n0 = blockIdx.x * 64;

    int tid = threadIdx.x;
    int warp = tid >> 5, lane = tid & 31;
    int wm = (warp >> 1) * 32, wn = (warp & 1) * 32;
    int r = lane >> 2, q = lane & 3;

    const uint32_t a_smem  = (uint32_t)__cvta_generic_to_shared(&As[0][0]);
    const uint32_t bh_smem = (uint32_t)__cvta_generic_to_shared(&Bhs[0][0]);
    const uint32_t bl_smem = (uint32_t)__cvta_generic_to_shared(&Bls[0][0]);
    const uint32_t abuf = 128*APITCH*4;
    const uint32_t bbuf = 8*BPITCH*4;

    int am0 = tid >> 2, ac = tid & 3;
    int tl  = tid & 127;
    int brow = tl >> 4, bch = tl & 15;   // kp-row 0..7, n-chunk 0..15

    int KT = K >> 4;

    auto issue = [&](int kt) {
        int k0 = kt << 4, kp0 = kt << 3, buf = kt & 1;
        CPA16(a_smem + buf*abuf + (uint32_t)(am0*APITCH + ac*4)*4,
              A + (long)(m0 + am0)*lda + k0 + ac*4);
        CPA16(a_smem + buf*abuf + (uint32_t)((am0+64)*APITCH + ac*4)*4,
              A + (long)(m0 + am0 + 64)*lda + k0 + ac*4);
        if (tid < 128) {
            CPA16(bh_smem + buf*bbuf + (uint32_t)(brow*BPITCH + bch*4)*4,
                  Bhp + (long)(kp0 + brow)*ldbp + n0 + bch*4);
        } else {
            CPA16(bl_smem + buf*bbuf + (uint32_t)(brow*BPITCH + bch*4)*4,
                  Blp + (long)(kp0 + brow)*ldbp + n0 + bch*4);
        }
        asm volatile("cp.async.commit_group;");
    };

    float acc[2][4][4];
    #pragma unroll
    for (int mt = 0; mt < 2; mt++)
        #pragma unroll
        for (int nt = 0; nt < 4; nt++)
            #pragma unroll
            for (int e = 0; e < 4; e++) acc[mt][nt][e] = 0.f;

    issue(0);
    for (int kt = 0; kt < KT; kt++) {
        if (kt + 1 < KT) {
            issue(kt + 1);
            asm volatile("cp.async.wait_group 1;" ::: "memory");
        } else {
            asm volatile("cp.async.wait_group 0;" ::: "memory");
        }
        __syncthreads();

        const float*    Ab  = &As [kt & 1][0];
        const uint32_t* Bhb = &Bhs[kt & 1][0];
        const uint32_t* Blb = &Bls[kt & 1][0];

        uint32_t bh[4][2], bl[4][2];
        #pragma unroll
        for (int nt = 0; nt < 4; nt++) {
            int n = wn + nt*8 + r;
            bh[nt][0] = Bhb[ q     *BPITCH + n];
            bh[nt][1] = Bhb[(q+4)  *BPITCH + n];
            bl[nt][0] = Blb[ q     *BPITCH + n];
            bl[nt][1] = Blb[(q+4)  *BPITCH + n];
        }

        #pragma unroll
        for (int mt = 0; mt < 2; mt++) {
            int m = wm + mt*16 + r;
            float2 q0 = *(const float2*)(Ab +  m    *APITCH + 2*q);
            float2 q1 = *(const float2*)(Ab + (m+8) *APITCH + 2*q);
            float2 q2 = *(const float2*)(Ab +  m    *APITCH + 2*q + 8);
            float2 q3 = *(const float2*)(Ab + (m+8) *APITCH + 2*q + 8);
            uint32_t ah[4], al[4];
            bsplit2(q0.x, q0.y, ah[0], al[0]);
            bsplit2(q1.x, q1.y, ah[1], al[1]);
            bsplit2(q2.x, q2.y, ah[2], al[2]);
            bsplit2(q3.x, q3.y, ah[3], al[3]);
            #pragma unroll
            for (int nt = 0; nt < 4; nt++) {
                MMA16(acc[mt][nt], ah, bh[nt]);
                MMA16(acc[mt][nt], ah, bl[nt]);
                MMA16(acc[mt][nt], al, bh[nt]);
            }
        }
        __syncthreads();
    }

    #pragma unroll
    for (int mt = 0; mt < 2; mt++)
        #pragma unroll
        for (int nt = 0; nt < 4; nt++) {
            int mrow = m0 + wm + mt*16 + r;
            int ncol = n0 + wn + nt*8 + q*2;
            float b0 = bias ? bias[ncol]   : 0.f;
            float b1 = bias ? bias[ncol+1] : 0.f;
            C[(long)mrow*ldc + ncol  ]     = alpha*acc[mt][nt][0] + b0;
            C[(long)mrow*ldc + ncol+1]     = alpha*acc[mt][nt][1] + b1;
            C[(long)(mrow+8)*ldc + ncol  ] = alpha*acc[mt][nt][2] + b0;
            C[(long)(mrow+8)*ldc + ncol+1] = alpha*acc[mt][nt][3] + b1;
        }
}

// ---------------------------------------------------------------------------
// Persistent LSTM recurrence — tensor-core matvec, K-SPLIT across 16 warps
// (unchanged from R14).
// ---------------------------------------------------------------------------
__global__ __launch_bounds__(512)
void lstm_persistent(const float* __restrict__ gx)
{
    extern __shared__ float sm[];
    float* Bhs = sm;                    // [16][516] presplit weight hi
    float* Bls = sm + 16*HPAD;          // [16][516] presplit weight lo (raw residual)
    float* hs  = sm + 32*HPAD;          // [64][516] staged h
    float* red = sm + 96*HPAD;          // [8][32][4] group-1 partial accs

    const int tid = threadIdx.x, bid = blockIdx.x;
    const int c0 = bid * 16;
    const int warp = tid >> 5, lane = tid & 31;
    const int kg = warp >> 3;           // k-group: 0 or 1
    const int wl = warp & 7;            // warp id within group
    const int nt = wl & 1;
    const int r = lane >> 2, q = lane & 3;
    const int row0 = (wl >> 1)*16 + r;

    for (int idx = tid; idx < 16*512; idx += 512) {
        int k = idx >> 4, j = idx & 15;
        float w = g_Whp[(long)k*G4 + c0 + j];
        float hi = tf32_rnd(w);
        Bhs[j*HPAD + k] = hi;
        Bls[j*HPAD + k] = w - hi;
    }

    float c_a = 0.f, c_b = 0.f;
    float* h0 = g_h[0];
    float* h1 = g_h[1];
    const int u = bid*4 + nt*2 + (q >> 1);

    const uint32_t hs_u32 = (uint32_t)__cvta_generic_to_shared(hs);
    __syncthreads();

    const float* arow0 = hs + row0*HPAD;
    const float* arow8 = arow0 + 8*HPAD;
    const float* brh   = Bhs + (nt*8 + r)*HPAD;
    const float* brl   = Bls + (nt*8 + r)*HPAD;

    const int kbase = kg * 256;
    const int tl = tid & 255;

    for (int t = 0; t < S_LEN; t++) {
        float2 gA = make_float2(0.f, 0.f), gB = make_float2(0.f, 0.f);
        if (kg == 0) {
            const float* gbase = gx + ((long)t*BATCH)*G4 + c0 + nt*8 + 2*q;
            gA = *(const float2*)(gbase + (long)row0*G4);
            gB = *(const float2*)(gbase + (long)(row0+8)*G4);
        }

        if (t) {
            if (tid == 0) {
                unsigned target = (unsigned)t * NB;
                while (*(volatile unsigned*)&g_cnt < target) { }
                __threadfence();
            }
            __syncthreads();
        }

        const float* hr = (t & 1) ? h1 : h0;
        #pragma unroll 4
        for (int i = 0; i < 16; i++) {
            int idx = tl + i*256;
            int rr = idx >> 6, cc = idx & 63;
            CPA16(hs_u32 + (uint32_t)(rr*HPAD + kbase + cc*4)*4,
                  hr + rr*HID + kbase + cc*4);
        }
        asm volatile("cp.async.commit_group;");
        asm volatile("cp.async.wait_group 0;" ::: "memory");
        if (kg == 0) asm volatile("bar.sync 1, 256;" ::: "memory");
        else         asm volatile("bar.sync 2, 256;" ::: "memory");

        float acc[4] = {0.f, 0.f, 0.f, 0.f};
        #pragma unroll 4
        for (int k0 = kbase; k0 < kbase + 256; k0 += 8) {
            float a0 = arow0[k0+q  ];
            float a1 = arow8[k0+q  ];
            float a2 = arow0[k0+q+4];
            float a3 = arow8[k0+q+4];
            float h0f = tf32_rnd(a0), h1f = tf32_rnd(a1);
            float h2f = tf32_rnd(a2), h3f = tf32_rnd(a3);
            uint32_t ah[4] = { fu(h0f), fu(h1f), fu(h2f), fu(h3f) };
            uint32_t al[4] = { fu(a0 - h0f), fu(a1 - h1f),
                               fu(a2 - h2f), fu(a3 - h3f) };
            uint32_t bh[2] = { fu(brh[k0+q]), fu(brh[k0+q+4]) };
            uint32_t bl[2] = { fu(brl[k0+q]), fu(brl[k0+q+4]) };
            MMA8(acc, ah, bh);
            MMA8(acc, ah, bl);
            MMA8(acc, al, bh);
        }

        if (kg == 1)
            ((float4*)red)[wl*32 + lane] = make_float4(acc[0], acc[1], acc[2], acc[3]);
        __syncthreads();

        if (kg == 0) {
            float4 pa = ((float4*)red)[wl*32 + lane];
            float p0 = acc[0] + pa.x + gA.x;
            float p1 = acc[1] + pa.y + gA.y;
            float p2 = acc[2] + pa.z + gB.x;
            float p3 = acc[3] + pa.w + gB.y;

            float s0, s1, s2, s3;
            if (q & 1) {
                s0 = tanhf(p0);
                s1 = 1.f / (1.f + expf(-p1));
                s2 = tanhf(p2);
                s3 = 1.f / (1.f + expf(-p3));
            } else {
                s0 = 1.f / (1.f + expf(-p0));
                s1 = 1.f / (1.f + expf(-p1));
                s2 = 1.f / (1.f + expf(-p2));
                s3 = 1.f / (1.f + expf(-p3));
            }
            float x0 = __shfl_xor_sync(0xFFFFFFFFu, s0, 1);
            float x1 = __shfl_xor_sync(0xFFFFFFFFu, s1, 1);
            float x2 = __shfl_xor_sync(0xFFFFFFFFu, s2, 1);
            float x3 = __shfl_xor_sync(0xFFFFFFFFu, s3, 1);

            if (!(q & 1)) {
                c_a = s0 * c_a + s1 * x0;
                float hA = x1 * tanhf(c_a);
                c_b = s2 * c_b + s3 * x2;
                float hB = x3 * tanhf(c_b);

                float* hw = (t & 1) ? h0 : h1;
                hw[row0*HID + u] = hA;
                hw[(row0+8)*HID + u] = hB;
                g_lstm[((long)t*BATCH + row0)*HID + u] = hA;
                g_lstm[((long)t*BATCH + row0+8)*HID + u] = hB;
                if (t == S_LEN-1) {
                    g_c[row0*HID + u] = c_a;
                    g_c[(row0+8)*HID + u] = c_b;
                }
            }
        }

        __syncthreads();
        if (tid == 0) {
            __threadfence();
            atomicAdd(&g_cnt, 1u);
        }
    }
}

// ---------------------------------------------------------------------------
// Row softmax over 512-wide rows. One block (128 threads) per row.
// ---------------------------------------------------------------------------
__global__ __launch_bounds__(128)
void softmax512(float* __restrict__ s)
{
    float* row = s + (size_t)blockIdx.x * 512;
    int tid = threadIdx.x;
    float v0 = row[tid], v1 = row[tid+128], v2 = row[tid+256], v3 = row[tid+384];
    float mx = fmaxf(fmaxf(v0, v1), fmaxf(v2, v3));
    __shared__ float sm[4];
    __shared__ float ss[4];
    #pragma unroll
    for (int off = 16; off > 0; off >>= 1)
        mx = fmaxf(mx, __shfl_xor_sync(0xFFFFFFFFu, mx, off));
    if ((tid & 31) == 0) sm[tid >> 5] = mx;
    __syncthreads();
    mx = fmaxf(fmaxf(sm[0], sm[1]), fmaxf(sm[2], sm[3]));
    v0 = expf(v0 - mx); v1 = expf(v1 - mx); v2 = expf(v2 - mx); v3 = expf(v3 - mx);
    float sum = v0 + v1 + v2 + v3;
    #pragma unroll
    for (int off = 16; off > 0; off >>= 1)
        sum += __shfl_xor_sync(0xFFFFFFFFu, sum, off);
    if ((tid & 31) == 0) ss[tid >> 5] = sum;
    __syncthreads();
    sum = ss[0] + ss[1] + ss[2] + ss[3];
    float inv = 1.f / sum;
    row[tid] = v0*inv; row[tid+128] = v1*inv; row[tid+256] = v2*inv; row[tid+384] = v3*inv;
}

__global__ void copy_hc(const float* __restrict__ h, const float* __restrict__ c,
                        float* __restrict__ out)
{
    int i = blockIdx.x * blockDim.x + threadIdx.x;
    if (i < BATCH*HID) {
        out[DEC_ELEMS + i] = h[i];
        out[DEC_ELEMS + BATCH*HID + i] = c[i];
    }
}

// ---------------------------------------------------------------------------
// Host orchestration (graph-capturable: launches only)
// ---------------------------------------------------------------------------
extern "C" void kernel_launch(void* const* d_in, const int* in_sizes, int n_in,
                              void* d_out, int out_size)
{
    const float* x  = (const float*)d_in[0];
    const float* Wf = (const float*)d_in[1];
    const float* bf = (const float*)d_in[2];
    const float* Wi = (const float*)d_in[3];
    const float* bi = (const float*)d_in[4];
    const float* Wg = (const float*)d_in[5];
    const float* bg = (const float*)d_in[6];
    const float* Wo = (const float*)d_in[7];
    const float* bo = (const float*)d_in[8];
    const float* Wq = (const float*)d_in[9];
    const float* bq = (const float*)d_in[10];
    const float* Wk = (const float*)d_in[11];
    const float* bk = (const float*)d_in[12];
    const float* Wv = (const float*)d_in[13];
    const float* bv = (const float*)d_in[14];
    float* out = (float*)d_out;

    float *biasp, *gx, *lstm, *hbase, *c, *PQ, *PK, *PV, *Wxph, *Wxpl;
    uint32_t *Wqh, *Wql, *Wkh, *Wkl, *Wvh, *Wvl;
    cudaGetSymbolAddress((void**)&biasp, g_biasp);
    cudaGetSymbolAddress((void**)&gx,    g_gx);
    cudaGetSymbolAddress((void**)&lstm,  g_lstm);
    cudaGetSymbolAddress((void**)&hbase, g_h);
    cudaGetSymbolAddress((void**)&c,     g_c);
    cudaGetSymbolAddress((void**)&PQ,    g_PQ);
    cudaGetSymbolAddress((void**)&PK,    g_PK);
    cudaGetSymbolAddress((void**)&PV,    g_PV);
    cudaGetSymbolAddress((void**)&Wxph,  g_Wxph);
    cudaGetSymbolAddress((void**)&Wxpl,  g_Wxpl);
    cudaGetSymbolAddress((void**)&Wqh,   g_Wqh);
    cudaGetSymbolAddress((void**)&Wql,   g_Wql);
    cudaGetSymbolAddress((void**)&Wkh,   g_Wkh);
    cudaGetSymbolAddress((void**)&Wkl,   g_Wkl);
    cudaGetSymbolAddress((void**)&Wvh,   g_Wvh);
    cudaGetSymbolAddress((void**)&Wvl,   g_Wvl);
    float* h0 = hbase;

    const int SMEM_LSTM = (96*HPAD + 8*32*4) * (int)sizeof(float);
    cudaFuncSetAttribute(lstm_persistent,
                         cudaFuncAttributeMaxDynamicSharedMemorySize, SMEM_LSTM);

    // 1. repack + zero + pre-split weights
    pack_weights<<<(768*HID + 255)/256, 256>>>(Wf, Wi, Wg, Wo, bf, bi, bg, bo);
    zero_state<<<(BATCH*HID + 255)/256, 256>>>();
    split_wxp<<<(D_IN*G4 + 255)/256, 256>>>();
    const int NW = (HID/2)*HID;
    split_w_bfp<<<(NW + 255)/256, 256>>>(Wq, Wqh, Wql, HID, NW);
    split_w_bfp<<<(NW + 255)/256, 256>>>(Wk, Wkh, Wkl, HID, NW);
    split_w_bfp<<<(NW + 255)/256, 256>>>(Wv, Wvh, Wvl, HID, NW);

    // 2. x-side gate preacts (tf32 3-split — feeds the recurrence)
    gemm_tf32_pb<<<dim3(G4/64, ROWS/128), 256>>>(
        x, D_IN, Wxph, Wxpl, G4, biasp, gx, G4, D_IN, 1.0f);

    // 3. recurrence: persistent tensor-core kernel, k-split, grid barrier/step
    lstm_persistent<<<NB, 512, SMEM_LSTM>>>(gx);

    // 4. Q/K/V projections (bf16 3-split, pre-packed weights)
    gemm_bf16_pb<<<dim3(HID/64, ROWS/128), 256>>>(
        lstm, HID, Wqh, Wql, HID, bq, PQ, HID, HID, 1.0f);
    gemm_bf16_pb<<<dim3(HID/64, ROWS/128), 256>>>(
        lstm, HID, Wkh, Wkl, HID, bk, PK, HID, HID, 1.0f);
    gemm_bf16_pb<<<dim3(HID/64, ROWS/128), 256>>>(
        lstm, HID, Wvh, Wvl, HID, bv, PV, HID, HID, 1.0f);

    // 5. scores = (Q @ K^T)/sqrt(dk)  (bf16 3-split)
    const long pbS = (long)S_LEN * HID;
    const long phS = DK;
    const long scB = 4L * S_LEN * S_LEN;
    const long scH = (long)S_LEN * S_LEN;
    float scale = 1.0f / sqrtf((float)DK);
    gemm_bf16<<<dim3(S_LEN/64, S_LEN/128, BATCH*NH), 256>>>(
        PQ, HID, pbS, phS,
        PK, HID, pbS, phS,
        (const float*)0,
        gx /* reused as scores */, S_LEN, scB, scH, DK, scale, 1);

    // 6. softmax over last axis
    softmax512<<<BATCH*NH*S_LEN, 128>>>(gx);

    // 7. out = attn @ V (bf16 3-split), decoded layout
    gemm_bf16<<<dim3(DK/64, S_LEN/128, BATCH*NH), 256>>>(
        gx, S_LEN, scB, scH,
        PV, HID, pbS, phS,
        (const float*)0,
        out, BATCH*HID, (long)HID, (long)DK, S_LEN, 1.0f, 0);

    // 8. final hidden/cell state (after step 511 the live h buffer is h0)
    copy_hc<<<(BATCH*HID + 255)/256, 256>>>(h0, c, out);
}

// round 16
// speedup vs baseline: 1.5503x; 1.1538x over previous
#include <cuda_runtime.h>
#include <math.h>
#include <stdint.h>

// ---------------------------------------------------------------------------
// Problem constants
// ---------------------------------------------------------------------------
#define S_LEN   512
#define BATCH   64
#define D_IN    256
#define HID     512
#define G4      2048        // 4 gates * HID, packed unit-major: col = u*4 + gate
#define NH      4
#define DK      128
#define ROWS    (S_LEN*BATCH)        // 32768
#define DEC_ELEMS (S_LEN*BATCH*HID)  // 16777216
#define NB      128                  // persistent LSTM blocks (1/SM -> full chip)
#define KPW     256                  // k-pairs per h row (HID/2)
#define KPP     260                  // kp-array smem pitch (mod 32 == 4)
#define APITCH  20                   // gemm A-smem pitch (floats)
#define BPITCH  72                   // gemm B-smem pitch, normal path
#define BTFL    1280                 // gemm B buffer floats (max of 16*72, 64*20)

// ---------------------------------------------------------------------------
// Device scratch (static allocations only — no cudaMalloc allowed)
// ---------------------------------------------------------------------------
__device__ float g_Wxp[D_IN*G4];          //   2 MB  packed input-gate weights
__device__ float g_Whp[HID*G4];           //   4 MB  packed recurrent-gate weights
__device__ float g_biasp[G4];
__device__ float g_gx[ROWS*G4];           // 256 MB  x-side gate preacts; reused as attn scores
__device__ float g_lstm[ROWS*HID];        //  64 MB  lstm_out [S,B,HID]
__device__ uint32_t g_hh[2][BATCH*KPW];   //  h double buffer, packed bf16x2 hi
__device__ uint32_t g_hl[2][BATCH*KPW];   //  h double buffer, packed bf16x2 lo
__device__ float g_c[BATCH*HID];
__device__ float g_PQ[ROWS*HID];          //  64 MB
__device__ float g_PK[ROWS*HID];
__device__ float g_PV[ROWS*HID];
__device__ unsigned g_cnt;                //  grid barrier counter
// pre-split copies: Wxp as fp32 hi/lo (tf32 path); Wq/k/v as packed bf16x2 hi/lo
__device__ float g_Wxph[D_IN*G4], g_Wxpl[D_IN*G4];
__device__ uint32_t g_Wqh[(HID/2)*HID], g_Wql[(HID/2)*HID];
__device__ uint32_t g_Wkh[(HID/2)*HID], g_Wkl[(HID/2)*HID];
__device__ uint32_t g_Wvh[(HID/2)*HID], g_Wvl[(HID/2)*HID];

// ---------------------------------------------------------------------------
// Helpers
// ---------------------------------------------------------------------------
__device__ __forceinline__ float tf32_rnd(float x) {
    uint32_t u; asm("cvt.rna.tf32.f32 %0, %1;" : "=r"(u) : "f"(x));
    return __uint_as_float(u);
}
__device__ __forceinline__ uint32_t fu(float x) { return __float_as_uint(x); }

// bf16 pair split: h = {trunc16(f0) lo, trunc16(f1) hi} (exact bf16 values),
// l = rn-bf16x2 of the exact fp32 residuals. low half = even-k element.
__device__ __forceinline__ void bsplit2(float f0, float f1, uint32_t& h, uint32_t& l)
{
    uint32_t u0 = __float_as_uint(f0), u1 = __float_as_uint(f1);
    asm("prmt.b32 %0, %1, %2, 0x7632;" : "=r"(h) : "r"(u0), "r"(u1));
    float h0 = __uint_as_float(u0 & 0xFFFF0000u);
    float h1 = __uint_as_float(u1 & 0xFFFF0000u);
    asm("cvt.rn.bf16x2.f32 %0, %1, %2;" : "=r"(l) : "f"(f1 - h1), "f"(f0 - h0));
}

#define MMA8(cc, a, bb) \
    asm volatile("mma.sync.aligned.m16n8k8.row.col.f32.tf32.tf32.f32 " \
        "{%0,%1,%2,%3},{%4,%5,%6,%7},{%8,%9},{%0,%1,%2,%3};" \
        : "+f"(cc[0]), "+f"(cc[1]), "+f"(cc[2]), "+f"(cc[3]) \
        : "r"(a[0]), "r"(a[1]), "r"(a[2]), "r"(a[3]), "r"(bb[0]), "r"(bb[1]))

#define MMA16(cc, a, bb) \
    asm volatile("mma.sync.aligned.m16n8k16.row.col.f32.bf16.bf16.f32 " \
        "{%0,%1,%2,%3},{%4,%5,%6,%7},{%8,%9},{%0,%1,%2,%3};" \
        : "+f"(cc[0]), "+f"(cc[1]), "+f"(cc[2]), "+f"(cc[3]) \
        : "r"(a[0]), "r"(a[1]), "r"(a[2]), "r"(a[3]), "r"(bb[0]), "r"(bb[1]))

#define CPA16(dst, src) \
    asm volatile("cp.async.cg.shared.global [%0], [%1], 16;" :: "r"(dst), "l"(src))

// ---------------------------------------------------------------------------
// Weight repack + splits
// ---------------------------------------------------------------------------
__global__ void pack_weights(const float* __restrict__ Wf, const float* __restrict__ Wi,
                             const float* __restrict__ Wg, const float* __restrict__ Wo,
                             const float* __restrict__ bf, const float* __restrict__ bi,
                             const float* __restrict__ bg, const float* __restrict__ bo)
{
    int idx = blockIdx.x * blockDim.x + threadIdx.x;   // over 768*512
    if (idx < 768*HID) {
        int k = idx / HID, u = idx % HID;
        float vf = Wf[idx], vi = Wi[idx], vg = Wg[idx], vo = Wo[idx];
        float* dst = (k < D_IN) ? (g_Wxp + (long)k*G4) : (g_Whp + (long)(k - D_IN)*G4);
        dst[u*4+0] = vf; dst[u*4+1] = vi; dst[u*4+2] = vg; dst[u*4+3] = vo;
    }
    if (idx < HID) {
        g_biasp[idx*4+0] = bf[idx];
        g_biasp[idx*4+1] = bi[idx];
        g_biasp[idx*4+2] = bg[idx];
        g_biasp[idx*4+3] = bo[idx];
    }
}

__global__ void zero_state()
{
    int i = blockIdx.x * blockDim.x + threadIdx.x;
    if (i < BATCH*KPW) { g_hh[0][i] = 0u; g_hl[0][i] = 0u; }
    if (i < BATCH*HID) g_c[i] = 0.f;
    if (i == 0) g_cnt = 0u;
}

__global__ void split_wxp()
{
    int i = blockIdx.x * blockDim.x + threadIdx.x;
    if (i < D_IN*G4) {
        float w = g_Wxp[i];
        float hi = tf32_rnd(w);
        g_Wxph[i] = hi;
        g_Wxpl[i] = w - hi;
    }
}

// pack W[K][N] fp32 into bf16x2 hi/lo arrays [K/2][N] (k-pairs per entry)
__global__ void split_w_bfp(const float* __restrict__ W, uint32_t* __restrict__ Wh,
                            uint32_t* __restrict__ Wl, int N, int total)
{
    int idx = blockIdx.x * blockDim.x + threadIdx.x;
    if (idx < total) {
        int kp = idx / N, n = idx - kp*N;
        float f0 = W[(long)(2*kp)*N + n];
        float f1 = W[(long)(2*kp+1)*N + n];
        uint32_t h, l;
        bsplit2(f0, f1, h, l);
        Wh[idx] = h;
        Wl[idx] = l;
    }
}

// ---------------------------------------------------------------------------
// tf32 3-split GEMM, PRE-SPLIT B (fp32 hi/lo). Used ONLY for gx. Proven R13-15.
// ---------------------------------------------------------------------------
__global__ __launch_bounds__(256, 2)
void gemm_tf32_pb(const float* __restrict__ A, int lda,
                  const float* __restrict__ Bh, const float* __restrict__ Bl, int ldb,
                  const float* __restrict__ bias,
                  float* __restrict__ C, int ldc,
                  int K, float alpha)
{
    __shared__ float As [2][128*APITCH];
    __shared__ float Bhs[2][16*BPITCH];
    __shared__ float Bls[2][16*BPITCH];

    int m0 = blockIdx.y * 128, n0 = blockIdx.x * 64;

    int tid = threadIdx.x;
    int warp = tid >> 5, lane = tid & 31;
    int wm = (warp >> 1) * 32, wn = (warp & 1) * 32;
    int r = lane >> 2, q = lane & 3;

    const uint32_t a_smem  = (uint32_t)__cvta_generic_to_shared(&As[0][0]);
    const uint32_t bh_smem = (uint32_t)__cvta_generic_to_shared(&Bhs[0][0]);
    const uint32_t bl_smem = (uint32_t)__cvta_generic_to_shared(&Bls[0][0]);
    const uint32_t abuf = 128*APITCH*4;
    const uint32_t bbuf = 16*BPITCH*4;

    int am0 = tid >> 2, ac = tid & 3;
    int bkr = tid >> 4, bc = tid & 15;

    int KT = K >> 4;

    auto issue = [&](int kt) {
        int k0 = kt << 4, buf = kt & 1;
        CPA16(a_smem + buf*abuf + (uint32_t)(am0*APITCH + ac*4)*4,
              A + (long)(m0 + am0)*lda + k0 + ac*4);
        CPA16(a_smem + buf*abuf + (uint32_t)((am0+64)*APITCH + ac*4)*4,
              A + (long)(m0 + am0 + 64)*lda + k0 + ac*4);
        CPA16(bh_smem + buf*bbuf + (uint32_t)(bkr*BPITCH + bc*4)*4,
              Bh + (long)(k0 + bkr)*ldb + n0 + bc*4);
        CPA16(bl_smem + buf*bbuf + (uint32_t)(bkr*BPITCH + bc*4)*4,
              Bl + (long)(k0 + bkr)*ldb + n0 + bc*4);
        asm volatile("cp.async.commit_group;");
    };

    float acc[2][4][4];
    #pragma unroll
    for (int mt = 0; mt < 2; mt++)
        #pragma unroll
        for (int nt = 0; nt < 4; nt++)
            #pragma unroll
            for (int e = 0; e < 4; e++) acc[mt][nt][e] = 0.f;

    issue(0);
    for (int kt = 0; kt < KT; kt++) {
        if (kt + 1 < KT) {
            issue(kt + 1);
            asm volatile("cp.async.wait_group 1;" ::: "memory");
        } else {
            asm volatile("cp.async.wait_group 0;" ::: "memory");
        }
        __syncthreads();

        const float* Abb = &As [kt & 1][0];
        const float* Bhb = &Bhs[kt & 1][0];
        const float* Blb = &Bls[kt & 1][0];
        #pragma unroll
        for (int p = 0; p < 2; p++) {
            int kb = p*8;
            uint32_t bh[4][2], bl[4][2];
            #pragma unroll
            for (int nt = 0; nt < 4; nt++) {
                int n = wn + nt*8 + r;
                bh[nt][0] = fu(Bhb[(kb+q  )*BPITCH + n]);
                bh[nt][1] = fu(Bhb[(kb+q+4)*BPITCH + n]);
                bl[nt][0] = fu(Blb[(kb+q  )*BPITCH + n]);
                bl[nt][1] = fu(Blb[(kb+q+4)*BPITCH + n]);
            }
            #pragma unroll
            for (int mt = 0; mt < 2; mt++) {
                int m = wm + mt*16 + r;
                float ar[4];
                ar[0] = Abb[ m     *APITCH + kb+q  ];
                ar[1] = Abb[(m+8)  *APITCH + kb+q  ];
                ar[2] = Abb[ m     *APITCH + kb+q+4];
                ar[3] = Abb[(m+8)  *APITCH + kb+q+4];
                uint32_t ah[4], al[4];
                #pragma unroll
                for (int e = 0; e < 4; e++) {
                    float hi = tf32_rnd(ar[e]);
                    ah[e] = fu(hi);
                    al[e] = fu(ar[e] - hi);
                }
                #pragma unroll
                for (int nt = 0; nt < 4; nt++) {
                    MMA8(acc[mt][nt], ah, bh[nt]);
                    MMA8(acc[mt][nt], ah, bl[nt]);
                    MMA8(acc[mt][nt], al, bh[nt]);
                }
            }
        }
        __syncthreads();
    }

    #pragma unroll
    for (int mt = 0; mt < 2; mt++)
        #pragma unroll
        for (int nt = 0; nt < 4; nt++) {
            int mrow = m0 + wm + mt*16 + r;
            int ncol = n0 + wn + nt*8 + q*2;
            float b0 = bias ? bias[ncol]   : 0.f;
            float b1 = bias ? bias[ncol+1] : 0.f;
            C[(long)mrow*ldc + ncol  ]     = alpha*acc[mt][nt][0] + b0;
            C[(long)mrow*ldc + ncol+1]     = alpha*acc[mt][nt][1] + b1;
            C[(long)(mrow+8)*ldc + ncol  ] = alpha*acc[mt][nt][2] + b0;
            C[(long)(mrow+8)*ldc + ncol+1] = alpha*acc[mt][nt][3] + b1;
        }
}

// ---------------------------------------------------------------------------
// bf16 3-split GEMM (m16n8k16), runtime split. Scores (transB=1) and attn@V.
// Proven R15.
// ---------------------------------------------------------------------------
__global__ __launch_bounds__(256, 2)
void gemm_bf16(const float* __restrict__ A, int lda, long as1, long as2,
               const float* __restrict__ B, int ldb, long bs1, long bs2,
               const float* __restrict__ bias,
               float* __restrict__ C, int ldc, long cs1, long cs2,
               int K, float alpha, int transB)
{
    __shared__ float As[2][128*APITCH];
    __shared__ float Bs[2][BTFL];

    int z = blockIdx.z;
    A += (long)(z >> 2) * as1 + (long)(z & 3) * as2;
    B += (long)(z >> 2) * bs1 + (long)(z & 3) * bs2;
    C += (long)(z >> 2) * cs1 + (long)(z & 3) * cs2;
    int m0 = blockIdx.y * 128, n0 = blockIdx.x * 64;

    int tid = threadIdx.x;
    int warp = tid >> 5, lane = tid & 31;
    int wm = (warp >> 1) * 32, wn = (warp & 1) * 32;
    int r = lane >> 2, q = lane & 3;

    const uint32_t a_smem = (uint32_t)__cvta_generic_to_shared(&As[0][0]);
    const uint32_t b_smem = (uint32_t)__cvta_generic_to_shared(&Bs[0][0]);
    const uint32_t abuf = 128*APITCH*4;
    const uint32_t bbuf = BTFL*4;

    int am0 = tid >> 2, ac = tid & 3;
    int bkr = tid >> 4, bc = tid & 15;
    int bn = tid >> 2, bc4 = tid & 3;

    int KT = K >> 4;

    auto issue = [&](int kt) {
        int k0 = kt << 4, buf = kt & 1;
        CPA16(a_smem + buf*abuf + (uint32_t)(am0*APITCH + ac*4)*4,
              A + (long)(m0 + am0)*lda + k0 + ac*4);
        CPA16(a_smem + buf*abuf + (uint32_t)((am0+64)*APITCH + ac*4)*4,
              A + (long)(m0 + am0 + 64)*lda + k0 + ac*4);
        if (!transB) {
            CPA16(b_smem + buf*bbuf + (uint32_t)(bkr*BPITCH + bc*4)*4,
                  B + (long)(k0 + bkr)*ldb + n0 + bc*4);
        } else {
            CPA16(b_smem + buf*bbuf + (uint32_t)(bn*APITCH + bc4*4)*4,
                  B + (long)(n0 + bn)*ldb + k0 + bc4*4);
        }
        asm volatile("cp.async.commit_group;");
    };

    float acc[2][4][4];
    #pragma unroll
    for (int mt = 0; mt < 2; mt++)
        #pragma unroll
        for (int nt = 0; nt < 4; nt++)
            #pragma unroll
            for (int e = 0; e < 4; e++) acc[mt][nt][e] = 0.f;

    issue(0);
    for (int kt = 0; kt < KT; kt++) {
        if (kt + 1 < KT) {
            issue(kt + 1);
            asm volatile("cp.async.wait_group 1;" ::: "memory");
        } else {
            asm volatile("cp.async.wait_group 0;" ::: "memory");
        }
        __syncthreads();

        const float* Ab = &As[kt & 1][0];
        const float* Bb = &Bs[kt & 1][0];

        uint32_t bh[4][2], bl[4][2];
        #pragma unroll
        for (int nt = 0; nt < 4; nt++) {
            int n = wn + nt*8 + r;
            if (!transB) {
                bsplit2(Bb[(2*q  )*BPITCH + n], Bb[(2*q+1)*BPITCH + n],
                        bh[nt][0], bl[nt][0]);
                bsplit2(Bb[(2*q+8)*BPITCH + n], Bb[(2*q+9)*BPITCH + n],
                        bh[nt][1], bl[nt][1]);
            } else {
                float2 p0 = *(const float2*)(Bb + n*APITCH + 2*q);
                float2 p1 = *(const float2*)(Bb + n*APITCH + 2*q + 8);
                bsplit2(p0.x, p0.y, bh[nt][0], bl[nt][0]);
                bsplit2(p1.x, p1.y, bh[nt][1], bl[nt][1]);
            }
        }

        #pragma unroll
        for (int mt = 0; mt < 2; mt++) {
            int m = wm + mt*16 + r;
            float2 q0 = *(const float2*)(Ab +  m    *APITCH + 2*q);
            float2 q1 = *(const float2*)(Ab + (m+8) *APITCH + 2*q);
            float2 q2 = *(const float2*)(Ab +  m    *APITCH + 2*q + 8);
            float2 q3 = *(const float2*)(Ab + (m+8) *APITCH + 2*q + 8);
            uint32_t ah[4], al[4];
            bsplit2(q0.x, q0.y, ah[0], al[0]);
            bsplit2(q1.x, q1.y, ah[1], al[1]);
            bsplit2(q2.x, q2.y, ah[2], al[2]);
            bsplit2(q3.x, q3.y, ah[3], al[3]);
            #pragma unroll
            for (int nt = 0; nt < 4; nt++) {
                MMA16(acc[mt][nt], ah, bh[nt]);
                MMA16(acc[mt][nt], ah, bl[nt]);
                MMA16(acc[mt][nt], al, bh[nt]);
            }
        }
        __syncthreads();
    }

    #pragma unroll
    for (int mt = 0; mt < 2; mt++)
        #pragma unroll
        for (int nt = 0; nt < 4; nt++) {
            int mrow = m0 + wm + mt*16 + r;
            int ncol = n0 + wn + nt*8 + q*2;
            float b0 = bias ? bias[ncol]   : 0.f;
            float b1 = bias ? bias[ncol+1] : 0.f;
            C[(long)mrow*ldc + ncol  ]     = alpha*acc[mt][nt][0] + b0;
            C[(long)mrow*ldc + ncol+1]     = alpha*acc[mt][nt][1] + b1;
            C[(long)(mrow+8)*ldc + ncol  ] = alpha*acc[mt][nt][2] + b0;
            C[(long)(mrow+8)*ldc + ncol+1] = alpha*acc[mt][nt][3] + b1;
        }
}

// ---------------------------------------------------------------------------
// bf16 3-split GEMM, PRE-PACKED B. Q/K/V projections. Proven R15.
// ---------------------------------------------------------------------------
__global__ __launch_bounds__(256, 2)
void gemm_bf16_pb(const float* __restrict__ A, int lda,
                  const uint32_t* __restrict__ Bhp, const uint32_t* __restrict__ Blp,
                  int ldbp,
                  const float* __restrict__ bias,
                  float* __restrict__ C, int ldc,
                  int K, float alpha)
{
    __shared__ float    As [2][128*APITCH];
    __shared__ uint32_t Bhs[2][8*BPITCH];
    __shared__ uint32_t Bls[2][8*BPITCH];

    int m0 = blockIdx.y * 128, n0 = blockIdx.x * 64;

    int tid = threadIdx.x;
    int warp = tid >> 5, lane = tid & 31;
    int wm = (warp >> 1) * 32, wn = (warp & 1) * 32;
    int r = lane >> 2, q = lane & 3;

    const uint32_t a_smem  = (uint32_t)__cvta_generic_to_shared(&As[0][0]);
    const uint32_t bh_smem = (uint32_t)__cvta_generic_to_shared(&Bhs[0][0]);
    const uint32_t bl_smem = (uint32_t)__cvta_generic_to_shared(&Bls[0][0]);
    const uint32_t abuf = 128*APITCH*4;
    const uint32_t bbuf = 8*BPITCH*4;

    int am0 = tid >> 2, ac = tid & 3;
    int tl  = tid & 127;
    int brow = tl >> 4, bch = tl & 15;

    int KT = K >> 4;

    auto issue = [&](int kt) {
        int k0 = kt << 4, kp0 = kt << 3, buf = kt & 1;
        CPA16(a_smem + buf*abuf + (uint32_t)(am0*APITCH + ac*4)*4,
              A + (long)(m0 + am0)*lda + k0 + ac*4);
        CPA16(a_smem + buf*abuf + (uint32_t)((am0+64)*APITCH + ac*4)*4,
              A + (long)(m0 + am0 + 64)*lda + k0 + ac*4);
        if (tid < 128) {
            CPA16(bh_smem + buf*bbuf + (uint32_t)(brow*BPITCH + bch*4)*4,
                  Bhp + (long)(kp0 + brow)*ldbp + n0 + bch*4);
        } else {
            CPA16(bl_smem + buf*bbuf + (uint32_t)(brow*BPITCH + bch*4)*4,
                  Blp + (long)(kp0 + brow)*ldbp + n0 + bch*4);
        }
        asm volatile("cp.async.commit_group;");
    };

    float acc[2][4][4];
    #pragma unroll
    for (int mt = 0; mt < 2; mt++)
        #pragma unroll
        for (int nt = 0; nt < 4; nt++)
            #pragma unroll
            for (int e = 0; e < 4; e++) acc[mt][nt][e] = 0.f;

    issue(0);
    for (int kt = 0; kt < KT; kt++) {
        if (kt + 1 < KT) {
            issue(kt + 1);
            asm volatile("cp.async.wait_group 1;" ::: "memory");
        } else {
            asm volatile("cp.async.wait_group 0;" ::: "memory");
        }
        __syncthreads();

        const float*    Ab  = &As [kt & 1][0];
        const uint32_t* Bhb = &Bhs[kt & 1][0];
        const uint32_t* Blb = &Bls[kt & 1][0];

        uint32_t bh[4][2], bl[4][2];
        #pragma unroll
        for (int nt = 0; nt < 4; nt++) {
            int n = wn + nt*8 + r;
            bh[nt][0] = Bhb[ q     *BPITCH + n];
            bh[nt][1] = Bhb[(q+4)  *BPITCH + n];
            bl[nt][0] = Blb[ q     *BPITCH + n];
            bl[nt][1] = Blb[(q+4)  *BPITCH + n];
        }

        #pragma unroll
        for (int mt = 0; mt < 2; mt++) {
            int m = wm + mt*16 + r;
            float2 q0 = *(const float2*)(Ab +  m    *APITCH + 2*q);
            float2 q1 = *(const float2*)(Ab + (m+8) *APITCH + 2*q);
            float2 q2 = *(const float2*)(Ab +  m    *APITCH + 2*q + 8);
            float2 q3 = *(const float2*)(Ab + (m+8) *APITCH + 2*q + 8);
            uint32_t ah[4], al[4];
            bsplit2(q0.x, q0.y, ah[0], al[0]);
            bsplit2(q1.x, q1.y, ah[1], al[1]);
            bsplit2(q2.x, q2.y, ah[2], al[2]);
            bsplit2(q3.x, q3.y, ah[3], al[3]);
            #pragma unroll
            for (int nt = 0; nt < 4; nt++) {
                MMA16(acc[mt][nt], ah, bh[nt]);
                MMA16(acc[mt][nt], ah, bl[nt]);
                MMA16(acc[mt][nt], al, bh[nt]);
            }
        }
        __syncthreads();
    }

    #pragma unroll
    for (int mt = 0; mt < 2; mt++)
        #pragma unroll
        for (int nt = 0; nt < 4; nt++) {
            int mrow = m0 + wm + mt*16 + r;
            int ncol = n0 + wn + nt*8 + q*2;
            float b0 = bias ? bias[ncol]   : 0.f;
            float b1 = bias ? bias[ncol+1] : 0.f;
            C[(long)mrow*ldc + ncol  ]     = alpha*acc[mt][nt][0] + b0;
            C[(long)mrow*ldc + ncol+1]     = alpha*acc[mt][nt][1] + b1;
            C[(long)(mrow+8)*ldc + ncol  ] = alpha*acc[mt][nt][2] + b0;
            C[(long)(mrow+8)*ldc + ncol+1] = alpha*acc[mt][nt][3] + b1;
        }
}

// ---------------------------------------------------------------------------
// Persistent LSTM recurrence — bf16-split tensor-core matvec, k-split over
// 16 warps (two 8-warp groups). h is PRODUCED pre-split: epilogue writes
// packed bf16x2 hi/lo global arrays (hi = exact truncation, lo = rn residual),
// so the k-loop is pure LDS + MMA16 (no conversions). Weights pre-split once
// into packed bf16x2 smem [j][kp], pitch 260 (conflict-free).
// ---------------------------------------------------------------------------
__global__ __launch_bounds__(512)
void lstm_persistent(const float* __restrict__ gx)
{
    extern __shared__ uint32_t smu[];
    uint32_t* WBh = smu;                   // [16][260] weight hi (bf16x2, kp-packed)
    uint32_t* WBl = smu + 16*KPP;          // [16][260] weight lo
    uint32_t* hH  = smu + 32*KPP;          // [64][260] h hi
    uint32_t* hL  = smu + 32*KPP + 64*KPP; // [64][260] h lo
    float*    red = (float*)(smu + 32*KPP + 128*KPP);   // [8][32][4]

    const int tid = threadIdx.x, bid = blockIdx.x;
    const int c0 = bid * 16;
    const int warp = tid >> 5, lane = tid & 31;
    const int kg = warp >> 3;           // k-group: 0 or 1
    const int wl = warp & 7;            // warp id within group
    const int nt = wl & 1;
    const int r = lane >> 2, q = lane & 3;
    const int row0 = (wl >> 1)*16 + r;

    // ---- presplit weight slice into packed bf16x2 hi/lo (once) ----
    for (int idx = tid; idx < 16*KPW; idx += 512) {
        int j = idx >> 8, kp = idx & 255;
        float w0 = g_Whp[(long)(2*kp  )*G4 + c0 + j];
        float w1 = g_Whp[(long)(2*kp+1)*G4 + c0 + j];
        uint32_t h, l;
        bsplit2(w0, w1, h, l);
        WBh[j*KPP + kp] = h;
        WBl[j*KPP + kp] = l;
    }

    float c_a = 0.f, c_b = 0.f;
    const int u = bid*4 + nt*2 + (q >> 1);

    const uint32_t hH_s = (uint32_t)__cvta_generic_to_shared(hH);
    const uint32_t hL_s = (uint32_t)__cvta_generic_to_shared(hL);
    __syncthreads();

    const uint32_t* aH0 = hH + row0*KPP;
    const uint32_t* aH8 = aH0 + 8*KPP;
    const uint32_t* aL0 = hL + row0*KPP;
    const uint32_t* aL8 = aL0 + 8*KPP;
    const uint32_t* bHr = WBh + (nt*8 + r)*KPP;
    const uint32_t* bLr = WBl + (nt*8 + r)*KPP;

    const int kpb = kg * 128;           // this group's kp-offset
    const int tl = tid & 255;

    for (int t = 0; t < S_LEN; t++) {
        float2 gA = make_float2(0.f, 0.f), gB = make_float2(0.f, 0.f);
        if (kg == 0) {
            const float* gbase = gx + ((long)t*BATCH)*G4 + c0 + nt*8 + 2*q;
            gA = *(const float2*)(gbase + (long)row0*G4);
            gB = *(const float2*)(gbase + (long)(row0+8)*G4);
        }

        // ---- grid barrier: all blocks done with step t-1 ----
        if (t) {
            if (tid == 0) {
                unsigned target = (unsigned)t * NB;
                while (*(volatile unsigned*)&g_cnt < target) { }
                __threadfence();
            }
            __syncthreads();
        }

        // ---- stage this group's kp-half of the pre-split h (hi + lo) ----
        const uint32_t* ghh = g_hh[t & 1];    // read buffer (t even -> [0])
        const uint32_t* ghl = g_hl[t & 1];
        // wait: convention from R14: read (t&1)?h1:h0 -> buffer index (t&1)
        #pragma unroll 4
        for (int i = 0; i < 8; i++) {
            int idx = tl + i*256;              // 0..2047 (16B chunks of hi)
            int rr = idx >> 5, cc = idx & 31;
            CPA16(hH_s + (uint32_t)(rr*KPP + kpb + cc*4)*4,
                  ghh + rr*KPW + kpb + cc*4);
        }
        #pragma unroll 4
        for (int i = 0; i < 8; i++) {
            int idx = tl + i*256;
            int rr = idx >> 5, cc = idx & 31;
            CPA16(hL_s + (uint32_t)(rr*KPP + kpb + cc*4)*4,
                  ghl + rr*KPW + kpb + cc*4);
        }
        asm volatile("cp.async.commit_group;");
        asm volatile("cp.async.wait_group 0;" ::: "memory");
        if (kg == 0) asm volatile("bar.sync 1, 256;" ::: "memory");
        else         asm volatile("bar.sync 2, 256;" ::: "memory");

        // ---- mma over this group's kp-half: 16 k16-iters, no conversions ----
        float acc[4] = {0.f, 0.f, 0.f, 0.f};
        #pragma unroll 4
        for (int kp0 = kpb; kp0 < kpb + 128; kp0 += 8) {
            uint32_t ah[4] = { aH0[kp0+q], aH8[kp0+q], aH0[kp0+q+4], aH8[kp0+q+4] };
            uint32_t al[4] = { aL0[kp0+q], aL8[kp0+q], aL0[kp0+q+4], aL8[kp0+q+4] };
            uint32_t bh[2] = { bHr[kp0+q], bHr[kp0+q+4] };
            uint32_t bl[2] = { bLr[kp0+q], bLr[kp0+q+4] };
            MMA16(acc, ah, bh);
            MMA16(acc, ah, bl);
            MMA16(acc, al, bh);
        }

        // ---- cross-group reduction ----
        if (kg == 1)
            ((float4*)red)[wl*32 + lane] = make_float4(acc[0], acc[1], acc[2], acc[3]);
        __syncthreads();

        if (kg == 0) {
            float4 pa = ((float4*)red)[wl*32 + lane];
            float p0 = acc[0] + pa.x + gA.x;
            float p1 = acc[1] + pa.y + gA.y;
            float p2 = acc[2] + pa.z + gB.x;
            float p3 = acc[3] + pa.w + gB.y;

            float s0, s1, s2, s3;
            if (q & 1) {                // odd lanes: cols are (g, o)
                s0 = tanhf(p0);
                s1 = 1.f / (1.f + expf(-p1));
                s2 = tanhf(p2);
                s3 = 1.f / (1.f + expf(-p3));
            } else {                    // even lanes: cols are (f, i)
                s0 = 1.f / (1.f + expf(-p0));
                s1 = 1.f / (1.f + expf(-p1));
                s2 = 1.f / (1.f + expf(-p2));
                s3 = 1.f / (1.f + expf(-p3));
            }
            float x0 = __shfl_xor_sync(0xFFFFFFFFu, s0, 1);
            float x1 = __shfl_xor_sync(0xFFFFFFFFu, s1, 1);
            float x2 = __shfl_xor_sync(0xFFFFFFFFu, s2, 1);
            float x3 = __shfl_xor_sync(0xFFFFFFFFu, s3, 1);

            if (!(q & 1)) {
                c_a = s0 * c_a + s1 * x0;
                float hA = x1 * tanhf(c_a);
                c_b = s2 * c_b + s3 * x2;
                float hB = x3 * tanhf(c_b);

                // fp32 lstm_out (consumed by QKV gemms)
                g_lstm[((long)t*BATCH + row0)*HID + u] = hA;
                g_lstm[((long)t*BATCH + row0+8)*HID + u] = hB;

                // pre-split h for the next step: hi = trunc16, lo = rn(residual)
                int wb = (t & 1) ^ 1;              // write buffer
                unsigned short* whh = (unsigned short*)g_hh[wb];
                unsigned short* whl = (unsigned short*)g_hl[wb];
                uint32_t uA = __float_as_uint(hA);
                uint32_t uB = __float_as_uint(hB);
                float rA = hA - __uint_as_float(uA & 0xFFFF0000u);
                float rB = hB - __uint_as_float(uB & 0xFFFF0000u);
                unsigned short lA, lB;
                asm("cvt.rn.bf16.f32 %0, %1;" : "=h"(lA) : "f"(rA));
                asm("cvt.rn.bf16.f32 %0, %1;" : "=h"(lB) : "f"(rB));
                whh[row0*HID + u]     = (unsigned short)(uA >> 16);
                whh[(row0+8)*HID + u] = (unsigned short)(uB >> 16);
                whl[row0*HID + u]     = lA;
                whl[(row0+8)*HID + u] = lB;

                if (t == S_LEN-1) {
                    g_c[row0*HID + u] = c_a;
                    g_c[(row0+8)*HID + u] = c_b;
                }
            }
        }

        // ---- arrive: cta barrier, then tid0-only fence + atomic ----
        __syncthreads();
        if (tid == 0) {
            __threadfence();
            atomicAdd(&g_cnt, 1u);
        }
    }
}

// ---------------------------------------------------------------------------
// Row softmax over 512-wide rows. One block (128 threads) per row.
// ---------------------------------------------------------------------------
__global__ __launch_bounds__(128)
void softmax512(float* __restrict__ s)
{
    float* row = s + (size_t)blockIdx.x * 512;
    int tid = threadIdx.x;
    float v0 = row[tid], v1 = row[tid+128], v2 = row[tid+256], v3 = row[tid+384];
    float mx = fmaxf(fmaxf(v0, v1), fmaxf(v2, v3));
    __shared__ float sm[4];
    __shared__ float ss[4];
    #pragma unroll
    for (int off = 16; off > 0; off >>= 1)
        mx = fmaxf(mx, __shfl_xor_sync(0xFFFFFFFFu, mx, off));
    if ((tid & 31) == 0) sm[tid >> 5] = mx;
    __syncthreads();
    mx = fmaxf(fmaxf(sm[0], sm[1]), fmaxf(sm[2], sm[3]));
    v0 = expf(v0 - mx); v1 = expf(v1 - mx); v2 = expf(v2 - mx); v3 = expf(v3 - mx);
    float sum = v0 + v1 + v2 + v3;
    #pragma unroll
    for (int off = 16; off > 0; off >>= 1)
        sum += __shfl_xor_sync(0xFFFFFFFFu, sum, off);
    if ((tid & 31) == 0) ss[tid >> 5] = sum;
    __syncthreads();
    sum = ss[0] + ss[1] + ss[2] + ss[3];
    float inv = 1.f / sum;
    row[tid] = v0*inv; row[tid+128] = v1*inv; row[tid+256] = v2*inv; row[tid+384] = v3*inv;
}

__global__ void copy_hc(const float* __restrict__ h, const float* __restrict__ c,
                        float* __restrict__ out)
{
    int i = blockIdx.x * blockDim.x + threadIdx.x;
    if (i < BATCH*HID) {
        out[DEC_ELEMS + i] = h[i];
        out[DEC_ELEMS + BATCH*HID + i] = c[i];
    }
}

// ---------------------------------------------------------------------------
// Host orchestration (graph-capturable: launches only)
// ---------------------------------------------------------------------------
extern "C" void kernel_launch(void* const* d_in, const int* in_sizes, int n_in,
                              void* d_out, int out_size)
{
    const float* x  = (const float*)d_in[0];
    const float* Wf = (const float*)d_in[1];
    const float* bf = (const float*)d_in[2];
    const float* Wi = (const float*)d_in[3];
    const float* bi = (const float*)d_in[4];
    const float* Wg = (const float*)d_in[5];
    const float* bg = (const float*)d_in[6];
    const float* Wo = (const float*)d_in[7];
    const float* bo = (const float*)d_in[8];
    const float* Wq = (const float*)d_in[9];
    const float* bq = (const float*)d_in[10];
    const float* Wk = (const float*)d_in[11];
    const float* bk = (const float*)d_in[12];
    const float* Wv = (const float*)d_in[13];
    const float* bv = (const float*)d_in[14];
    float* out = (float*)d_out;

    float *biasp, *gx, *lstm, *c, *PQ, *PK, *PV, *Wxph, *Wxpl;
    uint32_t *Wqh, *Wql, *Wkh, *Wkl, *Wvh, *Wvl;
    cudaGetSymbolAddress((void**)&biasp, g_biasp);
    cudaGetSymbolAddress((void**)&gx,    g_gx);
    cudaGetSymbolAddress((void**)&lstm,  g_lstm);
    cudaGetSymbolAddress((void**)&c,     g_c);
    cudaGetSymbolAddress((void**)&PQ,    g_PQ);
    cudaGetSymbolAddress((void**)&PK,    g_PK);
    cudaGetSymbolAddress((void**)&PV,    g_PV);
    cudaGetSymbolAddress((void**)&Wxph,  g_Wxph);
    cudaGetSymbolAddress((void**)&Wxpl,  g_Wxpl);
    cudaGetSymbolAddress((void**)&Wqh,   g_Wqh);
    cudaGetSymbolAddress((void**)&Wql,   g_Wql);
    cudaGetSymbolAddress((void**)&Wkh,   g_Wkh);
    cudaGetSymbolAddress((void**)&Wkl,   g_Wkl);
    cudaGetSymbolAddress((void**)&Wvh,   g_Wvh);
    cudaGetSymbolAddress((void**)&Wvl,   g_Wvl);

    // smem: (32 + 128)*KPP u32 + 1024 floats = 170,496 B
    const int SMEM_LSTM = (160*KPP + 8*32*4) * (int)sizeof(uint32_t);
    cudaFuncSetAttribute(lstm_persistent,
                         cudaFuncAttributeMaxDynamicSharedMemorySize, SMEM_LSTM);

    // 1. repack + zero + pre-split weights
    pack_weights<<<(768*HID + 255)/256, 256>>>(Wf, Wi, Wg, Wo, bf, bi, bg, bo);
    zero_state<<<(BATCH*HID + 255)/256, 256>>>();
    split_wxp<<<(D_IN*G4 + 255)/256, 256>>>();
    const int NW = (HID/2)*HID;
    split_w_bfp<<<(NW + 255)/256, 256>>>(Wq, Wqh, Wql, HID, NW);
    split_w_bfp<<<(NW + 255)/256, 256>>>(Wk, Wkh, Wkl, HID, NW);
    split_w_bfp<<<(NW + 255)/256, 256>>>(Wv, Wvh, Wvl, HID, NW);

    // 2. x-side gate preacts (tf32 3-split — feeds the recurrence)
    gemm_tf32_pb<<<dim3(G4/64, ROWS/128), 256>>>(
        x, D_IN, Wxph, Wxpl, G4, biasp, gx, G4, D_IN, 1.0f);

    // 3. recurrence: persistent bf16-split tensor-core kernel
    lstm_persistent<<<NB, 512, SMEM_LSTM>>>(gx);

    // 4. Q/K/V projections (bf16 3-split, pre-packed weights)
    gemm_bf16_pb<<<dim3(HID/64, ROWS/128), 256>>>(
        lstm, HID, Wqh, Wql, HID, bq, PQ, HID, HID, 1.0f);
    gemm_bf16_pb<<<dim3(HID/64, ROWS/128), 256>>>(
        lstm, HID, Wkh, Wkl, HID, bk, PK, HID, HID, 1.0f);
    gemm_bf16_pb<<<dim3(HID/64, ROWS/128), 256>>>(
        lstm, HID, Wvh, Wvl, HID, bv, PV, HID, HID, 1.0f);

    // 5. scores = (Q @ K^T)/sqrt(dk)  (bf16 3-split)
    const long pbS = (long)S_LEN * HID;
    const long phS = DK;
    const long scB = 4L * S_LEN * S_LEN;
    const long scH = (long)S_LEN * S_LEN;
    float scale = 1.0f / sqrtf((float)DK);
    gemm_bf16<<<dim3(S_LEN/64, S_LEN/128, BATCH*NH), 256>>>(
        PQ, HID, pbS, phS,
        PK, HID, pbS, phS,
        (const float*)0,
        gx /* reused as scores */, S_LEN, scB, scH, DK, scale, 1);

    // 6. softmax over last axis
    softmax512<<<BATCH*NH*S_LEN, 128>>>(gx);

    // 7. out = attn @ V (bf16 3-split), decoded layout
    gemm_bf16<<<dim3(DK/64, S_LEN/128, BATCH*NH), 256>>>(
        gx, S_LEN, scB, scH,
        PV, HID, pbS, phS,
        (const float*)0,
        out, BATCH*HID, (long)HID, (long)DK, S_LEN, 1.0f, 0);

    // 8. final hidden/cell state (h_final = last lstm_out slice, fp32)
    copy_hc<<<(BATCH*HID + 255)/256, 256>>>(
        lstm + (long)(S_LEN-1)*BATCH*HID, c, out);
}

// round 17
// speedup vs baseline: 1.5956x; 1.0292x over previous
#include <cuda_runtime.h>
#include <math.h>
#include <stdint.h>

// ---------------------------------------------------------------------------
// Problem constants
// ---------------------------------------------------------------------------
#define S_LEN   512
#define BATCH   64
#define D_IN    256
#define HID     512
#define G4      2048        // 4 gates * HID, packed unit-major: col = u*4 + gate
#define NH      4
#define DK      128
#define ROWS    (S_LEN*BATCH)        // 32768
#define DEC_ELEMS (S_LEN*BATCH*HID)  // 16777216
#define NB      128                  // persistent LSTM blocks
#define KPW     256                  // k-pairs per h row (HID/2)
#define KPP     260                  // kp smem pitch (mod 32 == 4)
#define APITCH  20                   // fp32 gemm A-smem pitch
#define BPITCH  72                   // gemm B-smem pitch
#define BTFL    1280                 // fp32 gemm B buffer floats
#define APP     12                   // packed-A smem pitch (8 kp + pad; mod 32 == 12)
#define SKP     68                   // scores packed smem pitch (mod 32 == 4)

// ---------------------------------------------------------------------------
// Device scratch (static allocations only)
// ---------------------------------------------------------------------------
__device__ float g_Wxp[D_IN*G4];
__device__ float g_Whp[HID*G4];
__device__ float g_biasp[G4];
__device__ float g_gx[ROWS*G4];           // gate preacts; reused as attn scores
__device__ uint32_t g_lph[ROWS*KPW];      // 32 MB lstm_out packed bf16x2 hi (IS h history)
__device__ uint32_t g_lpl[ROWS*KPW];      // 32 MB lstm_out packed bf16x2 lo
__device__ float g_hfin[BATCH*HID];       // final h (fp32)
__device__ float g_c[BATCH*HID];
__device__ float g_PV[ROWS*HID];          // V projection (fp32, AV gemm needs k=s pairs)
__device__ uint32_t g_PQph[ROWS*KPW], g_PQpl[ROWS*KPW];   // Q packed
__device__ uint32_t g_PKph[ROWS*KPW], g_PKpl[ROWS*KPW];   // K packed
__device__ unsigned g_cnt;
// pre-split weights
__device__ float g_Wxph[D_IN*G4], g_Wxpl[D_IN*G4];
__device__ uint32_t g_Wqh[(HID/2)*HID], g_Wql[(HID/2)*HID];
__device__ uint32_t g_Wkh[(HID/2)*HID], g_Wkl[(HID/2)*HID];
__device__ uint32_t g_Wvh[(HID/2)*HID], g_Wvl[(HID/2)*HID];

// ---------------------------------------------------------------------------
// Helpers
// ---------------------------------------------------------------------------
__device__ __forceinline__ float tf32_rnd(float x) {
    uint32_t u; asm("cvt.rna.tf32.f32 %0, %1;" : "=r"(u) : "f"(x));
    return __uint_as_float(u);
}
__device__ __forceinline__ uint32_t fu(float x) { return __float_as_uint(x); }

__device__ __forceinline__ void bsplit2(float f0, float f1, uint32_t& h, uint32_t& l)
{
    uint32_t u0 = __float_as_uint(f0), u1 = __float_as_uint(f1);
    asm("prmt.b32 %0, %1, %2, 0x7632;" : "=r"(h) : "r"(u0), "r"(u1));
    float h0 = __uint_as_float(u0 & 0xFFFF0000u);
    float h1 = __uint_as_float(u1 & 0xFFFF0000u);
    asm("cvt.rn.bf16x2.f32 %0, %1, %2;" : "=r"(l) : "f"(f1 - h1), "f"(f0 - h0));
}

#define MMA8(cc, a, bb) \
    asm volatile("mma.sync.aligned.m16n8k8.row.col.f32.tf32.tf32.f32 " \
        "{%0,%1,%2,%3},{%4,%5,%6,%7},{%8,%9},{%0,%1,%2,%3};" \
        : "+f"(cc[0]), "+f"(cc[1]), "+f"(cc[2]), "+f"(cc[3]) \
        : "r"(a[0]), "r"(a[1]), "r"(a[2]), "r"(a[3]), "r"(bb[0]), "r"(bb[1]))

#define MMA16(cc, a, bb) \
    asm volatile("mma.sync.aligned.m16n8k16.row.col.f32.bf16.bf16.f32 " \
        "{%0,%1,%2,%3},{%4,%5,%6,%7},{%8,%9},{%0,%1,%2,%3};" \
        : "+f"(cc[0]), "+f"(cc[1]), "+f"(cc[2]), "+f"(cc[3]) \
        : "r"(a[0]), "r"(a[1]), "r"(a[2]), "r"(a[3]), "r"(bb[0]), "r"(bb[1]))

#define CPA16(dst, src) \
    asm volatile("cp.async.cg.shared.global [%0], [%1], 16;" :: "r"(dst), "l"(src))

// ---------------------------------------------------------------------------
// Weight repack + splits
// ---------------------------------------------------------------------------
__global__ void pack_weights(const float* __restrict__ Wf, const float* __restrict__ Wi,
                             const float* __restrict__ Wg, const float* __restrict__ Wo,
                             const float* __restrict__ bf, const float* __restrict__ bi,
                             const float* __restrict__ bg, const float* __restrict__ bo)
{
    int idx = blockIdx.x * blockDim.x + threadIdx.x;
    if (idx < 768*HID) {
        int k = idx / HID, u = idx % HID;
        float vf = Wf[idx], vi = Wi[idx], vg = Wg[idx], vo = Wo[idx];
        float* dst = (k < D_IN) ? (g_Wxp + (long)k*G4) : (g_Whp + (long)(k - D_IN)*G4);
        dst[u*4+0] = vf; dst[u*4+1] = vi; dst[u*4+2] = vg; dst[u*4+3] = vo;
    }
    if (idx < HID) {
        g_biasp[idx*4+0] = bf[idx];
        g_biasp[idx*4+1] = bi[idx];
        g_biasp[idx*4+2] = bg[idx];
        g_biasp[idx*4+3] = bo[idx];
    }
    if (idx == 0) g_cnt = 0u;
}

__global__ void split_wxp()
{
    int i = blockIdx.x * blockDim.x + threadIdx.x;
    if (i < D_IN*G4) {
        float w = g_Wxp[i];
        float hi = tf32_rnd(w);
        g_Wxph[i] = hi;
        g_Wxpl[i] = w - hi;
    }
}

__global__ void split_w_bfp(const float* __restrict__ W, uint32_t* __restrict__ Wh,
                            uint32_t* __restrict__ Wl, int N, int total)
{
    int idx = blockIdx.x * blockDim.x + threadIdx.x;
    if (idx < total) {
        int kp = idx / N, n = idx - kp*N;
        float f0 = W[(long)(2*kp)*N + n];
        float f1 = W[(long)(2*kp+1)*N + n];
        uint32_t h, l;
        bsplit2(f0, f1, h, l);
        Wh[idx] = h;
        Wl[idx] = l;
    }
}

// ---------------------------------------------------------------------------
// tf32 3-split GEMM, PRE-SPLIT B (fp32 hi/lo). gx only. Proven R13-16.
// ---------------------------------------------------------------------------
__global__ __launch_bounds__(256, 2)
void gemm_tf32_pb(const float* __restrict__ A, int lda,
                  const float* __restrict__ Bh, const float* __restrict__ Bl, int ldb,
                  const float* __restrict__ bias,
                  float* __restrict__ C, int ldc,
                  int K, float alpha)
{
    __shared__ float As [2][128*APITCH];
    __shared__ float Bhs[2][16*BPITCH];
    __shared__ float Bls[2][16*BPITCH];

    int m0 = blockIdx.y * 128, n0 = blockIdx.x * 64;
    int tid = threadIdx.x;
    int warp = tid >> 5, lane = tid & 31;
    int wm = (warp >> 1) * 32, wn = (warp & 1) * 32;
    int r = lane >> 2, q = lane & 3;

    const uint32_t a_smem  = (uint32_t)__cvta_generic_to_shared(&As[0][0]);
    const uint32_t bh_smem = (uint32_t)__cvta_generic_to_shared(&Bhs[0][0]);
    const uint32_t bl_smem = (uint32_t)__cvta_generic_to_shared(&Bls[0][0]);
    const uint32_t abuf = 128*APITCH*4;
    const uint32_t bbuf = 16*BPITCH*4;

    int am0 = tid >> 2, ac = tid & 3;
    int bkr = tid >> 4, bc = tid & 15;
    int KT = K >> 4;

    auto issue = [&](int kt) {
        int k0 = kt << 4, buf = kt & 1;
        CPA16(a_smem + buf*abuf + (uint32_t)(am0*APITCH + ac*4)*4,
              A + (long)(m0 + am0)*lda + k0 + ac*4);
        CPA16(a_smem + buf*abuf + (uint32_t)((am0+64)*APITCH + ac*4)*4,
              A + (long)(m0 + am0 + 64)*lda + k0 + ac*4);
        CPA16(bh_smem + buf*bbuf + (uint32_t)(bkr*BPITCH + bc*4)*4,
              Bh + (long)(k0 + bkr)*ldb + n0 + bc*4);
        CPA16(bl_smem + buf*bbuf + (uint32_t)(bkr*BPITCH + bc*4)*4,
              Bl + (long)(k0 + bkr)*ldb + n0 + bc*4);
        asm volatile("cp.async.commit_group;");
    };

    float acc[2][4][4];
    #pragma unroll
    for (int mt = 0; mt < 2; mt++)
        #pragma unroll
        for (int nt = 0; nt < 4; nt++)
            #pragma unroll
            for (int e = 0; e < 4; e++) acc[mt][nt][e] = 0.f;

    issue(0);
    for (int kt = 0; kt < KT; kt++) {
        if (kt + 1 < KT) {
            issue(kt + 1);
            asm volatile("cp.async.wait_group 1;" ::: "memory");
        } else {
            asm volatile("cp.async.wait_group 0;" ::: "memory");
        }
        __syncthreads();

        const float* Abb = &As [kt & 1][0];
        const float* Bhb = &Bhs[kt & 1][0];
        const float* Blb = &Bls[kt & 1][0];
        #pragma unroll
        for (int p = 0; p < 2; p++) {
            int kb = p*8;
            uint32_t bh[4][2], bl[4][2];
            #pragma unroll
            for (int nt = 0; nt < 4; nt++) {
                int n = wn + nt*8 + r;
                bh[nt][0] = fu(Bhb[(kb+q  )*BPITCH + n]);
                bh[nt][1] = fu(Bhb[(kb+q+4)*BPITCH + n]);
                bl[nt][0] = fu(Blb[(kb+q  )*BPITCH + n]);
                bl[nt][1] = fu(Blb[(kb+q+4)*BPITCH + n]);
            }
            #pragma unroll
            for (int mt = 0; mt < 2; mt++) {
                int m = wm + mt*16 + r;
                float ar[4];
                ar[0] = Abb[ m     *APITCH + kb+q  ];
                ar[1] = Abb[(m+8)  *APITCH + kb+q  ];
                ar[2] = Abb[ m     *APITCH + kb+q+4];
                ar[3] = Abb[(m+8)  *APITCH + kb+q+4];
                uint32_t ah[4], al[4];
                #pragma unroll
                for (int e = 0; e < 4; e++) {
                    float hi = tf32_rnd(ar[e]);
                    ah[e] = fu(hi);
                    al[e] = fu(ar[e] - hi);
                }
                #pragma unroll
                for (int nt = 0; nt < 4; nt++) {
                    MMA8(acc[mt][nt], ah, bh[nt]);
                    MMA8(acc[mt][nt], ah, bl[nt]);
                    MMA8(acc[mt][nt], al, bh[nt]);
                }
            }
        }
        __syncthreads();
    }

    #pragma unroll
    for (int mt = 0; mt < 2; mt++)
        #pragma unroll
        for (int nt = 0; nt < 4; nt++) {
            int mrow = m0 + wm + mt*16 + r;
            int ncol = n0 + wn + nt*8 + q*2;
            float b0 = bias ? bias[ncol]   : 0.f;
            float b1 = bias ? bias[ncol+1] : 0.f;
            C[(long)mrow*ldc + ncol  ]     = alpha*acc[mt][nt][0] + b0;
            C[(long)mrow*ldc + ncol+1]     = alpha*acc[mt][nt][1] + b1;
            C[(long)(mrow+8)*ldc + ncol  ] = alpha*acc[mt][nt][2] + b0;
            C[(long)(mrow+8)*ldc + ncol+1] = alpha*acc[mt][nt][3] + b1;
        }
}

// ---------------------------------------------------------------------------
// bf16 3-split GEMM (runtime split). attn@V only now. Proven R15/16.
// ---------------------------------------------------------------------------
__global__ __launch_bounds__(256, 2)
void gemm_bf16(const float* __restrict__ A, int lda, long as1, long as2,
               const float* __restrict__ B, int ldb, long bs1, long bs2,
               float* __restrict__ C, int ldc, long cs1, long cs2,
               int K, float alpha)
{
    __shared__ float As[2][128*APITCH];
    __shared__ float Bs[2][BTFL];

    int z = blockIdx.z;
    A += (long)(z >> 2) * as1 + (long)(z & 3) * as2;
    B += (long)(z >> 2) * bs1 + (long)(z & 3) * bs2;
    C += (long)(z >> 2) * cs1 + (long)(z & 3) * cs2;
    int m0 = blockIdx.y * 128, n0 = blockIdx.x * 64;

    int tid = threadIdx.x;
    int warp = tid >> 5, lane = tid & 31;
    int wm = (warp >> 1) * 32, wn = (warp & 1) * 32;
    int r = lane >> 2, q = lane & 3;

    const uint32_t a_smem = (uint32_t)__cvta_generic_to_shared(&As[0][0]);
    const uint32_t b_smem = (uint32_t)__cvta_generic_to_shared(&Bs[0][0]);
    const uint32_t abuf = 128*APITCH*4;
    const uint32_t bbuf = BTFL*4;

    int am0 = tid >> 2, ac = tid & 3;
    int bkr = tid >> 4, bc = tid & 15;
    int KT = K >> 4;

    auto issue = [&](int kt) {
        int k0 = kt << 4, buf = kt & 1;
        CPA16(a_smem + buf*abuf + (uint32_t)(am0*APITCH + ac*4)*4,
              A + (long)(m0 + am0)*lda + k0 + ac*4);
        CPA16(a_smem + buf*abuf + (uint32_t)((am0+64)*APITCH + ac*4)*4,
              A + (long)(m0 + am0 + 64)*lda + k0 + ac*4);
        CPA16(b_smem + buf*bbuf + (uint32_t)(bkr*BPITCH + bc*4)*4,
              B + (long)(k0 + bkr)*ldb + n0 + bc*4);
        asm volatile("cp.async.commit_group;");
    };

    float acc[2][4][4];
    #pragma unroll
    for (int mt = 0; mt < 2; mt++)
        #pragma unroll
        for (int nt = 0; nt < 4; nt++)
            #pragma unroll
            for (int e = 0; e < 4; e++) acc[mt][nt][e] = 0.f;

    issue(0);
    for (int kt = 0; kt < KT; kt++) {
        if (kt + 1 < KT) {
            issue(kt + 1);
            asm volatile("cp.async.wait_group 1;" ::: "memory");
        } else {
            asm volatile("cp.async.wait_group 0;" ::: "memory");
        }
        __syncthreads();

        const float* Ab = &As[kt & 1][0];
        const float* Bb = &Bs[kt & 1][0];

        uint32_t bh[4][2], bl[4][2];
        #pragma unroll
        for (int nt = 0; nt < 4; nt++) {
            int n = wn + nt*8 + r;
            bsplit2(Bb[(2*q  )*BPITCH + n], Bb[(2*q+1)*BPITCH + n],
                    bh[nt][0], bl[nt][0]);
            bsplit2(Bb[(2*q+8)*BPITCH + n], Bb[(2*q+9)*BPITCH + n],
                    bh[nt][1], bl[nt][1]);
        }

        #pragma unroll
        for (int mt = 0; mt < 2; mt++) {
            int m = wm + mt*16 + r;
            float2 q0 = *(const float2*)(Ab +  m    *APITCH + 2*q);
            float2 q1 = *(const float2*)(Ab + (m+8) *APITCH + 2*q);
            float2 q2 = *(const float2*)(Ab +  m    *APITCH + 2*q + 8);
            float2 q3 = *(const float2*)(Ab + (m+8) *APITCH + 2*q + 8);
            uint32_t ah[4], al[4];
            bsplit2(q0.x, q0.y, ah[0], al[0]);
            bsplit2(q1.x, q1.y, ah[1], al[1]);
            bsplit2(q2.x, q2.y, ah[2], al[2]);
            bsplit2(q3.x, q3.y, ah[3], al[3]);
            #pragma unroll
            for (int nt = 0; nt < 4; nt++) {
                MMA16(acc[mt][nt], ah, bh[nt]);
                MMA16(acc[mt][nt], ah, bl[nt]);
                MMA16(acc[mt][nt], al, bh[nt]);
            }
        }
        __syncthreads();
    }

    #pragma unroll
    for (int mt = 0; mt < 2; mt++)
        #pragma unroll
        for (int nt = 0; nt < 4; nt++) {
            int mrow = m0 + wm + mt*16 + r;
            int ncol = n0 + wn + nt*8 + q*2;
            C[(long)mrow*ldc + ncol  ]     = alpha*acc[mt][nt][0];
            C[(long)mrow*ldc + ncol+1]     = alpha*acc[mt][nt][1];
            C[(long)(mrow+8)*ldc + ncol  ] = alpha*acc[mt][nt][2];
            C[(long)(mrow+8)*ldc + ncol+1] = alpha*acc[mt][nt][3];
        }
}

// ---------------------------------------------------------------------------
// bf16 GEMM, BOTH operands pre-packed (zero in-loop conversions).
// A = packed bf16x2 hi/lo [M][K/2]; B = packed [K/2][N].
// Output: packed (Cph/Cpl, pairs along n) if Cph != 0, else fp32 Cf.
// Used for Q/K/V projections.
// ---------------------------------------------------------------------------
__global__ __launch_bounds__(256, 2)
void gemm_bf16_aa(const uint32_t* __restrict__ Aph, const uint32_t* __restrict__ Apl,
                  int ldap,
                  const uint32_t* __restrict__ Bhp, const uint32_t* __restrict__ Blp,
                  int ldbp,
                  const float* __restrict__ bias,
                  float* __restrict__ Cf, int ldc,
                  uint32_t* __restrict__ Cph, uint32_t* __restrict__ Cpl, int ldcp,
                  int K, float alpha)
{
    __shared__ uint32_t Ahs[2][128*APP], Als[2][128*APP];
    __shared__ uint32_t Bhs[2][8*BPITCH], Bls[2][8*BPITCH];

    int m0 = blockIdx.y * 128, n0 = blockIdx.x * 64;
    int tid = threadIdx.x;
    int warp = tid >> 5, lane = tid & 31;
    int wm = (warp >> 1) * 32, wn = (warp & 1) * 32;
    int r = lane >> 2, q = lane & 3;

    const uint32_t ah_smem = (uint32_t)__cvta_generic_to_shared(&Ahs[0][0]);
    const uint32_t al_smem = (uint32_t)__cvta_generic_to_shared(&Als[0][0]);
    const uint32_t bh_smem = (uint32_t)__cvta_generic_to_shared(&Bhs[0][0]);
    const uint32_t bl_smem = (uint32_t)__cvta_generic_to_shared(&Bls[0][0]);
    const uint32_t abuf = 128*APP*4;
    const uint32_t bbuf = 8*BPITCH*4;

    int am = tid >> 1, ah4 = tid & 1;      // A: 128 rows x 2 halves
    int tl = tid & 127;
    int brow = tl >> 4, bch = tl & 15;     // B: 8 kp rows x 16 n-chunks

    int KT = K >> 4;

    auto issue = [&](int kt) {
        int kp0 = kt << 3, buf = kt & 1;
        CPA16(ah_smem + buf*abuf + (uint32_t)(am*APP + ah4*4)*4,
              Aph + (long)(m0 + am)*ldap + kp0 + ah4*4);
        CPA16(al_smem + buf*abuf + (uint32_t)(am*APP + ah4*4)*4,
              Apl + (long)(m0 + am)*ldap + kp0 + ah4*4);
        if (tid < 128) {
            CPA16(bh_smem + buf*bbuf + (uint32_t)(brow*BPITCH + bch*4)*4,
                  Bhp + (long)(kp0 + brow)*ldbp + n0 + bch*4);
        } else {
            CPA16(bl_smem + buf*bbuf + (uint32_t)(brow*BPITCH + bch*4)*4,
                  Blp + (long)(kp0 + brow)*ldbp + n0 + bch*4);
        }
        asm volatile("cp.async.commit_group;");
    };

    float acc[2][4][4];
    #pragma unroll
    for (int mt = 0; mt < 2; mt++)
        #pragma unroll
        for (int nt = 0; nt < 4; nt++)
            #pragma unroll
            for (int e = 0; e < 4; e++) acc[mt][nt][e] = 0.f;

    issue(0);
    for (int kt = 0; kt < KT; kt++) {
        if (kt + 1 < KT) {
            issue(kt + 1);
            asm volatile("cp.async.wait_group 1;" ::: "memory");
        } else {
            asm volatile("cp.async.wait_group 0;" ::: "memory");
        }
        __syncthreads();

        const uint32_t* Ahb = &Ahs[kt & 1][0];
        const uint32_t* Alb = &Als[kt & 1][0];
        const uint32_t* Bhb = &Bhs[kt & 1][0];
        const uint32_t* Blb = &Bls[kt & 1][0];

        uint32_t bh[4][2], bl[4][2];
        #pragma unroll
        for (int nt = 0; nt < 4; nt++) {
            int n = wn + nt*8 + r;
            bh[nt][0] = Bhb[ q     *BPITCH + n];
            bh[nt][1] = Bhb[(q+4)  *BPITCH + n];
            bl[nt][0] = Blb[ q     *BPITCH + n];
            bl[nt][1] = Blb[(q+4)  *BPITCH + n];
        }

        #pragma unroll
        for (int mt = 0; mt < 2; mt++) {
            int m = wm + mt*16 + r;
            uint32_t ah[4] = { Ahb[m*APP + q], Ahb[(m+8)*APP + q],
                               Ahb[m*APP + q+4], Ahb[(m+8)*APP + q+4] };
            uint32_t al[4] = { Alb[m*APP + q], Alb[(m+8)*APP + q],
                               Alb[m*APP + q+4], Alb[(m+8)*APP + q+4] };
            #pragma unroll
            for (int nt = 0; nt < 4; nt++) {
                MMA16(acc[mt][nt], ah, bh[nt]);
                MMA16(acc[mt][nt], ah, bl[nt]);
                MMA16(acc[mt][nt], al, bh[nt]);
            }
        }
        __syncthreads();
    }

    #pragma unroll
    for (int mt = 0; mt < 2; mt++)
        #pragma unroll
        for (int nt = 0; nt < 4; nt++) {
            int mrow = m0 + wm + mt*16 + r;
            int ncol = n0 + wn + nt*8 + q*2;
            float b0 = bias ? bias[ncol]   : 0.f;
            float b1 = bias ? bias[ncol+1] : 0.f;
            float v0 = alpha*acc[mt][nt][0] + b0;
            float v1 = alpha*acc[mt][nt][1] + b1;
            float v2 = alpha*acc[mt][nt][2] + b0;
            float v3 = alpha*acc[mt][nt][3] + b1;
            if (Cph) {
                uint32_t h0, l0, h1, l1;
                bsplit2(v0, v1, h0, l0);
                bsplit2(v2, v3, h1, l1);
                int kpo = ncol >> 1;
                Cph[(long)mrow*ldcp + kpo]     = h0;
                Cpl[(long)mrow*ldcp + kpo]     = l0;
                Cph[(long)(mrow+8)*ldcp + kpo] = h1;
                Cpl[(long)(mrow+8)*ldcp + kpo] = l1;
            } else {
                Cf[(long)mrow*ldc + ncol  ]     = v0;
                Cf[(long)mrow*ldc + ncol+1]     = v1;
                Cf[(long)(mrow+8)*ldc + ncol  ] = v2;
                Cf[(long)(mrow+8)*ldc + ncol+1] = v3;
            }
        }
}

// ---------------------------------------------------------------------------
// Scores GEMM: C = alpha * Q @ K^T from PACKED Q/K (bf16x2 hi/lo, kp along dk).
// K = DK = 128 (64 kp) staged ONCE; zero in-loop conversions.
// Dynamic smem: (256 + 128) * SKP u32 = 104,448 B.
// z = b'*4 + h: A/B offset (z>>2)*S_LEN*KPW + (z&3)*64; C strides hardcoded.
// ---------------------------------------------------------------------------
__global__ __launch_bounds__(256)
void gemm_bf16_sc(const uint32_t* __restrict__ Aph, const uint32_t* __restrict__ Apl,
                  const uint32_t* __restrict__ Bph, const uint32_t* __restrict__ Bpl,
                  float* __restrict__ C, float alpha)
{
    extern __shared__ uint32_t ss[];
    uint32_t* Ah = ss;                 // [128][68]
    uint32_t* Al = ss + 128*SKP;
    uint32_t* Bh = ss + 256*SKP;       // [64][68]
    uint32_t* Bl = ss + 256*SKP + 64*SKP;

    int z = blockIdx.z;
    long poff = (long)(z >> 2) * S_LEN * KPW + (long)(z & 3) * (DK/2);
    Aph += poff; Apl += poff; Bph += poff; Bpl += poff;
    C += (long)(z >> 2) * (4L*S_LEN*S_LEN) + (long)(z & 3) * ((long)S_LEN*S_LEN);
    int m0 = blockIdx.y * 128, n0 = blockIdx.x * 64;

    int tid = threadIdx.x;
    int warp = tid >> 5, lane = tid & 31;
    int wm = (warp >> 1) * 32, wn = (warp & 1) * 32;
    int r = lane >> 2, q = lane & 3;

    const uint32_t ah_s = (uint32_t)__cvta_generic_to_shared(Ah);
    const uint32_t al_s = (uint32_t)__cvta_generic_to_shared(Al);
    const uint32_t bh_s = (uint32_t)__cvta_generic_to_shared(Bh);
    const uint32_t bl_s = (uint32_t)__cvta_generic_to_shared(Bl);

    // stage A: 128 rows x 64 kp (hi+lo): 2048 chunks each, 8/thread
    #pragma unroll
    for (int i = 0; i < 8; i++) {
        int idx = tid + i*256;
        int row = idx >> 4, c4 = idx & 15;
        CPA16(ah_s + (uint32_t)(row*SKP + c4*4)*4,
              Aph + (long)(m0 + row)*KPW + c4*4);
        CPA16(al_s + (uint32_t)(row*SKP + c4*4)*4,
              Apl + (long)(m0 + row)*KPW + c4*4);
    }
    // stage B: 64 rows x 64 kp (hi+lo): 1024 chunks each, 4/thread
    #pragma unroll
    for (int i = 0; i < 4; i++) {
        int idx = tid + i*256;
        int row = idx >> 4, c4 = idx & 15;
        CPA16(bh_s + (uint32_t)(row*SKP + c4*4)*4,
              Bph + (long)(n0 + row)*KPW + c4*4);
        CPA16(bl_s + (uint32_t)(row*SKP + c4*4)*4,
              Bpl + (long)(n0 + row)*KPW + c4*4);
    }
    asm volatile("cp.async.commit_group;");
    asm volatile("cp.async.wait_group 0;" ::: "memory");
    __syncthreads();

    float acc[2][4][4];
    #pragma unroll
    for (int mt = 0; mt < 2; mt++)
        #pragma unroll
        for (int nt = 0; nt < 4; nt++)
            #pragma unroll
            for (int e = 0; e < 4; e++) acc[mt][nt][e] = 0.f;

    #pragma unroll
    for (int kp0 = 0; kp0 < 64; kp0 += 8) {
        uint32_t bhf[4][2], blf[4][2];
        #pragma unroll
        for (int nt = 0; nt < 4; nt++) {
            int n = wn + nt*8 + r;
            bhf[nt][0] = Bh[n*SKP + kp0 + q];
            bhf[nt][1] = Bh[n*SKP + kp0 + q+4];
            blf[nt][0] = Bl[n*SKP + kp0 + q];
            blf[nt][1] = Bl[n*SKP + kp0 + q+4];
        }
        #pragma unroll
        for (int mt = 0; mt < 2; mt++) {
            int m = wm + mt*16 + r;
            uint32_t ah[4] = { Ah[m*SKP + kp0 + q], Ah[(m+8)*SKP + kp0 + q],
                               Ah[m*SKP + kp0 + q+4], Ah[(m+8)*SKP + kp0 + q+4] };
            uint32_t al[4] = { Al[m*SKP + kp0 + q], Al[(m+8)*SKP + kp0 + q],
                               Al[m*SKP + kp0 + q+4], Al[(m+8)*SKP + kp0 + q+4] };
            #pragma unroll
            for (int nt = 0; nt < 4; nt++) {
                MMA16(acc[mt][nt], ah, bhf[nt]);
                MMA16(acc[mt][nt], ah, blf[nt]);
                MMA16(acc[mt][nt], al, bhf[nt]);
            }
        }
    }

    #pragma unroll
    for (int mt = 0; mt < 2; mt++)
        #pragma unroll
        for (int nt = 0; nt < 4; nt++) {
            int mrow = m0 + wm + mt*16 + r;
            int ncol = n0 + wn + nt*8 + q*2;
            C[(long)mrow*S_LEN + ncol  ]     = alpha*acc[mt][nt][0];
            C[(long)mrow*S_LEN + ncol+1]     = alpha*acc[mt][nt][1];
            C[(long)(mrow+8)*S_LEN + ncol  ] = alpha*acc[mt][nt][2];
            C[(long)(mrow+8)*S_LEN + ncol+1] = alpha*acc[mt][nt][3];
        }
}

// ---------------------------------------------------------------------------
// Persistent LSTM recurrence — bf16-split mma, k-split over 16 warps.
// h history IS the packed lstm output (g_lph/g_lpl); t=0 skips the matvec.
// Epilogue packs (u0, u0+1) pairs via shfl_down(2) and writes packed only
// (fp32 g_hfin + g_c at t = S_LEN-1).
// ---------------------------------------------------------------------------
__global__ __launch_bounds__(512)
void lstm_persistent(const float* __restrict__ gx)
{
    extern __shared__ uint32_t smu[];
    uint32_t* WBh = smu;                   // [16][260] weight hi
    uint32_t* WBl = smu + 16*KPP;          // [16][260] weight lo
    uint32_t* hH  = smu + 32*KPP;          // [64][260] h hi
    uint32_t* hL  = smu + 32*KPP + 64*KPP; // [64][260] h lo
    float*    red = (float*)(smu + 32*KPP + 128*KPP);

    const int tid = threadIdx.x, bid = blockIdx.x;
    const int c0 = bid * 16;
    const int warp = tid >> 5, lane = tid & 31;
    const int kg = warp >> 3;
    const int wl = warp & 7;
    const int nt = wl & 1;
    const int r = lane >> 2, q = lane & 3;
    const int row0 = (wl >> 1)*16 + r;

    for (int idx = tid; idx < 16*KPW; idx += 512) {
        int j = idx >> 8, kp = idx & 255;
        float w0 = g_Whp[(long)(2*kp  )*G4 + c0 + j];
        float w1 = g_Whp[(long)(2*kp+1)*G4 + c0 + j];
        uint32_t h, l;
        bsplit2(w0, w1, h, l);
        WBh[j*KPP + kp] = h;
        WBl[j*KPP + kp] = l;
    }

    float c_a = 0.f, c_b = 0.f;
    const int u = bid*4 + nt*2 + (q >> 1);
    const int kpo = bid*2 + nt;           // packed pair index (u0, u0+1)

    const uint32_t hH_s = (uint32_t)__cvta_generic_to_shared(hH);
    const uint32_t hL_s = (uint32_t)__cvta_generic_to_shared(hL);
    __syncthreads();

    const uint32_t* aH0 = hH + row0*KPP;
    const uint32_t* aH8 = aH0 + 8*KPP;
    const uint32_t* aL0 = hL + row0*KPP;
    const uint32_t* aL8 = aL0 + 8*KPP;
    const uint32_t* bHr = WBh + (nt*8 + r)*KPP;
    const uint32_t* bLr = WBl + (nt*8 + r)*KPP;

    const int kpb = kg * 128;
    const int tl = tid & 255;

    for (int t = 0; t < S_LEN; t++) {
        float2 gA = make_float2(0.f, 0.f), gB = make_float2(0.f, 0.f);
        if (kg == 0) {
            const float* gbase = gx + ((long)t*BATCH)*G4 + c0 + nt*8 + 2*q;
            gA = *(const float2*)(gbase + (long)row0*G4);
            gB = *(const float2*)(gbase + (long)(row0+8)*G4);
        }

        float acc[4] = {0.f, 0.f, 0.f, 0.f};

        if (t) {
            // ---- grid barrier ----
            if (tid == 0) {
                unsigned target = (unsigned)t * NB;
                while (*(volatile unsigned*)&g_cnt < target) { }
                __threadfence();
            }
            __syncthreads();

            // ---- stage this group's kp-half of h = lstm_out[t-1] packed ----
            const uint32_t* ghh = g_lph + (long)(t-1)*BATCH*KPW;
            const uint32_t* ghl = g_lpl + (long)(t-1)*BATCH*KPW;
            #pragma unroll 4
            for (int i = 0; i < 8; i++) {
                int idx = tl + i*256;
                int rr = idx >> 5, cc = idx & 31;
                CPA16(hH_s + (uint32_t)(rr*KPP + kpb + cc*4)*4,
                      ghh + rr*KPW + kpb + cc*4);
            }
            #pragma unroll 4
            for (int i = 0; i < 8; i++) {
                int idx = tl + i*256;
                int rr = idx >> 5, cc = idx & 31;
                CPA16(hL_s + (uint32_t)(rr*KPP + kpb + cc*4)*4,
                      ghl + rr*KPW + kpb + cc*4);
            }
            asm volatile("cp.async.commit_group;");
            asm volatile("cp.async.wait_group 0;" ::: "memory");
            if (kg == 0) asm volatile("bar.sync 1, 256;" ::: "memory");
            else         asm volatile("bar.sync 2, 256;" ::: "memory");

            // ---- mma over this group's kp-half (no conversions) ----
            #pragma unroll 4
            for (int kp0 = kpb; kp0 < kpb + 128; kp0 += 8) {
                uint32_t ah[4] = { aH0[kp0+q], aH8[kp0+q], aH0[kp0+q+4], aH8[kp0+q+4] };
                uint32_t al[4] = { aL0[kp0+q], aL8[kp0+q], aL0[kp0+q+4], aL8[kp0+q+4] };
                uint32_t bh[2] = { bHr[kp0+q], bHr[kp0+q+4] };
                uint32_t bl[2] = { bLr[kp0+q], bLr[kp0+q+4] };
                MMA16(acc, ah, bh);
                MMA16(acc, ah, bl);
                MMA16(acc, al, bh);
            }
        }

        // ---- cross-group reduction ----
        if (kg == 1)
            ((float4*)red)[wl*32 + lane] = make_float4(acc[0], acc[1], acc[2], acc[3]);
        __syncthreads();

        if (kg == 0) {
            float4 pa = ((float4*)red)[wl*32 + lane];
            float p0 = acc[0] + pa.x + gA.x;
            float p1 = acc[1] + pa.y + gA.y;
            float p2 = acc[2] + pa.z + gB.x;
            float p3 = acc[3] + pa.w + gB.y;

            float s0, s1, s2, s3;
            if (q & 1) {
                s0 = tanhf(p0);
                s1 = 1.f / (1.f + expf(-p1));
                s2 = tanhf(p2);
                s3 = 1.f / (1.f + expf(-p3));
            } else {
                s0 = 1.f / (1.f + expf(-p0));
                s1 = 1.f / (1.f + expf(-p1));
                s2 = 1.f / (1.f + expf(-p2));
                s3 = 1.f / (1.f + expf(-p3));
            }
            float x0 = __shfl_xor_sync(0xFFFFFFFFu, s0, 1);
            float x1 = __shfl_xor_sync(0xFFFFFFFFu, s1, 1);
            float x2 = __shfl_xor_sync(0xFFFFFFFFu, s2, 1);
            float x3 = __shfl_xor_sync(0xFFFFFFFFu, s3, 1);

            float hA = 0.f, hB = 0.f;
            if (!(q & 1)) {
                c_a = s0 * c_a + s1 * x0;
                hA = x1 * tanhf(c_a);
                c_b = s2 * c_b + s3 * x2;
                hB = x3 * tanhf(c_b);
            }
            // pack (u0, u0+1): q=0 lane takes q=2's value
            float hA2 = __shfl_down_sync(0xFFFFFFFFu, hA, 2);
            float hB2 = __shfl_down_sync(0xFFFFFFFFu, hB, 2);
            if (q == 0) {
                long rb = (long)t*BATCH;
                uint32_t h0p, l0p, h1p, l1p;
                bsplit2(hA, hA2, h0p, l0p);
                bsplit2(hB, hB2, h1p, l1p);
                g_lph[(rb+row0)*KPW + kpo]   = h0p;
                g_lpl[(rb+row0)*KPW + kpo]   = l0p;
                g_lph[(rb+row0+8)*KPW + kpo] = h1p;
                g_lpl[(rb+row0+8)*KPW + kpo] = l1p;
            }
            if (!(q & 1) && t == S_LEN-1) {
                g_hfin[row0*HID + u] = hA;
                g_hfin[(row0+8)*HID + u] = hB;
                g_c[row0*HID + u] = c_a;
                g_c[(row0+8)*HID + u] = c_b;
            }
        }

        __syncthreads();
        if (tid == 0) {
            __threadfence();
            atomicAdd(&g_cnt, 1u);
        }
    }
}

// ---------------------------------------------------------------------------
// Row softmax over 512-wide rows.
// ---------------------------------------------------------------------------
__global__ __launch_bounds__(128)
void softmax512(float* __restrict__ s)
{
    float* row = s + (size_t)blockIdx.x * 512;
    int tid = threadIdx.x;
    float v0 = row[tid], v1 = row[tid+128], v2 = row[tid+256], v3 = row[tid+384];
    float mx = fmaxf(fmaxf(v0, v1), fmaxf(v2, v3));
    __shared__ float sm[4];
    __shared__ float ssum[4];
    #pragma unroll
    for (int off = 16; off > 0; off >>= 1)
        mx = fmaxf(mx, __shfl_xor_sync(0xFFFFFFFFu, mx, off));
    if ((tid & 31) == 0) sm[tid >> 5] = mx;
    __syncthreads();
    mx = fmaxf(fmaxf(sm[0], sm[1]), fmaxf(sm[2], sm[3]));
    v0 = expf(v0 - mx); v1 = expf(v1 - mx); v2 = expf(v2 - mx); v3 = expf(v3 - mx);
    float sum = v0 + v1 + v2 + v3;
    #pragma unroll
    for (int off = 16; off > 0; off >>= 1)
        sum += __shfl_xor_sync(0xFFFFFFFFu, sum, off);
    if ((tid & 31) == 0) ssum[tid >> 5] = sum;
    __syncthreads();
    sum = ssum[0] + ssum[1] + ssum[2] + ssum[3];
    float inv = 1.f / sum;
    row[tid] = v0*inv; row[tid+128] = v1*inv; row[tid+256] = v2*inv; row[tid+384] = v3*inv;
}

__global__ void copy_hc(const float* __restrict__ h, const float* __restrict__ c,
                        float* __restrict__ out)
{
    int i = blockIdx.x * blockDim.x + threadIdx.x;
    if (i < BATCH*HID) {
        out[DEC_ELEMS + i] = h[i];
        out[DEC_ELEMS + BATCH*HID + i] = c[i];
    }
}

// ---------------------------------------------------------------------------
// Host orchestration (graph-capturable: launches only)
// ---------------------------------------------------------------------------
extern "C" void kernel_launch(void* const* d_in, const int* in_sizes, int n_in,
                              void* d_out, int out_size)
{
    const float* x  = (const float*)d_in[0];
    const float* Wf = (const float*)d_in[1];
    const float* bf = (const float*)d_in[2];
    const float* Wi = (const float*)d_in[3];
    const float* bi = (const float*)d_in[4];
    const float* Wg = (const float*)d_in[5];
    const float* bg = (const float*)d_in[6];
    const float* Wo = (const float*)d_in[7];
    const float* bo = (const float*)d_in[8];
    const float* Wq = (const float*)d_in[9];
    const float* bq = (const float*)d_in[10];
    const float* Wk = (const float*)d_in[11];
    const float* bk = (const float*)d_in[12];
    const float* Wv = (const float*)d_in[13];
    const float* bv = (const float*)d_in[14];
    float* out = (float*)d_out;

    float *biasp, *gx, *hfin, *c, *PV, *Wxph, *Wxpl;
    uint32_t *lph, *lpl, *PQph, *PQpl, *PKph, *PKpl;
    uint32_t *Wqh, *Wql, *Wkh, *Wkl, *Wvh, *Wvl;
    cudaGetSymbolAddress((void**)&biasp, g_biasp);
    cudaGetSymbolAddress((void**)&gx,    g_gx);
    cudaGetSymbolAddress((void**)&lph,   g_lph);
    cudaGetSymbolAddress((void**)&lpl,   g_lpl);
    cudaGetSymbolAddress((void**)&hfin,  g_hfin);
    cudaGetSymbolAddress((void**)&c,     g_c);
    cudaGetSymbolAddress((void**)&PV,    g_PV);
    cudaGetSymbolAddress((void**)&PQph,  g_PQph);
    cudaGetSymbolAddress((void**)&PQpl,  g_PQpl);
    cudaGetSymbolAddress((void**)&PKph,  g_PKph);
    cudaGetSymbolAddress((void**)&PKpl,  g_PKpl);
    cudaGetSymbolAddress((void**)&Wxph,  g_Wxph);
    cudaGetSymbolAddress((void**)&Wxpl,  g_Wxpl);
    cudaGetSymbolAddress((void**)&Wqh,   g_Wqh);
    cudaGetSymbolAddress((void**)&Wql,   g_Wql);
    cudaGetSymbolAddress((void**)&Wkh,   g_Wkh);
    cudaGetSymbolAddress((void**)&Wkl,   g_Wkl);
    cudaGetSymbolAddress((void**)&Wvh,   g_Wvh);
    cudaGetSymbolAddress((void**)&Wvl,   g_Wvl);

    const int SMEM_LSTM = (160*KPP + 8*32*4) * (int)sizeof(uint32_t);
    cudaFuncSetAttribute(lstm_persistent,
                         cudaFuncAttributeMaxDynamicSharedMemorySize, SMEM_LSTM);
    const int SMEM_SC = 384*SKP * (int)sizeof(uint32_t);   // 104,448 B
    cudaFuncSetAttribute(gemm_bf16_sc,
                         cudaFuncAttributeMaxDynamicSharedMemorySize, SMEM_SC);

    // 1. repack + pre-split weights (+ reset barrier counter)
    pack_weights<<<(768*HID + 255)/256, 256>>>(Wf, Wi, Wg, Wo, bf, bi, bg, bo);
    split_wxp<<<(D_IN*G4 + 255)/256, 256>>>();
    const int NW = (HID/2)*HID;
    split_w_bfp<<<(NW + 255)/256, 256>>>(Wq, Wqh, Wql, HID, NW);
    split_w_bfp<<<(NW + 255)/256, 256>>>(Wk, Wkh, Wkl, HID, NW);
    split_w_bfp<<<(NW + 255)/256, 256>>>(Wv, Wvh, Wvl, HID, NW);

    // 2. x-side gate preacts (tf32 3-split)
    gemm_tf32_pb<<<dim3(G4/64, ROWS/128), 256>>>(
        x, D_IN, Wxph, Wxpl, G4, biasp, gx, G4, D_IN, 1.0f);

    // 3. recurrence (writes packed lstm_out)
    lstm_persistent<<<NB, 512, SMEM_LSTM>>>(gx);

    // 4. Q/K/V projections — zero-conversion packed GEMMs
    gemm_bf16_aa<<<dim3(HID/64, ROWS/128), 256>>>(
        lph, lpl, KPW, Wqh, Wql, HID, bq,
        (float*)0, 0, PQph, PQpl, KPW, HID, 1.0f);
    gemm_bf16_aa<<<dim3(HID/64, ROWS/128), 256>>>(
        lph, lpl, KPW, Wkh, Wkl, HID, bk,
        (float*)0, 0, PKph, PKpl, KPW, HID, 1.0f);
    gemm_bf16_aa<<<dim3(HID/64, ROWS/128), 256>>>(
        lph, lpl, KPW, Wvh, Wvl, HID, bv,
        PV, HID, (uint32_t*)0, (uint32_t*)0, 0, HID, 1.0f);

    // 5. scores = (Q @ K^T)/sqrt(dk) — both operands pre-packed
    float scale = 1.0f / sqrtf((float)DK);
    gemm_bf16_sc<<<dim3(S_LEN/64, S_LEN/128, BATCH*NH), 256, SMEM_SC>>>(
        PQph, PQpl, PKph, PKpl, gx, scale);

    // 6. softmax
    softmax512<<<BATCH*NH*S_LEN, 128>>>(gx);

    // 7. out = attn @ V (runtime bf16 split), decoded layout
    const long pbS = (long)S_LEN * HID;
    const long phS = DK;
    const long scB = 4L * S_LEN * S_LEN;
    const long scH = (long)S_LEN * S_LEN;
    gemm_bf16<<<dim3(DK/64, S_LEN/128, BATCH*NH), 256>>>(
        gx, S_LEN, scB, scH,
        PV, HID, pbS, phS,
        out, BATCH*HID, (long)HID, (long)DK, S_LEN, 1.0f);

    // 8. final hidden/cell state
    copy_hc<<<(BATCH*HID + 255)/256, 256>>>(hfin, c, out);
}